// round 9
// baseline (speedup 1.0000x reference)
#include <cuda_runtime.h>
#include <cstdint>
#include <cstddef>

// Shapes: N=1, L=384, NODE=256, H=8, HD=32, PD=128, D1=1280
#define L 384
#define SPAT 147456       // 384*384
#define NODE 256
#define NH 8
#define HD 32
#define PD 128

// ---- scratch layout (floats) ----
#define OFF_Q       0          // 98304
#define OFF_K       98304
#define OFF_V       196608
#define OFF_A2H     294912     // 16*147456 = 2359296
#define OFF_A8      2654208    // 8*147456 = 1179648
#define OFF_AFIN    3833856    // 1179648
#define OFF_CAT     5013504    // 384*1280 = 491520
#define OFF_CATN    5505024    // 491520
#define OFF_H1      5996544    // 384*512
#define OFF_H2      6193152    // 384*512
#define OFF_H3      6389760    // 384*256
#define OFF_WT      6488064    // 136*9*128 = 156672
#define OFF_MEAN16  6644736
#define OFF_RSTD16  6644752
#define OFF_MEAN9   6644768
#define OFF_RSTD9   6644784
#define OFF_MEAN136 6644800    // 160 slots
#define OFF_RSTD136 6644960    // 160 slots
#define OFF_PSUM    6645120    // 128*384
#define OFF_PSQ     6694272    // 128*384
#define SCRATCH_FLOATS 6743424

__device__ float g_scratch[SCRATCH_FLOATS];

__device__ __forceinline__ float lrelu(float v){ return v >= 0.f ? v : 0.01f*v; }

// ------------------------------------------------------------------
// q,k,v = x @ Wq/Wk/Wv     grid 384, block 256
// ------------------------------------------------------------------
__global__ void qkv_kernel(const float* __restrict__ x, const float* __restrict__ Wq,
                           const float* __restrict__ Wk, const float* __restrict__ Wv,
                           float* __restrict__ q, float* __restrict__ k, float* __restrict__ v){
    __shared__ float xs[256];
    int l = blockIdx.x, t = threadIdx.x;
    xs[t] = x[l*256 + t];
    __syncthreads();
    float aq = 0.f, ak = 0.f, av = 0.f;
    #pragma unroll 4
    for (int i = 0; i < 256; i++){
        float xv = xs[i];
        aq += xv * Wq[i*256 + t];
        ak += xv * Wk[i*256 + t];
        av += xv * Wv[i*256 + t];
    }
    q[l*256 + t] = aq; k[l*256 + t] = ak; v[l*256 + t] = av;
}

// ------------------------------------------------------------------
// a_pair[h][l][m] = z[l,m,:] . Wp2a[:,h]   (channels 0..7 of a2h)
// grid (48, 384), block 256 (8 warps, warp per (l,m))
// ------------------------------------------------------------------
__global__ void apair_kernel(const float* __restrict__ z, const float* __restrict__ Wp2a,
                             float* __restrict__ a2h){
    __shared__ float ws[128*9]; // padded: ws[p*9+h]
    int t = threadIdx.x;
    for (int i = t; i < 1024; i += 256){
        int p = i >> 3, h = i & 7;
        ws[p*9 + h] = Wp2a[i];
    }
    __syncthreads();
    int lane = t & 31, wp = t >> 5;
    int m = blockIdx.x*8 + wp;
    int l = blockIdx.y;
    const float4 zv = *(const float4*)(z + ((size_t)l*L + m)*128 + lane*4);
    int p = lane*4;
    float acc[8];
    #pragma unroll
    for (int h = 0; h < 8; h++){
        acc[h] = zv.x*ws[p*9 + h] + zv.y*ws[(p+1)*9 + h]
               + zv.z*ws[(p+2)*9 + h] + zv.w*ws[(p+3)*9 + h];
    }
    #pragma unroll
    for (int h = 0; h < 8; h++){
        float s = acc[h];
        for (int o = 16; o > 0; o >>= 1) s += __shfl_down_sync(0xffffffffu, s, o);
        if (lane == 0) a2h[h*SPAT + l*L + m] = s;
    }
}

// ------------------------------------------------------------------
// a_node[h][l][m] = q[l,h,:].k[m,h,:]/sqrt(32)  (channels 8..15)
// grid (12,12,8), block (32,32)
// ------------------------------------------------------------------
__global__ void anode_kernel(const float* __restrict__ q, const float* __restrict__ k,
                             float* __restrict__ a2h){
    int h = blockIdx.z;
    int l0 = blockIdx.y*32, m0 = blockIdx.x*32;
    __shared__ float Qs[32][33], Ks[32][33];
    int tx = threadIdx.x, ty = threadIdx.y;
    Qs[ty][tx] = q[(l0+ty)*256 + h*32 + tx];
    Ks[ty][tx] = k[(m0+ty)*256 + h*32 + tx];
    __syncthreads();
    float acc = 0.f;
    #pragma unroll
    for (int d = 0; d < 32; d++) acc += Qs[ty][d]*Ks[tx][d];
    a2h[(8+h)*SPAT + (l0+ty)*L + m0 + tx] = acc * 0.17677669529663687f;
}

// ------------------------------------------------------------------
// Per-channel instance-norm stats for channel-first contiguous buffers
// grid = #channels, block 256.  channel c<nA from srcA, else srcB.
// ------------------------------------------------------------------
__global__ void stats_kernel(const float* __restrict__ srcA, int nA,
                             const float* __restrict__ srcB,
                             float* __restrict__ mean, float* __restrict__ rstd){
    int c = blockIdx.x, t = threadIdx.x;
    const float* p = (c < nA) ? srcA + (size_t)c*SPAT : srcB + (size_t)(c-nA)*SPAT;
    const float4* p4 = (const float4*)p;
    float s = 0.f, s2 = 0.f;
    for (int i = t; i < SPAT/4; i += 256){
        float4 v = p4[i];
        s  += v.x + v.y + v.z + v.w;
        s2 += v.x*v.x + v.y*v.y + v.z*v.z + v.w*v.w;
    }
    __shared__ float ss[256], ss2[256];
    ss[t] = s; ss2[t] = s2; __syncthreads();
    for (int o = 128; o > 0; o >>= 1){
        if (t < o){ ss[t] += ss[t+o]; ss2[t] += ss2[t+o]; }
        __syncthreads();
    }
    if (t == 0){
        float m = ss[0] * (1.f/SPAT);
        float var = ss2[0] * (1.f/SPAT) - m*m;
        mean[c] = m; rstd[c] = rsqrtf(var + 1e-5f);
    }
}

// z channel stats, stage 1: per-(l) partials, deterministic. grid 384, block 256.
__global__ void zstats1_kernel(const float* __restrict__ z,
                               float* __restrict__ psum, float* __restrict__ psq){
    int l = blockIdx.x, t = threadIdx.x;
    int c = t & 127, half = t >> 7;
    const float* base = z + (size_t)l*L*128;
    float s = 0.f, s2 = 0.f;
    for (int m = half; m < L; m += 2){
        float v = base[m*128 + c];
        s += v; s2 += v*v;
    }
    __shared__ float sh[256], sh2[256];
    sh[t] = s; sh2[t] = s2; __syncthreads();
    if (half == 0){
        psum[c*L + l] = sh[t] + sh[t+128];
        psq [c*L + l] = sh2[t] + sh2[t+128];
    }
}

// stage 2: reduce over l. grid 128, block 128.
__global__ void zstats2_kernel(const float* __restrict__ psum, const float* __restrict__ psq,
                               float* __restrict__ mean, float* __restrict__ rstd){
    int c = blockIdx.x, t = threadIdx.x;
    float s = 0.f, s2 = 0.f;
    for (int l = t; l < L; l += 128){ s += psum[c*L + l]; s2 += psq[c*L + l]; }
    __shared__ float ss[128], ss2[128];
    ss[t] = s; ss2[t] = s2; __syncthreads();
    for (int o = 64; o > 0; o >>= 1){
        if (t < o){ ss[t] += ss[t+o]; ss2[t] += ss2[t+o]; }
        __syncthreads();
    }
    if (t == 0){
        float m = ss[0] * (1.f/SPAT);
        float var = ss2[0] * (1.f/SPAT) - m*m;
        mean[c] = m; rstd[c] = rsqrtf(var + 1e-5f);
    }
}

// ------------------------------------------------------------------
// conv_a: 16ch (instance-normed a2h) -> 8ch, 3x3 SAME, leaky. grid (24,24), 256 thr
// ------------------------------------------------------------------
__global__ void conva_kernel(const float* __restrict__ a2h, const float* __restrict__ w,
                             const float* __restrict__ bias, const float* __restrict__ mean,
                             const float* __restrict__ rstd, float* __restrict__ a8){
    __shared__ float tin[16*324];
    __shared__ float wk[1152];
    int t = threadIdx.x;
    for (int i = t; i < 1152; i += 256) wk[i] = w[i];
    int x0 = blockIdx.x*16 - 1, y0 = blockIdx.y*16 - 1;
    for (int i = t; i < 16*324; i += 256){
        int c = i / 324, r = i % 324;
        int gy = y0 + r/18, gx = x0 + r%18;
        float v = 0.f;
        if ((unsigned)gy < 384u && (unsigned)gx < 384u)
            v = (a2h[c*SPAT + gy*L + gx] - mean[c]) * rstd[c];
        tin[i] = v;
    }
    __syncthreads();
    int lx = t & 15, ly = t >> 4;
    float acc[8];
    #pragma unroll
    for (int o = 0; o < 8; o++) acc[o] = bias[o];
    for (int c = 0; c < 16; c++){
        float iv[9];
        #pragma unroll
        for (int ky = 0; ky < 3; ky++)
            #pragma unroll
            for (int kx = 0; kx < 3; kx++)
                iv[ky*3+kx] = tin[c*324 + (ly+ky)*18 + lx + kx];
        #pragma unroll
        for (int o = 0; o < 8; o++){
            const float* wp = &wk[(o*16 + c)*9];
            acc[o] += wp[0]*iv[0]+wp[1]*iv[1]+wp[2]*iv[2]
                    + wp[3]*iv[3]+wp[4]*iv[4]+wp[5]*iv[5]
                    + wp[6]*iv[6]+wp[7]*iv[7]+wp[8]*iv[8];
        }
    }
    int gx = blockIdx.x*16 + lx, gy = blockIdx.y*16 + ly;
    #pragma unroll
    for (int o = 0; o < 8; o++)
        a8[o*SPAT + gy*L + gx] = lrelu(acc[o]);
}

// conv_m: 9ch (a8 normed + plddt normed) -> 8ch, leaky. grid (24,24), 256 thr
__global__ void convm_kernel(const float* __restrict__ a8, const float* __restrict__ plddt,
                             const float* __restrict__ w, const float* __restrict__ bias,
                             const float* __restrict__ mean, const float* __restrict__ rstd,
                             float* __restrict__ afin){
    __shared__ float tin[9*324];
    __shared__ float wk[648];
    int t = threadIdx.x;
    for (int i = t; i < 648; i += 256) wk[i] = w[i];
    int x0 = blockIdx.x*16 - 1, y0 = blockIdx.y*16 - 1;
    for (int i = t; i < 9*324; i += 256){
        int c = i / 324, r = i % 324;
        int gy = y0 + r/18, gx = x0 + r%18;
        float v = 0.f;
        if ((unsigned)gy < 384u && (unsigned)gx < 384u){
            float raw = (c < 8) ? a8[c*SPAT + gy*L + gx] : plddt[gy*L + gx];
            v = (raw - mean[c]) * rstd[c];
        }
        tin[i] = v;
    }
    __syncthreads();
    int lx = t & 15, ly = t >> 4;
    float acc[8];
    #pragma unroll
    for (int o = 0; o < 8; o++) acc[o] = bias[o];
    for (int c = 0; c < 9; c++){
        float iv[9];
        #pragma unroll
        for (int ky = 0; ky < 3; ky++)
            #pragma unroll
            for (int kx = 0; kx < 3; kx++)
                iv[ky*3+kx] = tin[c*324 + (ly+ky)*18 + lx + kx];
        #pragma unroll
        for (int o = 0; o < 8; o++){
            const float* wp = &wk[(o*9 + c)*9];
            acc[o] += wp[0]*iv[0]+wp[1]*iv[1]+wp[2]*iv[2]
                    + wp[3]*iv[3]+wp[4]*iv[4]+wp[5]*iv[5]
                    + wp[6]*iv[6]+wp[7]*iv[7]+wp[8]*iv[8];
        }
    }
    int gx = blockIdx.x*16 + lx, gy = blockIdx.y*16 + ly;
    #pragma unroll
    for (int o = 0; o < 8; o++)
        afin[o*SPAT + gy*L + gx] = lrelu(acc[o]);
}

// ------------------------------------------------------------------
// nfn: cat[l, 1024 + h*32+d] = sum_m afin[h][l][m] * v[m, h*32+d]
// grid (8 heads, 12 ltiles), block (32,32)
// ------------------------------------------------------------------
__global__ void nfn_kernel(const float* __restrict__ afin, const float* __restrict__ v,
                           float* __restrict__ cat){
    int h = blockIdx.x, l0 = blockIdx.y*32;
    int tx = threadIdx.x, ty = threadIdx.y;
    __shared__ float As[32][33], Vs[32][33];
    float acc = 0.f;
    for (int m0 = 0; m0 < L; m0 += 32){
        As[ty][tx] = afin[h*SPAT + (l0+ty)*L + m0 + tx];
        Vs[ty][tx] = v[(m0+ty)*256 + h*32 + tx];
        __syncthreads();
        #pragma unroll
        for (int kk = 0; kk < 32; kk++) acc += As[ty][kk]*Vs[kk][tx];
        __syncthreads();
    }
    cat[(size_t)(l0+ty)*1280 + 1024 + h*32 + tx] = acc;
}

// nfp: cat[l, h*128+p] = sum_m afin[h][l][m] * z[l,m,p].  grid 384, block 256
__global__ void nfp_kernel(const float* __restrict__ afin, const float* __restrict__ z,
                           float* __restrict__ cat){
    int l = blockIdx.x, t = threadIdx.x;
    __shared__ float As[8][32];
    __shared__ float Zs[32*128];
    int p = t & 127, hb = (t >> 7)*4;
    float acc0 = 0.f, acc1 = 0.f, acc2 = 0.f, acc3 = 0.f;
    for (int m0 = 0; m0 < L; m0 += 32){
        __syncthreads();
        { int hh = t >> 5, mm = t & 31; As[hh][mm] = afin[hh*SPAT + l*L + m0 + mm]; }
        const float4* zsrc = (const float4*)(z + ((size_t)l*L + m0)*128);
        float4* zd = (float4*)Zs;
        for (int i = t; i < 1024; i += 256) zd[i] = zsrc[i];
        __syncthreads();
        #pragma unroll 8
        for (int mm = 0; mm < 32; mm++){
            float zv = Zs[mm*128 + p];
            acc0 += As[hb  ][mm]*zv;
            acc1 += As[hb+1][mm]*zv;
            acc2 += As[hb+2][mm]*zv;
            acc3 += As[hb+3][mm]*zv;
        }
    }
    cat[(size_t)l*1280 + (hb  )*128 + p] = acc0;
    cat[(size_t)l*1280 + (hb+1)*128 + p] = acc1;
    cat[(size_t)l*1280 + (hb+2)*128 + p] = acc2;
    cat[(size_t)l*1280 + (hb+3)*128 + p] = acc3;
}

// ------------------------------------------------------------------
// row LayerNorm: out = [(in+add?) - m]/sqrt(v+eps)*w + b  (opt leaky)
// grid = rows, block 256, dyn smem D floats
// ------------------------------------------------------------------
__global__ void ln_kernel(const float* __restrict__ in, const float* __restrict__ add,
                          float* __restrict__ out, const float* __restrict__ w,
                          const float* __restrict__ b, int D, int do_leaky){
    extern __shared__ float sh[];
    __shared__ float red[256];
    int r = blockIdx.x, t = threadIdx.x;
    float s = 0.f;
    for (int i = t; i < D; i += 256){
        float v = in[(size_t)r*D + i];
        if (add) v += add[(size_t)r*D + i];
        sh[i] = v; s += v;
    }
    red[t] = s; __syncthreads();
    for (int o = 128; o > 0; o >>= 1){ if (t < o) red[t] += red[t+o]; __syncthreads(); }
    float mean = red[0] / D;
    __syncthreads();
    float s2 = 0.f;
    for (int i = t; i < D; i += 256){ float d = sh[i] - mean; s2 += d*d; }
    red[t] = s2; __syncthreads();
    for (int o = 128; o > 0; o >>= 1){ if (t < o) red[t] += red[t+o]; __syncthreads(); }
    float rstd = rsqrtf(red[0]/D + 1e-5f);
    for (int i = t; i < D; i += 256){
        float v = (sh[i] - mean)*rstd*w[i] + b[i];
        if (do_leaky) v = lrelu(v);
        out[(size_t)r*D + i] = v;
    }
}

// generic GEMM C = A(MxK) @ B(KxN) + bias.  block (16,16), tiles 32x32x32
__global__ void gemm_kernel(const float* __restrict__ A, const float* __restrict__ B,
                            const float* __restrict__ bias, float* __restrict__ C,
                            int M, int N, int K){
    __shared__ float As[32][33], Bs[32][33];
    int tx = threadIdx.x, ty = threadIdx.y;
    int t = ty*16 + tx;
    int r0 = blockIdx.y*32, c0 = blockIdx.x*32;
    float a00 = 0.f, a01 = 0.f, a10 = 0.f, a11 = 0.f;
    for (int k0 = 0; k0 < K; k0 += 32){
        for (int i = t; i < 1024; i += 256){
            int rr = i >> 5, cc = i & 31;
            As[rr][cc] = A[(size_t)(r0+rr)*K + k0 + cc];
            Bs[rr][cc] = B[(size_t)(k0+rr)*N + c0 + cc];
        }
        __syncthreads();
        #pragma unroll
        for (int kk = 0; kk < 32; kk++){
            float av0 = As[ty*2][kk], av1 = As[ty*2+1][kk];
            float bv0 = Bs[kk][tx*2], bv1 = Bs[kk][tx*2+1];
            a00 += av0*bv0; a01 += av0*bv1; a10 += av1*bv0; a11 += av1*bv1;
        }
        __syncthreads();
    }
    int r = r0 + ty*2, c = c0 + tx*2;
    C[(size_t)r*N + c]       = a00 + bias[c];
    C[(size_t)r*N + c+1]     = a01 + bias[c+1];
    C[(size_t)(r+1)*N + c]   = a10 + bias[c];
    C[(size_t)(r+1)*N + c+1] = a11 + bias[c+1];
}

// transpose conv_p weights (128,136,3,3) -> wt[(ci*9+k)*128 + po]
__global__ void wprep_kernel(const float* __restrict__ w, float* __restrict__ wt){
    int i = blockIdx.x*256 + threadIdx.x;  // 156672 total
    if (i < 156672){
        int po = i / 1224, rem = i % 1224;
        int ci = rem / 9, kk = rem % 9;
        wt[(ci*9 + kk)*128 + po] = w[i];
    }
}

// ------------------------------------------------------------------
// conv_p: 136ch (z + afin, instance-normed on the fly) -> 128ch, leaky,
// write channel-last (l,m,p). grid (12,12,8 ocg), block 256.
// Each thread: 4 horizontally adjacent pixels x 16 out channels.
// ------------------------------------------------------------------
__global__ void convp_kernel(const float* __restrict__ z, const float* __restrict__ afin,
                             const float* __restrict__ wt, const float* __restrict__ bias,
                             const float* __restrict__ mean136, const float* __restrict__ rstd136,
                             float* __restrict__ out){
    __shared__ float tin[4*1156];   // 4 channels x 34x34 halo
    __shared__ float wsm[576];      // 4ci x 9k x 16po
    int t = threadIdx.x;
    int x0b = blockIdx.x*32, y0 = blockIdx.y*32, ocg = blockIdx.z;
    int X0 = (t & 7)*4, y = t >> 3;

    float4 b0 = *(const float4*)(bias + ocg*16);
    float4 b1 = *(const float4*)(bias + ocg*16 + 4);
    float4 b2 = *(const float4*)(bias + ocg*16 + 8);
    float4 b3 = *(const float4*)(bias + ocg*16 + 12);
    float acc[4][16];
    #pragma unroll
    for (int px = 0; px < 4; px++){
        acc[px][0]=b0.x; acc[px][1]=b0.y; acc[px][2]=b0.z; acc[px][3]=b0.w;
        acc[px][4]=b1.x; acc[px][5]=b1.y; acc[px][6]=b1.z; acc[px][7]=b1.w;
        acc[px][8]=b2.x; acc[px][9]=b2.y; acc[px][10]=b2.z; acc[px][11]=b2.w;
        acc[px][12]=b3.x; acc[px][13]=b3.y; acc[px][14]=b3.z; acc[px][15]=b3.w;
    }

    for (int ci0 = 0; ci0 < 136; ci0 += 4){
        __syncthreads();
        // weights for this (ci chunk, ocg)
        for (int i = t; i < 576; i += 256){
            int c = i / 144, rr = i % 144, kk = rr >> 4, po = rr & 15;
            wsm[i] = wt[((ci0 + c)*9 + kk)*128 + ocg*16 + po];
        }
        float mm0 = mean136[ci0],   rr0 = rstd136[ci0];
        float mm1 = mean136[ci0+1], rr1 = rstd136[ci0+1];
        float mm2 = mean136[ci0+2], rr2 = rstd136[ci0+2];
        float mm3 = mean136[ci0+3], rr3 = rstd136[ci0+3];
        if (ci0 < 128){
            for (int i = t; i < 1156; i += 256){
                int hy = i / 34, hx = i - hy*34;
                int gy = y0 - 1 + hy, gx = x0b - 1 + hx;
                bool inb = ((unsigned)gy < 384u) && ((unsigned)gx < 384u);
                float4 v = make_float4(0.f,0.f,0.f,0.f);
                if (inb) v = *(const float4*)(z + (size_t)(gy*L + gx)*128 + ci0);
                tin[i]        = inb ? (v.x - mm0)*rr0 : 0.f;
                tin[1156 + i] = inb ? (v.y - mm1)*rr1 : 0.f;
                tin[2312 + i] = inb ? (v.z - mm2)*rr2 : 0.f;
                tin[3468 + i] = inb ? (v.w - mm3)*rr3 : 0.f;
            }
        } else {
            for (int i = t; i < 1156; i += 256){
                int hy = i / 34, hx = i - hy*34;
                int gy = y0 - 1 + hy, gx = x0b - 1 + hx;
                bool inb = ((unsigned)gy < 384u) && ((unsigned)gx < 384u);
                int sp = gy*L + gx;
                tin[i]        = inb ? (afin[(ci0-128)*SPAT + sp] - mm0)*rr0 : 0.f;
                tin[1156 + i] = inb ? (afin[(ci0-127)*SPAT + sp] - mm1)*rr1 : 0.f;
                tin[2312 + i] = inb ? (afin[(ci0-126)*SPAT + sp] - mm2)*rr2 : 0.f;
                tin[3468 + i] = inb ? (afin[(ci0-125)*SPAT + sp] - mm3)*rr3 : 0.f;
            }
        }
        __syncthreads();

        #pragma unroll
        for (int c = 0; c < 4; c++){
            float iv[3][6];
            #pragma unroll
            for (int ky = 0; ky < 3; ky++)
                #pragma unroll
                for (int j = 0; j < 6; j++)
                    iv[ky][j] = tin[c*1156 + (y+ky)*34 + X0 + j];
            #pragma unroll
            for (int ky = 0; ky < 3; ky++)
            #pragma unroll
            for (int kx = 0; kx < 3; kx++){
                const float* wp = &wsm[(c*9 + ky*3 + kx)*16];
                float4 w0 = *(const float4*)wp;
                float4 w1 = *(const float4*)(wp + 4);
                float4 w2 = *(const float4*)(wp + 8);
                float4 w3 = *(const float4*)(wp + 12);
                #pragma unroll
                for (int px = 0; px < 4; px++){
                    float inv = iv[ky][px + kx];
                    acc[px][0]  += inv*w0.x; acc[px][1]  += inv*w0.y;
                    acc[px][2]  += inv*w0.z; acc[px][3]  += inv*w0.w;
                    acc[px][4]  += inv*w1.x; acc[px][5]  += inv*w1.y;
                    acc[px][6]  += inv*w1.z; acc[px][7]  += inv*w1.w;
                    acc[px][8]  += inv*w2.x; acc[px][9]  += inv*w2.y;
                    acc[px][10] += inv*w2.z; acc[px][11] += inv*w2.w;
                    acc[px][12] += inv*w3.x; acc[px][13] += inv*w3.y;
                    acc[px][14] += inv*w3.z; acc[px][15] += inv*w3.w;
                }
            }
        }
    }
    int gy = y0 + y;
    #pragma unroll
    for (int px = 0; px < 4; px++){
        int gx = x0b + X0 + px;
        float* o = out + (size_t)(gy*L + gx)*128 + ocg*16;
        float4 o0 = make_float4(lrelu(acc[px][0]), lrelu(acc[px][1]), lrelu(acc[px][2]), lrelu(acc[px][3]));
        float4 o1 = make_float4(lrelu(acc[px][4]), lrelu(acc[px][5]), lrelu(acc[px][6]), lrelu(acc[px][7]));
        float4 o2 = make_float4(lrelu(acc[px][8]), lrelu(acc[px][9]), lrelu(acc[px][10]), lrelu(acc[px][11]));
        float4 o3 = make_float4(lrelu(acc[px][12]), lrelu(acc[px][13]), lrelu(acc[px][14]), lrelu(acc[px][15]));
        *(float4*)(o)      = o0;
        *(float4*)(o + 4)  = o1;
        *(float4*)(o + 8)  = o2;
        *(float4*)(o + 12) = o3;
    }
}

// ------------------------------------------------------------------
extern "C" void kernel_launch(void* const* d_in, const int* in_sizes, int n_in,
                              void* d_out, int out_size){
    (void)in_sizes; (void)n_in; (void)out_size;
    const float* x        = (const float*)d_in[0];
    const float* z        = (const float*)d_in[1];
    const float* plddt    = (const float*)d_in[2];
    const float* Wq       = (const float*)d_in[3];
    const float* Wk       = (const float*)d_in[4];
    const float* Wv       = (const float*)d_in[5];
    const float* Wp2a     = (const float*)d_in[6];
    const float* conv_a_w = (const float*)d_in[7];
    const float* conv_a_b = (const float*)d_in[8];
    const float* conv_m_w = (const float*)d_in[9];
    const float* conv_m_b = (const float*)d_in[10];
    const float* ln1_w    = (const float*)d_in[11];
    const float* ln1_b    = (const float*)d_in[12];
    const float* lin1_w   = (const float*)d_in[13];
    const float* lin1_b   = (const float*)d_in[14];
    const float* ln2_w    = (const float*)d_in[15];
    const float* ln2_b    = (const float*)d_in[16];
    const float* lin2_w   = (const float*)d_in[17];
    const float* lin2_b   = (const float*)d_in[18];
    const float* lnf_w    = (const float*)d_in[19];
    const float* lnf_b    = (const float*)d_in[20];
    const float* conv_p_w = (const float*)d_in[21];
    const float* conv_p_b = (const float*)d_in[22];
    float* out = (float*)d_out;

    float* S = nullptr;
    cudaGetSymbolAddress((void**)&S, g_scratch);
    float* q       = S + OFF_Q;
    float* k       = S + OFF_K;
    float* v       = S + OFF_V;
    float* a2h     = S + OFF_A2H;
    float* a8      = S + OFF_A8;
    float* afin    = S + OFF_AFIN;
    float* cat     = S + OFF_CAT;
    float* catn    = S + OFF_CATN;
    float* h1      = S + OFF_H1;
    float* h2      = S + OFF_H2;
    float* h3      = S + OFF_H3;
    float* wt      = S + OFF_WT;
    float* mean16  = S + OFF_MEAN16;
    float* rstd16  = S + OFF_RSTD16;
    float* mean9   = S + OFF_MEAN9;
    float* rstd9   = S + OFF_RSTD9;
    float* mean136 = S + OFF_MEAN136;
    float* rstd136 = S + OFF_RSTD136;
    float* psum    = S + OFF_PSUM;
    float* psq     = S + OFF_PSQ;

    // z per-channel stats (channels 0..127 of zp) — independent, start early
    zstats1_kernel<<<384, 256>>>(z, psum, psq);
    zstats2_kernel<<<128, 128>>>(psum, psq, mean136, rstd136);
    // conv_p weight transpose — independent
    wprep_kernel<<<612, 256>>>(conv_p_w, wt);

    // qkv + attention logits
    qkv_kernel<<<384, 256>>>(x, Wq, Wk, Wv, q, k, v);
    apair_kernel<<<dim3(48, 384), 256>>>(z, Wp2a, a2h);
    anode_kernel<<<dim3(12, 12, 8), dim3(32, 32)>>>(q, k, a2h);

    // conv_a path
    stats_kernel<<<16, 256>>>(a2h, 16, nullptr, mean16, rstd16);
    conva_kernel<<<dim3(24, 24), 256>>>(a2h, conv_a_w, conv_a_b, mean16, rstd16, a8);

    // conv_m path
    stats_kernel<<<9, 256>>>(a8, 8, plddt, mean9, rstd9);
    convm_kernel<<<dim3(24, 24), 256>>>(a8, plddt, conv_m_w, conv_m_b, mean9, rstd9, afin);

    // stats for afin channels (128..135 of zp)
    stats_kernel<<<8, 256>>>(afin, 8, nullptr, mean136 + 128, rstd136 + 128);

    // aggregations
    nfn_kernel<<<dim3(8, 12), dim3(32, 32)>>>(afin, v, cat);
    nfp_kernel<<<384, 256>>>(afin, z, cat);

    // MLP + final node LN
    ln_kernel<<<384, 256, 1280*sizeof(float)>>>(cat, nullptr, catn, ln1_w, ln1_b, 1280, 0);
    gemm_kernel<<<dim3(16, 12), dim3(16, 16)>>>(catn, lin1_w, lin1_b, h1, 384, 512, 1280);
    ln_kernel<<<384, 256, 512*sizeof(float)>>>(h1, nullptr, h2, ln2_w, ln2_b, 512, 1);
    gemm_kernel<<<dim3(8, 12), dim3(16, 16)>>>(h2, lin2_w, lin2_b, h3, 384, 256, 512);
    ln_kernel<<<384, 256, 256*sizeof(float)>>>(h3, x, out, lnf_w, lnf_b, 256, 0);

    // pair update
    convp_kernel<<<dim3(12, 12, 8), 256>>>(z, afin, wt, conv_p_b, mean136, rstd136,
                                           out + 384*256);
}

// round 10
// speedup vs baseline: 1.1272x; 1.1272x over previous
#include <cuda_runtime.h>
#include <cstdint>
#include <cstddef>

// Shapes: N=1, L=384, NODE=256, H=8, HD=32, PD=128, D1=1280
#define L 384
#define SPAT 147456       // 384*384
#define NODE 256
#define NH 8
#define HD 32
#define PD 128

// ---- scratch layout (floats) ----
#define OFF_Q       0          // 98304
#define OFF_K       98304
#define OFF_V       196608
#define OFF_A2H     294912     // 16*147456 = 2359296
#define OFF_A8      2654208    // 8*147456 = 1179648
#define OFF_AFIN    3833856    // 1179648
#define OFF_CAT     5013504    // 384*1280 = 491520
#define OFF_CATN    5505024    // 491520
#define OFF_H1      5996544    // 384*512
#define OFF_H2      6193152    // 384*512
#define OFF_H3      6389760    // 384*256
#define OFF_WT      6488064    // 136*9*128 = 156672
#define OFF_MEAN16  6644736
#define OFF_RSTD16  6644752
#define OFF_MEAN9   6644768
#define OFF_RSTD9   6644784
#define OFF_MEAN136 6644800    // 160 slots
#define OFF_RSTD136 6644960    // 160 slots
#define OFF_PSUM    6645120    // 128*384
#define OFF_PSQ     6694272    // 128*384
#define SCRATCH_FLOATS 6743424

__device__ float g_scratch[SCRATCH_FLOATS];

__device__ __forceinline__ float lrelu(float v){ return v >= 0.f ? v : 0.01f*v; }

// ---- packed f32x2 helpers (FFMA2 path, sm_100+) ----
typedef unsigned long long ull;
__device__ __forceinline__ ull dup2(float v){
    ull r; unsigned u = __float_as_uint(v);
    asm("mov.b64 %0, {%1, %1};" : "=l"(r) : "r"(u));
    return r;
}
__device__ __forceinline__ ull pack2(float a, float b){
    ull r;
    asm("mov.b64 %0, {%1, %2};" : "=l"(r) : "r"(__float_as_uint(a)), "r"(__float_as_uint(b)));
    return r;
}
__device__ __forceinline__ void fma2(ull &acc, ull a, ull b){
    asm("fma.rn.f32x2 %0, %1, %2, %0;" : "+l"(acc) : "l"(a), "l"(b));
}
__device__ __forceinline__ float2 unpk(ull v){
    unsigned lo, hi;
    asm("mov.b64 {%0, %1}, %2;" : "=r"(lo), "=r"(hi) : "l"(v));
    return make_float2(__uint_as_float(lo), __uint_as_float(hi));
}

// ------------------------------------------------------------------
// q,k,v = x @ Wq/Wk/Wv     grid 48 (8 rows per block), block 256
// W traffic amortized 8x vs one-row-per-block version.
// ------------------------------------------------------------------
__global__ void qkv_kernel(const float* __restrict__ x, const float* __restrict__ Wq,
                           const float* __restrict__ Wk, const float* __restrict__ Wv,
                           float* __restrict__ q, float* __restrict__ k, float* __restrict__ v){
    __shared__ float xs[8*256];
    int l0 = blockIdx.x*8, t = threadIdx.x;
    #pragma unroll
    for (int r = 0; r < 8; r++) xs[r*256 + t] = x[(l0+r)*256 + t];
    __syncthreads();
    float aq[8], ak[8], av[8];
    #pragma unroll
    for (int r = 0; r < 8; r++){ aq[r]=0.f; ak[r]=0.f; av[r]=0.f; }
    #pragma unroll 4
    for (int i = 0; i < 256; i++){
        float wq = Wq[i*256 + t], wk = Wk[i*256 + t], wv = Wv[i*256 + t];
        #pragma unroll
        for (int r = 0; r < 8; r++){
            float xv = xs[r*256 + i];
            aq[r] += xv*wq; ak[r] += xv*wk; av[r] += xv*wv;
        }
    }
    #pragma unroll
    for (int r = 0; r < 8; r++){
        q[(l0+r)*256 + t] = aq[r];
        k[(l0+r)*256 + t] = ak[r];
        v[(l0+r)*256 + t] = av[r];
    }
}

// ------------------------------------------------------------------
// a_pair[h][l][m] = z[l,m,:] . Wp2a[:,h]   (channels 0..7 of a2h)
// ------------------------------------------------------------------
__global__ void apair_kernel(const float* __restrict__ z, const float* __restrict__ Wp2a,
                             float* __restrict__ a2h){
    __shared__ float ws[128*9]; // padded: ws[p*9+h]
    int t = threadIdx.x;
    for (int i = t; i < 1024; i += 256){
        int p = i >> 3, h = i & 7;
        ws[p*9 + h] = Wp2a[i];
    }
    __syncthreads();
    int lane = t & 31, wp = t >> 5;
    int m = blockIdx.x*8 + wp;
    int l = blockIdx.y;
    const float4 zv = *(const float4*)(z + ((size_t)l*L + m)*128 + lane*4);
    int p = lane*4;
    float acc[8];
    #pragma unroll
    for (int h = 0; h < 8; h++){
        acc[h] = zv.x*ws[p*9 + h] + zv.y*ws[(p+1)*9 + h]
               + zv.z*ws[(p+2)*9 + h] + zv.w*ws[(p+3)*9 + h];
    }
    #pragma unroll
    for (int h = 0; h < 8; h++){
        float s = acc[h];
        for (int o = 16; o > 0; o >>= 1) s += __shfl_down_sync(0xffffffffu, s, o);
        if (lane == 0) a2h[h*SPAT + l*L + m] = s;
    }
}

// ------------------------------------------------------------------
// a_node[h][l][m] = q[l,h,:].k[m,h,:]/sqrt(32)  (channels 8..15)
// ------------------------------------------------------------------
__global__ void anode_kernel(const float* __restrict__ q, const float* __restrict__ k,
                             float* __restrict__ a2h){
    int h = blockIdx.z;
    int l0 = blockIdx.y*32, m0 = blockIdx.x*32;
    __shared__ float Qs[32][33], Ks[32][33];
    int tx = threadIdx.x, ty = threadIdx.y;
    Qs[ty][tx] = q[(l0+ty)*256 + h*32 + tx];
    Ks[ty][tx] = k[(m0+ty)*256 + h*32 + tx];
    __syncthreads();
    float acc = 0.f;
    #pragma unroll
    for (int d = 0; d < 32; d++) acc += Qs[ty][d]*Ks[tx][d];
    a2h[(8+h)*SPAT + (l0+ty)*L + m0 + tx] = acc * 0.17677669529663687f;
}

// ------------------------------------------------------------------
// Per-channel instance-norm stats for channel-first contiguous buffers
// ------------------------------------------------------------------
__global__ void stats_kernel(const float* __restrict__ srcA, int nA,
                             const float* __restrict__ srcB,
                             float* __restrict__ mean, float* __restrict__ rstd){
    int c = blockIdx.x, t = threadIdx.x;
    const float* p = (c < nA) ? srcA + (size_t)c*SPAT : srcB + (size_t)(c-nA)*SPAT;
    const float4* p4 = (const float4*)p;
    float s = 0.f, s2 = 0.f;
    for (int i = t; i < SPAT/4; i += 256){
        float4 v = p4[i];
        s  += v.x + v.y + v.z + v.w;
        s2 += v.x*v.x + v.y*v.y + v.z*v.z + v.w*v.w;
    }
    __shared__ float ss[256], ss2[256];
    ss[t] = s; ss2[t] = s2; __syncthreads();
    for (int o = 128; o > 0; o >>= 1){
        if (t < o){ ss[t] += ss[t+o]; ss2[t] += ss2[t+o]; }
        __syncthreads();
    }
    if (t == 0){
        float m = ss[0] * (1.f/SPAT);
        float var = ss2[0] * (1.f/SPAT) - m*m;
        mean[c] = m; rstd[c] = rsqrtf(var + 1e-5f);
    }
}

// z channel stats, stage 1: per-(l) partials, deterministic. grid 384, block 256.
__global__ void zstats1_kernel(const float* __restrict__ z,
                               float* __restrict__ psum, float* __restrict__ psq){
    int l = blockIdx.x, t = threadIdx.x;
    int c = t & 127, half = t >> 7;
    const float* base = z + (size_t)l*L*128;
    float s = 0.f, s2 = 0.f;
    for (int m = half; m < L; m += 2){
        float v = base[m*128 + c];
        s += v; s2 += v*v;
    }
    __shared__ float sh[256], sh2[256];
    sh[t] = s; sh2[t] = s2; __syncthreads();
    if (half == 0){
        psum[c*L + l] = sh[t] + sh[t+128];
        psq [c*L + l] = sh2[t] + sh2[t+128];
    }
}

// stage 2: reduce over l. grid 128, block 128.
__global__ void zstats2_kernel(const float* __restrict__ psum, const float* __restrict__ psq,
                               float* __restrict__ mean, float* __restrict__ rstd){
    int c = blockIdx.x, t = threadIdx.x;
    float s = 0.f, s2 = 0.f;
    for (int l = t; l < L; l += 128){ s += psum[c*L + l]; s2 += psq[c*L + l]; }
    __shared__ float ss[128], ss2[128];
    ss[t] = s; ss2[t] = s2; __syncthreads();
    for (int o = 64; o > 0; o >>= 1){
        if (t < o){ ss[t] += ss[t+o]; ss2[t] += ss2[t+o]; }
        __syncthreads();
    }
    if (t == 0){
        float m = ss[0] * (1.f/SPAT);
        float var = ss2[0] * (1.f/SPAT) - m*m;
        mean[c] = m; rstd[c] = rsqrtf(var + 1e-5f);
    }
}

// ------------------------------------------------------------------
// conv_a: 16ch (instance-normed a2h) -> 8ch, 3x3 SAME, leaky. grid (24,24), 256 thr
// ------------------------------------------------------------------
__global__ void conva_kernel(const float* __restrict__ a2h, const float* __restrict__ w,
                             const float* __restrict__ bias, const float* __restrict__ mean,
                             const float* __restrict__ rstd, float* __restrict__ a8){
    __shared__ float tin[16*324];
    __shared__ float wk[1152];
    int t = threadIdx.x;
    for (int i = t; i < 1152; i += 256) wk[i] = w[i];
    int x0 = blockIdx.x*16 - 1, y0 = blockIdx.y*16 - 1;
    for (int i = t; i < 16*324; i += 256){
        int c = i / 324, r = i % 324;
        int gy = y0 + r/18, gx = x0 + r%18;
        float v = 0.f;
        if ((unsigned)gy < 384u && (unsigned)gx < 384u)
            v = (a2h[c*SPAT + gy*L + gx] - mean[c]) * rstd[c];
        tin[i] = v;
    }
    __syncthreads();
    int lx = t & 15, ly = t >> 4;
    float acc[8];
    #pragma unroll
    for (int o = 0; o < 8; o++) acc[o] = bias[o];
    for (int c = 0; c < 16; c++){
        float iv[9];
        #pragma unroll
        for (int ky = 0; ky < 3; ky++)
            #pragma unroll
            for (int kx = 0; kx < 3; kx++)
                iv[ky*3+kx] = tin[c*324 + (ly+ky)*18 + lx + kx];
        #pragma unroll
        for (int o = 0; o < 8; o++){
            const float* wp = &wk[(o*16 + c)*9];
            acc[o] += wp[0]*iv[0]+wp[1]*iv[1]+wp[2]*iv[2]
                    + wp[3]*iv[3]+wp[4]*iv[4]+wp[5]*iv[5]
                    + wp[6]*iv[6]+wp[7]*iv[7]+wp[8]*iv[8];
        }
    }
    int gx = blockIdx.x*16 + lx, gy = blockIdx.y*16 + ly;
    #pragma unroll
    for (int o = 0; o < 8; o++)
        a8[o*SPAT + gy*L + gx] = lrelu(acc[o]);
}

// conv_m: 9ch (a8 normed + plddt normed) -> 8ch, leaky. grid (24,24), 256 thr
__global__ void convm_kernel(const float* __restrict__ a8, const float* __restrict__ plddt,
                             const float* __restrict__ w, const float* __restrict__ bias,
                             const float* __restrict__ mean, const float* __restrict__ rstd,
                             float* __restrict__ afin){
    __shared__ float tin[9*324];
    __shared__ float wk[648];
    int t = threadIdx.x;
    for (int i = t; i < 648; i += 256) wk[i] = w[i];
    int x0 = blockIdx.x*16 - 1, y0 = blockIdx.y*16 - 1;
    for (int i = t; i < 9*324; i += 256){
        int c = i / 324, r = i % 324;
        int gy = y0 + r/18, gx = x0 + r%18;
        float v = 0.f;
        if ((unsigned)gy < 384u && (unsigned)gx < 384u){
            float raw = (c < 8) ? a8[c*SPAT + gy*L + gx] : plddt[gy*L + gx];
            v = (raw - mean[c]) * rstd[c];
        }
        tin[i] = v;
    }
    __syncthreads();
    int lx = t & 15, ly = t >> 4;
    float acc[8];
    #pragma unroll
    for (int o = 0; o < 8; o++) acc[o] = bias[o];
    for (int c = 0; c < 9; c++){
        float iv[9];
        #pragma unroll
        for (int ky = 0; ky < 3; ky++)
            #pragma unroll
            for (int kx = 0; kx < 3; kx++)
                iv[ky*3+kx] = tin[c*324 + (ly+ky)*18 + lx + kx];
        #pragma unroll
        for (int o = 0; o < 8; o++){
            const float* wp = &wk[(o*9 + c)*9];
            acc[o] += wp[0]*iv[0]+wp[1]*iv[1]+wp[2]*iv[2]
                    + wp[3]*iv[3]+wp[4]*iv[4]+wp[5]*iv[5]
                    + wp[6]*iv[6]+wp[7]*iv[7]+wp[8]*iv[8];
        }
    }
    int gx = blockIdx.x*16 + lx, gy = blockIdx.y*16 + ly;
    #pragma unroll
    for (int o = 0; o < 8; o++)
        afin[o*SPAT + gy*L + gx] = lrelu(acc[o]);
}

// ------------------------------------------------------------------
// nfn: cat[l, 1024 + h*32+d] = sum_m afin[h][l][m] * v[m, h*32+d]
// ------------------------------------------------------------------
__global__ void nfn_kernel(const float* __restrict__ afin, const float* __restrict__ v,
                           float* __restrict__ cat){
    int h = blockIdx.x, l0 = blockIdx.y*32;
    int tx = threadIdx.x, ty = threadIdx.y;
    __shared__ float As[32][33], Vs[32][33];
    float acc = 0.f;
    for (int m0 = 0; m0 < L; m0 += 32){
        As[ty][tx] = afin[h*SPAT + (l0+ty)*L + m0 + tx];
        Vs[ty][tx] = v[(m0+ty)*256 + h*32 + tx];
        __syncthreads();
        #pragma unroll
        for (int kk = 0; kk < 32; kk++) acc += As[ty][kk]*Vs[kk][tx];
        __syncthreads();
    }
    cat[(size_t)(l0+ty)*1280 + 1024 + h*32 + tx] = acc;
}

// nfp: cat[l, h*128+p] = sum_m afin[h][l][m] * z[l,m,p].  grid 384, block 256
__global__ void nfp_kernel(const float* __restrict__ afin, const float* __restrict__ z,
                           float* __restrict__ cat){
    int l = blockIdx.x, t = threadIdx.x;
    __shared__ float As[8][32];
    __shared__ float Zs[32*128];
    int p = t & 127, hb = (t >> 7)*4;
    float acc0 = 0.f, acc1 = 0.f, acc2 = 0.f, acc3 = 0.f;
    for (int m0 = 0; m0 < L; m0 += 32){
        __syncthreads();
        { int hh = t >> 5, mm = t & 31; As[hh][mm] = afin[hh*SPAT + l*L + m0 + mm]; }
        const float4* zsrc = (const float4*)(z + ((size_t)l*L + m0)*128);
        float4* zd = (float4*)Zs;
        for (int i = t; i < 1024; i += 256) zd[i] = zsrc[i];
        __syncthreads();
        #pragma unroll 8
        for (int mm = 0; mm < 32; mm++){
            float zv = Zs[mm*128 + p];
            acc0 += As[hb  ][mm]*zv;
            acc1 += As[hb+1][mm]*zv;
            acc2 += As[hb+2][mm]*zv;
            acc3 += As[hb+3][mm]*zv;
        }
    }
    cat[(size_t)l*1280 + (hb  )*128 + p] = acc0;
    cat[(size_t)l*1280 + (hb+1)*128 + p] = acc1;
    cat[(size_t)l*1280 + (hb+2)*128 + p] = acc2;
    cat[(size_t)l*1280 + (hb+3)*128 + p] = acc3;
}

// ------------------------------------------------------------------
// row LayerNorm: out = [(in+add?) - m]/sqrt(v+eps)*w + b  (opt leaky)
// ------------------------------------------------------------------
__global__ void ln_kernel(const float* __restrict__ in, const float* __restrict__ add,
                          float* __restrict__ out, const float* __restrict__ w,
                          const float* __restrict__ b, int D, int do_leaky){
    extern __shared__ float sh[];
    __shared__ float red[256];
    int r = blockIdx.x, t = threadIdx.x;
    float s = 0.f;
    for (int i = t; i < D; i += 256){
        float v = in[(size_t)r*D + i];
        if (add) v += add[(size_t)r*D + i];
        sh[i] = v; s += v;
    }
    red[t] = s; __syncthreads();
    for (int o = 128; o > 0; o >>= 1){ if (t < o) red[t] += red[t+o]; __syncthreads(); }
    float mean = red[0] / D;
    __syncthreads();
    float s2 = 0.f;
    for (int i = t; i < D; i += 256){ float d = sh[i] - mean; s2 += d*d; }
    red[t] = s2; __syncthreads();
    for (int o = 128; o > 0; o >>= 1){ if (t < o) red[t] += red[t+o]; __syncthreads(); }
    float rstd = rsqrtf(red[0]/D + 1e-5f);
    for (int i = t; i < D; i += 256){
        float v = (sh[i] - mean)*rstd*w[i] + b[i];
        if (do_leaky) v = lrelu(v);
        out[(size_t)r*D + i] = v;
    }
}

// generic GEMM C = A(MxK) @ B(KxN) + bias.  block (16,16), tiles 32x32x32
__global__ void gemm_kernel(const float* __restrict__ A, const float* __restrict__ B,
                            const float* __restrict__ bias, float* __restrict__ C,
                            int M, int N, int K){
    __shared__ float As[32][33], Bs[32][33];
    int tx = threadIdx.x, ty = threadIdx.y;
    int t = ty*16 + tx;
    int r0 = blockIdx.y*32, c0 = blockIdx.x*32;
    float a00 = 0.f, a01 = 0.f, a10 = 0.f, a11 = 0.f;
    for (int k0 = 0; k0 < K; k0 += 32){
        for (int i = t; i < 1024; i += 256){
            int rr = i >> 5, cc = i & 31;
            As[rr][cc] = A[(size_t)(r0+rr)*K + k0 + cc];
            Bs[rr][cc] = B[(size_t)(k0+rr)*N + c0 + cc];
        }
        __syncthreads();
        #pragma unroll
        for (int kk = 0; kk < 32; kk++){
            float av0 = As[ty*2][kk], av1 = As[ty*2+1][kk];
            float bv0 = Bs[kk][tx*2], bv1 = Bs[kk][tx*2+1];
            a00 += av0*bv0; a01 += av0*bv1; a10 += av1*bv0; a11 += av1*bv1;
        }
        __syncthreads();
    }
    int r = r0 + ty*2, c = c0 + tx*2;
    C[(size_t)r*N + c]       = a00 + bias[c];
    C[(size_t)r*N + c+1]     = a01 + bias[c+1];
    C[(size_t)(r+1)*N + c]   = a10 + bias[c];
    C[(size_t)(r+1)*N + c+1] = a11 + bias[c+1];
}

// transpose conv_p weights (128,136,3,3) -> wt[(ci*9+k)*128 + po]
__global__ void wprep_kernel(const float* __restrict__ w, float* __restrict__ wt){
    int i = blockIdx.x*256 + threadIdx.x;  // 156672 total
    if (i < 156672){
        int po = i / 1224, rem = i % 1224;
        int ci = rem / 9, kk = rem % 9;
        wt[(ci*9 + kk)*128 + po] = w[i];
    }
}

// ------------------------------------------------------------------
// conv_p: 136ch (z + afin, instance-normed on the fly) -> 128ch, leaky,
// packed f32x2 FFMA2 math: out-channel pairs in 64-bit accumulators.
// grid (12,12,8 ocg), block 256. Thread: 4 px x 16 oc (= 4x8 f32x2).
// Input halo tile uses row stride 36 so window loads are float4-aligned.
// ------------------------------------------------------------------
__global__ void __launch_bounds__(256, 1)
convp_kernel(const float* __restrict__ z, const float* __restrict__ afin,
             const float* __restrict__ wt, const float* __restrict__ bias,
             const float* __restrict__ mean136, const float* __restrict__ rstd136,
             float* __restrict__ out){
    __shared__ float tin[4*1224];   // 4 channels x 34 rows x stride 36
    __shared__ float wsm[576];      // 4ci x 9k x 16po
    int t = threadIdx.x;
    int x0b = blockIdx.x*32, y0 = blockIdx.y*32, ocg = blockIdx.z;
    int X0 = (t & 7)*4, y = t >> 3;

    const float* bp = bias + ocg*16;
    ull acc[4][8];
    #pragma unroll
    for (int j = 0; j < 8; j++){
        ull bj = pack2(bp[2*j], bp[2*j+1]);
        #pragma unroll
        for (int px = 0; px < 4; px++) acc[px][j] = bj;
    }

    for (int ci0 = 0; ci0 < 136; ci0 += 4){
        __syncthreads();
        // weights for this (ci chunk, ocg)
        for (int i = t; i < 576; i += 256){
            int c = i / 144, rr = i % 144, kk = rr >> 4, po = rr & 15;
            wsm[i] = wt[((ci0 + c)*9 + kk)*128 + ocg*16 + po];
        }
        float mm0 = mean136[ci0],   rr0 = rstd136[ci0];
        float mm1 = mean136[ci0+1], rr1 = rstd136[ci0+1];
        float mm2 = mean136[ci0+2], rr2 = rstd136[ci0+2];
        float mm3 = mean136[ci0+3], rr3 = rstd136[ci0+3];
        if (ci0 < 128){
            for (int i = t; i < 1156; i += 256){
                int hy = i / 34, hx = i - hy*34;
                int gy = y0 - 1 + hy, gx = x0b - 1 + hx;
                bool inb = ((unsigned)gy < 384u) && ((unsigned)gx < 384u);
                float4 v = make_float4(0.f,0.f,0.f,0.f);
                if (inb) v = *(const float4*)(z + (size_t)(gy*L + gx)*128 + ci0);
                int si = hy*36 + hx;
                tin[si]        = inb ? (v.x - mm0)*rr0 : 0.f;
                tin[1224 + si] = inb ? (v.y - mm1)*rr1 : 0.f;
                tin[2448 + si] = inb ? (v.z - mm2)*rr2 : 0.f;
                tin[3672 + si] = inb ? (v.w - mm3)*rr3 : 0.f;
            }
        } else {
            for (int i = t; i < 1156; i += 256){
                int hy = i / 34, hx = i - hy*34;
                int gy = y0 - 1 + hy, gx = x0b - 1 + hx;
                bool inb = ((unsigned)gy < 384u) && ((unsigned)gx < 384u);
                int sp = gy*L + gx;
                int si = hy*36 + hx;
                tin[si]        = inb ? (afin[(ci0-128)*SPAT + sp] - mm0)*rr0 : 0.f;
                tin[1224 + si] = inb ? (afin[(ci0-127)*SPAT + sp] - mm1)*rr1 : 0.f;
                tin[2448 + si] = inb ? (afin[(ci0-126)*SPAT + sp] - mm2)*rr2 : 0.f;
                tin[3672 + si] = inb ? (afin[(ci0-125)*SPAT + sp] - mm3)*rr3 : 0.f;
            }
        }
        __syncthreads();

        #pragma unroll
        for (int c = 0; c < 4; c++){
            // load 3 x 6-wide input windows, duplicate into f32x2
            ull ivp[3][6];
            #pragma unroll
            for (int ky = 0; ky < 3; ky++){
                const float* row = &tin[c*1224 + (y+ky)*36 + X0];
                float4 v4 = *(const float4*)row;
                float2 v2 = *(const float2*)(row + 4);
                ivp[ky][0] = dup2(v4.x); ivp[ky][1] = dup2(v4.y);
                ivp[ky][2] = dup2(v4.z); ivp[ky][3] = dup2(v4.w);
                ivp[ky][4] = dup2(v2.x); ivp[ky][5] = dup2(v2.y);
            }
            #pragma unroll
            for (int ky = 0; ky < 3; ky++)
            #pragma unroll
            for (int kx = 0; kx < 3; kx++){
                const ulonglong2* wp = (const ulonglong2*)&wsm[(c*9 + ky*3 + kx)*16];
                ulonglong2 wA = wp[0], wB = wp[1], wC = wp[2], wD = wp[3];
                #pragma unroll
                for (int px = 0; px < 4; px++){
                    ull inv = ivp[ky][kx + px];
                    fma2(acc[px][0], wA.x, inv); fma2(acc[px][1], wA.y, inv);
                    fma2(acc[px][2], wB.x, inv); fma2(acc[px][3], wB.y, inv);
                    fma2(acc[px][4], wC.x, inv); fma2(acc[px][5], wC.y, inv);
                    fma2(acc[px][6], wD.x, inv); fma2(acc[px][7], wD.y, inv);
                }
            }
        }
    }
    int gy = y0 + y;
    #pragma unroll
    for (int px = 0; px < 4; px++){
        int gx = x0b + X0 + px;
        float* o = out + (size_t)(gy*L + gx)*128 + ocg*16;
        float vals[16];
        #pragma unroll
        for (int j = 0; j < 8; j++){
            float2 p = unpk(acc[px][j]);
            vals[2*j]   = lrelu(p.x);
            vals[2*j+1] = lrelu(p.y);
        }
        #pragma unroll
        for (int j = 0; j < 4; j++)
            *(float4*)(o + 4*j) = make_float4(vals[4*j], vals[4*j+1], vals[4*j+2], vals[4*j+3]);
    }
}

// ------------------------------------------------------------------
extern "C" void kernel_launch(void* const* d_in, const int* in_sizes, int n_in,
                              void* d_out, int out_size){
    (void)in_sizes; (void)n_in; (void)out_size;
    const float* x        = (const float*)d_in[0];
    const float* z        = (const float*)d_in[1];
    const float* plddt    = (const float*)d_in[2];
    const float* Wq       = (const float*)d_in[3];
    const float* Wk       = (const float*)d_in[4];
    const float* Wv       = (const float*)d_in[5];
    const float* Wp2a     = (const float*)d_in[6];
    const float* conv_a_w = (const float*)d_in[7];
    const float* conv_a_b = (const float*)d_in[8];
    const float* conv_m_w = (const float*)d_in[9];
    const float* conv_m_b = (const float*)d_in[10];
    const float* ln1_w    = (const float*)d_in[11];
    const float* ln1_b    = (const float*)d_in[12];
    const float* lin1_w   = (const float*)d_in[13];
    const float* lin1_b   = (const float*)d_in[14];
    const float* ln2_w    = (const float*)d_in[15];
    const float* ln2_b    = (const float*)d_in[16];
    const float* lin2_w   = (const float*)d_in[17];
    const float* lin2_b   = (const float*)d_in[18];
    const float* lnf_w    = (const float*)d_in[19];
    const float* lnf_b    = (const float*)d_in[20];
    const float* conv_p_w = (const float*)d_in[21];
    const float* conv_p_b = (const float*)d_in[22];
    float* out = (float*)d_out;

    float* S = nullptr;
    cudaGetSymbolAddress((void**)&S, g_scratch);
    float* q       = S + OFF_Q;
    float* k       = S + OFF_K;
    float* v       = S + OFF_V;
    float* a2h     = S + OFF_A2H;
    float* a8      = S + OFF_A8;
    float* afin    = S + OFF_AFIN;
    float* cat     = S + OFF_CAT;
    float* catn    = S + OFF_CATN;
    float* h1      = S + OFF_H1;
    float* h2      = S + OFF_H2;
    float* h3      = S + OFF_H3;
    float* wt      = S + OFF_WT;
    float* mean16  = S + OFF_MEAN16;
    float* rstd16  = S + OFF_RSTD16;
    float* mean9   = S + OFF_MEAN9;
    float* rstd9   = S + OFF_RSTD9;
    float* mean136 = S + OFF_MEAN136;
    float* rstd136 = S + OFF_RSTD136;
    float* psum    = S + OFF_PSUM;
    float* psq     = S + OFF_PSQ;

    // z per-channel stats (channels 0..127 of zp) — independent, start early
    zstats1_kernel<<<384, 256>>>(z, psum, psq);
    zstats2_kernel<<<128, 128>>>(psum, psq, mean136, rstd136);
    // conv_p weight transpose — independent
    wprep_kernel<<<612, 256>>>(conv_p_w, wt);

    // qkv + attention logits
    qkv_kernel<<<48, 256>>>(x, Wq, Wk, Wv, q, k, v);
    apair_kernel<<<dim3(48, 384), 256>>>(z, Wp2a, a2h);
    anode_kernel<<<dim3(12, 12, 8), dim3(32, 32)>>>(q, k, a2h);

    // conv_a path
    stats_kernel<<<16, 256>>>(a2h, 16, nullptr, mean16, rstd16);
    conva_kernel<<<dim3(24, 24), 256>>>(a2h, conv_a_w, conv_a_b, mean16, rstd16, a8);

    // conv_m path
    stats_kernel<<<9, 256>>>(a8, 8, plddt, mean9, rstd9);
    convm_kernel<<<dim3(24, 24), 256>>>(a8, plddt, conv_m_w, conv_m_b, mean9, rstd9, afin);

    // stats for afin channels (128..135 of zp)
    stats_kernel<<<8, 256>>>(afin, 8, nullptr, mean136 + 128, rstd136 + 128);

    // aggregations
    nfn_kernel<<<dim3(8, 12), dim3(32, 32)>>>(afin, v, cat);
    nfp_kernel<<<384, 256>>>(afin, z, cat);

    // MLP + final node LN
    ln_kernel<<<384, 256, 1280*sizeof(float)>>>(cat, nullptr, catn, ln1_w, ln1_b, 1280, 0);
    gemm_kernel<<<dim3(16, 12), dim3(16, 16)>>>(catn, lin1_w, lin1_b, h1, 384, 512, 1280);
    ln_kernel<<<384, 256, 512*sizeof(float)>>>(h1, nullptr, h2, ln2_w, ln2_b, 512, 1);
    gemm_kernel<<<dim3(8, 12), dim3(16, 16)>>>(h2, lin2_w, lin2_b, h3, 384, 256, 512);
    ln_kernel<<<384, 256, 256*sizeof(float)>>>(h3, x, out, lnf_w, lnf_b, 256, 0);

    // pair update
    convp_kernel<<<dim3(12, 12, 8), 256>>>(z, afin, wt, conv_p_b, mean136, rstd136,
                                           out + 384*256);
}

// round 11
// speedup vs baseline: 1.1609x; 1.0299x over previous
#include <cuda_runtime.h>
#include <cstdint>
#include <cstddef>

// Shapes: N=1, L=384, NODE=256, H=8, HD=32, PD=128, D1=1280
#define L 384
#define SPAT 147456       // 384*384
#define NODE 256
#define NH 8
#define HD 32
#define PD 128

// ---- scratch layout (floats) ----
#define OFF_Q       0          // 98304
#define OFF_K       98304
#define OFF_V       196608
#define OFF_A2H     294912     // 16*147456 = 2359296
#define OFF_A8      2654208    // 8*147456 = 1179648
#define OFF_AFIN    3833856    // 1179648
#define OFF_CAT     5013504    // 384*1280 = 491520
#define OFF_CATN    5505024    // 491520
#define OFF_H1      5996544    // 384*512
#define OFF_H2      6193152    // 384*512
#define OFF_H3      6389760    // 384*256
#define OFF_WT      6488064    // 136*9*128 = 156672
#define OFF_MEAN16  6644736
#define OFF_RSTD16  6644752
#define OFF_MEAN9   6644768
#define OFF_RSTD9   6644784
#define OFF_MEAN136 6644800    // 160 slots
#define OFF_RSTD136 6644960    // 160 slots
#define OFF_PSUM    6645120    // 128*384
#define OFF_PSQ     6694272    // 128*384
#define SCRATCH_FLOATS 6743424

__device__ float g_scratch[SCRATCH_FLOATS];

__device__ __forceinline__ float lrelu(float v){ return v >= 0.f ? v : 0.01f*v; }

// ---- packed f32x2 helpers (FFMA2 path, sm_100+) ----
typedef unsigned long long ull;
__device__ __forceinline__ ull dup2(float v){
    ull r; unsigned u = __float_as_uint(v);
    asm("mov.b64 %0, {%1, %1};" : "=l"(r) : "r"(u));
    return r;
}
__device__ __forceinline__ ull pack2(float a, float b){
    ull r;
    asm("mov.b64 %0, {%1, %2};" : "=l"(r) : "r"(__float_as_uint(a)), "r"(__float_as_uint(b)));
    return r;
}
__device__ __forceinline__ void fma2(ull &acc, ull a, ull b){
    asm("fma.rn.f32x2 %0, %1, %2, %0;" : "+l"(acc) : "l"(a), "l"(b));
}
__device__ __forceinline__ float2 unpk(ull v){
    unsigned lo, hi;
    asm("mov.b64 {%0, %1}, %2;" : "=r"(lo), "=r"(hi) : "l"(v));
    return make_float2(__uint_as_float(lo), __uint_as_float(hi));
}

// ------------------------------------------------------------------
// q/k/v = x @ W.  grid (48 row-tiles, 3 matrices), block 256.
// 8 rows per block; blockIdx.y picks which W / output -> 144 blocks.
// ------------------------------------------------------------------
__global__ void qkv_kernel(const float* __restrict__ x, const float* __restrict__ Wq,
                           const float* __restrict__ Wk, const float* __restrict__ Wv,
                           float* __restrict__ q, float* __restrict__ k, float* __restrict__ v){
    __shared__ float xs[8*256];
    int l0 = blockIdx.x*8, t = threadIdx.x;
    const float* W; float* o;
    if (blockIdx.y == 0){ W = Wq; o = q; }
    else if (blockIdx.y == 1){ W = Wk; o = k; }
    else { W = Wv; o = v; }
    #pragma unroll
    for (int r = 0; r < 8; r++) xs[r*256 + t] = x[(l0+r)*256 + t];
    __syncthreads();
    float acc[8];
    #pragma unroll
    for (int r = 0; r < 8; r++) acc[r] = 0.f;
    #pragma unroll 4
    for (int i = 0; i < 256; i++){
        float w = W[i*256 + t];
        #pragma unroll
        for (int r = 0; r < 8; r++) acc[r] += xs[r*256 + i]*w;
    }
    #pragma unroll
    for (int r = 0; r < 8; r++) o[(l0+r)*256 + t] = acc[r];
}

// ------------------------------------------------------------------
// a_pair[h][l][m] = z[l,m,:] . Wp2a[:,h]   (channels 0..7 of a2h)
// ------------------------------------------------------------------
__global__ void apair_kernel(const float* __restrict__ z, const float* __restrict__ Wp2a,
                             float* __restrict__ a2h){
    __shared__ float ws[128*9]; // padded: ws[p*9+h]
    int t = threadIdx.x;
    for (int i = t; i < 1024; i += 256){
        int p = i >> 3, h = i & 7;
        ws[p*9 + h] = Wp2a[i];
    }
    __syncthreads();
    int lane = t & 31, wp = t >> 5;
    int m = blockIdx.x*8 + wp;
    int l = blockIdx.y;
    const float4 zv = *(const float4*)(z + ((size_t)l*L + m)*128 + lane*4);
    int p = lane*4;
    float acc[8];
    #pragma unroll
    for (int h = 0; h < 8; h++){
        acc[h] = zv.x*ws[p*9 + h] + zv.y*ws[(p+1)*9 + h]
               + zv.z*ws[(p+2)*9 + h] + zv.w*ws[(p+3)*9 + h];
    }
    #pragma unroll
    for (int h = 0; h < 8; h++){
        float s = acc[h];
        for (int o = 16; o > 0; o >>= 1) s += __shfl_down_sync(0xffffffffu, s, o);
        if (lane == 0) a2h[h*SPAT + l*L + m] = s;
    }
}

// ------------------------------------------------------------------
// a_node[h][l][m] = q[l,h,:].k[m,h,:]/sqrt(32)  (channels 8..15)
// ------------------------------------------------------------------
__global__ void anode_kernel(const float* __restrict__ q, const float* __restrict__ k,
                             float* __restrict__ a2h){
    int h = blockIdx.z;
    int l0 = blockIdx.y*32, m0 = blockIdx.x*32;
    __shared__ float Qs[32][33], Ks[32][33];
    int tx = threadIdx.x, ty = threadIdx.y;
    Qs[ty][tx] = q[(l0+ty)*256 + h*32 + tx];
    Ks[ty][tx] = k[(m0+ty)*256 + h*32 + tx];
    __syncthreads();
    float acc = 0.f;
    #pragma unroll
    for (int d = 0; d < 32; d++) acc += Qs[ty][d]*Ks[tx][d];
    a2h[(8+h)*SPAT + (l0+ty)*L + m0 + tx] = acc * 0.17677669529663687f;
}

// ------------------------------------------------------------------
// Per-channel instance-norm stats for channel-first contiguous buffers
// ------------------------------------------------------------------
__global__ void stats_kernel(const float* __restrict__ srcA, int nA,
                             const float* __restrict__ srcB,
                             float* __restrict__ mean, float* __restrict__ rstd){
    int c = blockIdx.x, t = threadIdx.x;
    const float* p = (c < nA) ? srcA + (size_t)c*SPAT : srcB + (size_t)(c-nA)*SPAT;
    const float4* p4 = (const float4*)p;
    float s = 0.f, s2 = 0.f;
    for (int i = t; i < SPAT/4; i += 256){
        float4 v = p4[i];
        s  += v.x + v.y + v.z + v.w;
        s2 += v.x*v.x + v.y*v.y + v.z*v.z + v.w*v.w;
    }
    __shared__ float ss[256], ss2[256];
    ss[t] = s; ss2[t] = s2; __syncthreads();
    for (int o = 128; o > 0; o >>= 1){
        if (t < o){ ss[t] += ss[t+o]; ss2[t] += ss2[t+o]; }
        __syncthreads();
    }
    if (t == 0){
        float m = ss[0] * (1.f/SPAT);
        float var = ss2[0] * (1.f/SPAT) - m*m;
        mean[c] = m; rstd[c] = rsqrtf(var + 1e-5f);
    }
}

// z channel stats, stage 1: per-(l) partials, deterministic. grid 384, block 256.
__global__ void zstats1_kernel(const float* __restrict__ z,
                               float* __restrict__ psum, float* __restrict__ psq){
    int l = blockIdx.x, t = threadIdx.x;
    int c = t & 127, half = t >> 7;
    const float* base = z + (size_t)l*L*128;
    float s = 0.f, s2 = 0.f;
    for (int m = half; m < L; m += 2){
        float v = base[m*128 + c];
        s += v; s2 += v*v;
    }
    __shared__ float sh[256], sh2[256];
    sh[t] = s; sh2[t] = s2; __syncthreads();
    if (half == 0){
        psum[c*L + l] = sh[t] + sh[t+128];
        psq [c*L + l] = sh2[t] + sh2[t+128];
    }
}

// stage 2: reduce over l. grid 128, block 128.
__global__ void zstats2_kernel(const float* __restrict__ psum, const float* __restrict__ psq,
                               float* __restrict__ mean, float* __restrict__ rstd){
    int c = blockIdx.x, t = threadIdx.x;
    float s = 0.f, s2 = 0.f;
    for (int l = t; l < L; l += 128){ s += psum[c*L + l]; s2 += psq[c*L + l]; }
    __shared__ float ss[128], ss2[128];
    ss[t] = s; ss2[t] = s2; __syncthreads();
    for (int o = 64; o > 0; o >>= 1){
        if (t < o){ ss[t] += ss[t+o]; ss2[t] += ss2[t+o]; }
        __syncthreads();
    }
    if (t == 0){
        float m = ss[0] * (1.f/SPAT);
        float var = ss2[0] * (1.f/SPAT) - m*m;
        mean[c] = m; rstd[c] = rsqrtf(var + 1e-5f);
    }
}

// ------------------------------------------------------------------
// conv_a: 16ch (instance-normed a2h) -> 8ch, 3x3 SAME, leaky. grid (24,24), 256 thr
// ------------------------------------------------------------------
__global__ void conva_kernel(const float* __restrict__ a2h, const float* __restrict__ w,
                             const float* __restrict__ bias, const float* __restrict__ mean,
                             const float* __restrict__ rstd, float* __restrict__ a8){
    __shared__ float tin[16*324];
    __shared__ float wk[1152];
    int t = threadIdx.x;
    for (int i = t; i < 1152; i += 256) wk[i] = w[i];
    int x0 = blockIdx.x*16 - 1, y0 = blockIdx.y*16 - 1;
    for (int i = t; i < 16*324; i += 256){
        int c = i / 324, r = i % 324;
        int gy = y0 + r/18, gx = x0 + r%18;
        float v = 0.f;
        if ((unsigned)gy < 384u && (unsigned)gx < 384u)
            v = (a2h[c*SPAT + gy*L + gx] - mean[c]) * rstd[c];
        tin[i] = v;
    }
    __syncthreads();
    int lx = t & 15, ly = t >> 4;
    float acc[8];
    #pragma unroll
    for (int o = 0; o < 8; o++) acc[o] = bias[o];
    for (int c = 0; c < 16; c++){
        float iv[9];
        #pragma unroll
        for (int ky = 0; ky < 3; ky++)
            #pragma unroll
            for (int kx = 0; kx < 3; kx++)
                iv[ky*3+kx] = tin[c*324 + (ly+ky)*18 + lx + kx];
        #pragma unroll
        for (int o = 0; o < 8; o++){
            const float* wp = &wk[(o*16 + c)*9];
            acc[o] += wp[0]*iv[0]+wp[1]*iv[1]+wp[2]*iv[2]
                    + wp[3]*iv[3]+wp[4]*iv[4]+wp[5]*iv[5]
                    + wp[6]*iv[6]+wp[7]*iv[7]+wp[8]*iv[8];
        }
    }
    int gx = blockIdx.x*16 + lx, gy = blockIdx.y*16 + ly;
    #pragma unroll
    for (int o = 0; o < 8; o++)
        a8[o*SPAT + gy*L + gx] = lrelu(acc[o]);
}

// conv_m: 9ch (a8 normed + plddt normed) -> 8ch, leaky. grid (24,24), 256 thr
__global__ void convm_kernel(const float* __restrict__ a8, const float* __restrict__ plddt,
                             const float* __restrict__ w, const float* __restrict__ bias,
                             const float* __restrict__ mean, const float* __restrict__ rstd,
                             float* __restrict__ afin){
    __shared__ float tin[9*324];
    __shared__ float wk[648];
    int t = threadIdx.x;
    for (int i = t; i < 648; i += 256) wk[i] = w[i];
    int x0 = blockIdx.x*16 - 1, y0 = blockIdx.y*16 - 1;
    for (int i = t; i < 9*324; i += 256){
        int c = i / 324, r = i % 324;
        int gy = y0 + r/18, gx = x0 + r%18;
        float v = 0.f;
        if ((unsigned)gy < 384u && (unsigned)gx < 384u){
            float raw = (c < 8) ? a8[c*SPAT + gy*L + gx] : plddt[gy*L + gx];
            v = (raw - mean[c]) * rstd[c];
        }
        tin[i] = v;
    }
    __syncthreads();
    int lx = t & 15, ly = t >> 4;
    float acc[8];
    #pragma unroll
    for (int o = 0; o < 8; o++) acc[o] = bias[o];
    for (int c = 0; c < 9; c++){
        float iv[9];
        #pragma unroll
        for (int ky = 0; ky < 3; ky++)
            #pragma unroll
            for (int kx = 0; kx < 3; kx++)
                iv[ky*3+kx] = tin[c*324 + (ly+ky)*18 + lx + kx];
        #pragma unroll
        for (int o = 0; o < 8; o++){
            const float* wp = &wk[(o*9 + c)*9];
            acc[o] += wp[0]*iv[0]+wp[1]*iv[1]+wp[2]*iv[2]
                    + wp[3]*iv[3]+wp[4]*iv[4]+wp[5]*iv[5]
                    + wp[6]*iv[6]+wp[7]*iv[7]+wp[8]*iv[8];
        }
    }
    int gx = blockIdx.x*16 + lx, gy = blockIdx.y*16 + ly;
    #pragma unroll
    for (int o = 0; o < 8; o++)
        afin[o*SPAT + gy*L + gx] = lrelu(acc[o]);
}

// ------------------------------------------------------------------
// nfn: cat[l, 1024 + h*32+d] = sum_m afin[h][l][m] * v[m, h*32+d]
// ------------------------------------------------------------------
__global__ void nfn_kernel(const float* __restrict__ afin, const float* __restrict__ v,
                           float* __restrict__ cat){
    int h = blockIdx.x, l0 = blockIdx.y*32;
    int tx = threadIdx.x, ty = threadIdx.y;
    __shared__ float As[32][33], Vs[32][33];
    float acc = 0.f;
    for (int m0 = 0; m0 < L; m0 += 32){
        As[ty][tx] = afin[h*SPAT + (l0+ty)*L + m0 + tx];
        Vs[ty][tx] = v[(m0+ty)*256 + h*32 + tx];
        __syncthreads();
        #pragma unroll
        for (int kk = 0; kk < 32; kk++) acc += As[ty][kk]*Vs[kk][tx];
        __syncthreads();
    }
    cat[(size_t)(l0+ty)*1280 + 1024 + h*32 + tx] = acc;
}

// nfp: cat[l, h*128+p] = sum_m afin[h][l][m] * z[l,m,p].  grid 384, block 256
__global__ void nfp_kernel(const float* __restrict__ afin, const float* __restrict__ z,
                           float* __restrict__ cat){
    int l = blockIdx.x, t = threadIdx.x;
    __shared__ float As[8][32];
    __shared__ float Zs[32*128];
    int p = t & 127, hb = (t >> 7)*4;
    float acc0 = 0.f, acc1 = 0.f, acc2 = 0.f, acc3 = 0.f;
    for (int m0 = 0; m0 < L; m0 += 32){
        __syncthreads();
        { int hh = t >> 5, mm = t & 31; As[hh][mm] = afin[hh*SPAT + l*L + m0 + mm]; }
        const float4* zsrc = (const float4*)(z + ((size_t)l*L + m0)*128);
        float4* zd = (float4*)Zs;
        for (int i = t; i < 1024; i += 256) zd[i] = zsrc[i];
        __syncthreads();
        #pragma unroll 8
        for (int mm = 0; mm < 32; mm++){
            float zv = Zs[mm*128 + p];
            acc0 += As[hb  ][mm]*zv;
            acc1 += As[hb+1][mm]*zv;
            acc2 += As[hb+2][mm]*zv;
            acc3 += As[hb+3][mm]*zv;
        }
    }
    cat[(size_t)l*1280 + (hb  )*128 + p] = acc0;
    cat[(size_t)l*1280 + (hb+1)*128 + p] = acc1;
    cat[(size_t)l*1280 + (hb+2)*128 + p] = acc2;
    cat[(size_t)l*1280 + (hb+3)*128 + p] = acc3;
}

// ------------------------------------------------------------------
// row LayerNorm: out = [(in+add?) - m]/sqrt(v+eps)*w + b  (opt leaky)
// ------------------------------------------------------------------
__global__ void ln_kernel(const float* __restrict__ in, const float* __restrict__ add,
                          float* __restrict__ out, const float* __restrict__ w,
                          const float* __restrict__ b, int D, int do_leaky){
    extern __shared__ float sh[];
    __shared__ float red[256];
    int r = blockIdx.x, t = threadIdx.x;
    float s = 0.f;
    for (int i = t; i < D; i += 256){
        float v = in[(size_t)r*D + i];
        if (add) v += add[(size_t)r*D + i];
        sh[i] = v; s += v;
    }
    red[t] = s; __syncthreads();
    for (int o = 128; o > 0; o >>= 1){ if (t < o) red[t] += red[t+o]; __syncthreads(); }
    float mean = red[0] / D;
    __syncthreads();
    float s2 = 0.f;
    for (int i = t; i < D; i += 256){ float d = sh[i] - mean; s2 += d*d; }
    red[t] = s2; __syncthreads();
    for (int o = 128; o > 0; o >>= 1){ if (t < o) red[t] += red[t+o]; __syncthreads(); }
    float rstd = rsqrtf(red[0]/D + 1e-5f);
    for (int i = t; i < D; i += 256){
        float v = (sh[i] - mean)*rstd*w[i] + b[i];
        if (do_leaky) v = lrelu(v);
        out[(size_t)r*D + i] = v;
    }
}

// generic GEMM C = A(MxK) @ B(KxN) + bias.  block (16,16), tiles 32x32x32
__global__ void gemm_kernel(const float* __restrict__ A, const float* __restrict__ B,
                            const float* __restrict__ bias, float* __restrict__ C,
                            int M, int N, int K){
    __shared__ float As[32][33], Bs[32][33];
    int tx = threadIdx.x, ty = threadIdx.y;
    int t = ty*16 + tx;
    int r0 = blockIdx.y*32, c0 = blockIdx.x*32;
    float a00 = 0.f, a01 = 0.f, a10 = 0.f, a11 = 0.f;
    for (int k0 = 0; k0 < K; k0 += 32){
        for (int i = t; i < 1024; i += 256){
            int rr = i >> 5, cc = i & 31;
            As[rr][cc] = A[(size_t)(r0+rr)*K + k0 + cc];
            Bs[rr][cc] = B[(size_t)(k0+rr)*N + c0 + cc];
        }
        __syncthreads();
        #pragma unroll
        for (int kk = 0; kk < 32; kk++){
            float av0 = As[ty*2][kk], av1 = As[ty*2+1][kk];
            float bv0 = Bs[kk][tx*2], bv1 = Bs[kk][tx*2+1];
            a00 += av0*bv0; a01 += av0*bv1; a10 += av1*bv0; a11 += av1*bv1;
        }
        __syncthreads();
    }
    int r = r0 + ty*2, c = c0 + tx*2;
    C[(size_t)r*N + c]       = a00 + bias[c];
    C[(size_t)r*N + c+1]     = a01 + bias[c+1];
    C[(size_t)(r+1)*N + c]   = a10 + bias[c];
    C[(size_t)(r+1)*N + c+1] = a11 + bias[c+1];
}

// transpose conv_p weights (128,136,3,3) -> wt[(ci*9+k)*128 + po]
__global__ void wprep_kernel(const float* __restrict__ w, float* __restrict__ wt){
    int i = blockIdx.x*256 + threadIdx.x;  // 156672 total
    if (i < 156672){
        int po = i / 1224, rem = i % 1224;
        int ci = rem / 9, kk = rem % 9;
        wt[(ci*9 + kk)*128 + po] = w[i];
    }
}

// ------------------------------------------------------------------
// conv_p: 136ch (z + afin, instance-normed on the fly) -> 128ch, leaky,
// packed f32x2 FFMA2 math. grid (12,12,8 ocg), block 256, 2 CTAs/SM.
// Thread: 4 px x 16 oc (= 4x8 f32x2 accumulators).
// Register-lean inner loop: only one ky-row of packed inputs live.
// ------------------------------------------------------------------
__global__ void __launch_bounds__(256, 2)
convp_kernel(const float* __restrict__ z, const float* __restrict__ afin,
             const float* __restrict__ wt, const float* __restrict__ bias,
             const float* __restrict__ mean136, const float* __restrict__ rstd136,
             float* __restrict__ out){
    __shared__ float tin[4*1224];   // 4 channels x 34 rows x stride 36
    __shared__ float wsm[576];      // 4ci x 9k x 16po
    int t = threadIdx.x;
    int x0b = blockIdx.x*32, y0 = blockIdx.y*32, ocg = blockIdx.z;
    int X0 = (t & 7)*4, y = t >> 3;

    const float* bp = bias + ocg*16;
    ull acc[4][8];
    #pragma unroll
    for (int j = 0; j < 8; j++){
        ull bj = pack2(bp[2*j], bp[2*j+1]);
        #pragma unroll
        for (int px = 0; px < 4; px++) acc[px][j] = bj;
    }

    for (int ci0 = 0; ci0 < 136; ci0 += 4){
        __syncthreads();
        // weights for this (ci chunk, ocg)
        for (int i = t; i < 576; i += 256){
            int c = i / 144, rr = i % 144, kk = rr >> 4, po = rr & 15;
            wsm[i] = wt[((ci0 + c)*9 + kk)*128 + ocg*16 + po];
        }
        float mm0 = mean136[ci0],   rr0 = rstd136[ci0];
        float mm1 = mean136[ci0+1], rr1 = rstd136[ci0+1];
        float mm2 = mean136[ci0+2], rr2 = rstd136[ci0+2];
        float mm3 = mean136[ci0+3], rr3 = rstd136[ci0+3];
        if (ci0 < 128){
            for (int i = t; i < 1156; i += 256){
                int hy = i / 34, hx = i - hy*34;
                int gy = y0 - 1 + hy, gx = x0b - 1 + hx;
                bool inb = ((unsigned)gy < 384u) && ((unsigned)gx < 384u);
                float4 v = make_float4(0.f,0.f,0.f,0.f);
                if (inb) v = *(const float4*)(z + (size_t)(gy*L + gx)*128 + ci0);
                int si = hy*36 + hx;
                tin[si]        = inb ? (v.x - mm0)*rr0 : 0.f;
                tin[1224 + si] = inb ? (v.y - mm1)*rr1 : 0.f;
                tin[2448 + si] = inb ? (v.z - mm2)*rr2 : 0.f;
                tin[3672 + si] = inb ? (v.w - mm3)*rr3 : 0.f;
            }
        } else {
            for (int i = t; i < 1156; i += 256){
                int hy = i / 34, hx = i - hy*34;
                int gy = y0 - 1 + hy, gx = x0b - 1 + hx;
                bool inb = ((unsigned)gy < 384u) && ((unsigned)gx < 384u);
                int sp = gy*L + gx;
                int si = hy*36 + hx;
                tin[si]        = inb ? (afin[(ci0-128)*SPAT + sp] - mm0)*rr0 : 0.f;
                tin[1224 + si] = inb ? (afin[(ci0-127)*SPAT + sp] - mm1)*rr1 : 0.f;
                tin[2448 + si] = inb ? (afin[(ci0-126)*SPAT + sp] - mm2)*rr2 : 0.f;
                tin[3672 + si] = inb ? (afin[(ci0-125)*SPAT + sp] - mm3)*rr3 : 0.f;
            }
        }
        __syncthreads();

        #pragma unroll
        for (int c = 0; c < 4; c++){
            #pragma unroll
            for (int ky = 0; ky < 3; ky++){
                // one 6-wide packed input row live at a time (register-lean)
                const float* row = &tin[c*1224 + (y+ky)*36 + X0];
                float4 v4 = *(const float4*)row;
                float2 v2 = *(const float2*)(row + 4);
                ull ivp[6];
                ivp[0] = dup2(v4.x); ivp[1] = dup2(v4.y);
                ivp[2] = dup2(v4.z); ivp[3] = dup2(v4.w);
                ivp[4] = dup2(v2.x); ivp[5] = dup2(v2.y);
                #pragma unroll
                for (int kx = 0; kx < 3; kx++){
                    const ulonglong2* wp = (const ulonglong2*)&wsm[(c*9 + ky*3 + kx)*16];
                    ulonglong2 wA = wp[0], wB = wp[1], wC = wp[2], wD = wp[3];
                    #pragma unroll
                    for (int px = 0; px < 4; px++){
                        ull inv = ivp[kx + px];
                        fma2(acc[px][0], wA.x, inv); fma2(acc[px][1], wA.y, inv);
                        fma2(acc[px][2], wB.x, inv); fma2(acc[px][3], wB.y, inv);
                        fma2(acc[px][4], wC.x, inv); fma2(acc[px][5], wC.y, inv);
                        fma2(acc[px][6], wD.x, inv); fma2(acc[px][7], wD.y, inv);
                    }
                }
            }
        }
    }
    int gy = y0 + y;
    #pragma unroll
    for (int px = 0; px < 4; px++){
        int gx = x0b + X0 + px;
        float* o = out + (size_t)(gy*L + gx)*128 + ocg*16;
        float vals[16];
        #pragma unroll
        for (int j = 0; j < 8; j++){
            float2 p = unpk(acc[px][j]);
            vals[2*j]   = lrelu(p.x);
            vals[2*j+1] = lrelu(p.y);
        }
        #pragma unroll
        for (int j = 0; j < 4; j++)
            *(float4*)(o + 4*j) = make_float4(vals[4*j], vals[4*j+1], vals[4*j+2], vals[4*j+3]);
    }
}

// ------------------------------------------------------------------
extern "C" void kernel_launch(void* const* d_in, const int* in_sizes, int n_in,
                              void* d_out, int out_size){
    (void)in_sizes; (void)n_in; (void)out_size;
    const float* x        = (const float*)d_in[0];
    const float* z        = (const float*)d_in[1];
    const float* plddt    = (const float*)d_in[2];
    const float* Wq       = (const float*)d_in[3];
    const float* Wk       = (const float*)d_in[4];
    const float* Wv       = (const float*)d_in[5];
    const float* Wp2a     = (const float*)d_in[6];
    const float* conv_a_w = (const float*)d_in[7];
    const float* conv_a_b = (const float*)d_in[8];
    const float* conv_m_w = (const float*)d_in[9];
    const float* conv_m_b = (const float*)d_in[10];
    const float* ln1_w    = (const float*)d_in[11];
    const float* ln1_b    = (const float*)d_in[12];
    const float* lin1_w   = (const float*)d_in[13];
    const float* lin1_b   = (const float*)d_in[14];
    const float* ln2_w    = (const float*)d_in[15];
    const float* ln2_b    = (const float*)d_in[16];
    const float* lin2_w   = (const float*)d_in[17];
    const float* lin2_b   = (const float*)d_in[18];
    const float* lnf_w    = (const float*)d_in[19];
    const float* lnf_b    = (const float*)d_in[20];
    const float* conv_p_w = (const float*)d_in[21];
    const float* conv_p_b = (const float*)d_in[22];
    float* out = (float*)d_out;

    float* S = nullptr;
    cudaGetSymbolAddress((void**)&S, g_scratch);
    float* q       = S + OFF_Q;
    float* k       = S + OFF_K;
    float* v       = S + OFF_V;
    float* a2h     = S + OFF_A2H;
    float* a8      = S + OFF_A8;
    float* afin    = S + OFF_AFIN;
    float* cat     = S + OFF_CAT;
    float* catn    = S + OFF_CATN;
    float* h1      = S + OFF_H1;
    float* h2      = S + OFF_H2;
    float* h3      = S + OFF_H3;
    float* wt      = S + OFF_WT;
    float* mean16  = S + OFF_MEAN16;
    float* rstd16  = S + OFF_RSTD16;
    float* mean9   = S + OFF_MEAN9;
    float* rstd9   = S + OFF_RSTD9;
    float* mean136 = S + OFF_MEAN136;
    float* rstd136 = S + OFF_RSTD136;
    float* psum    = S + OFF_PSUM;
    float* psq     = S + OFF_PSQ;

    // z per-channel stats (channels 0..127 of zp) — independent, start early
    zstats1_kernel<<<384, 256>>>(z, psum, psq);
    zstats2_kernel<<<128, 128>>>(psum, psq, mean136, rstd136);
    // conv_p weight transpose — independent
    wprep_kernel<<<612, 256>>>(conv_p_w, wt);

    // qkv + attention logits
    qkv_kernel<<<dim3(48, 3), 256>>>(x, Wq, Wk, Wv, q, k, v);
    apair_kernel<<<dim3(48, 384), 256>>>(z, Wp2a, a2h);
    anode_kernel<<<dim3(12, 12, 8), dim3(32, 32)>>>(q, k, a2h);

    // conv_a path
    stats_kernel<<<16, 256>>>(a2h, 16, nullptr, mean16, rstd16);
    conva_kernel<<<dim3(24, 24), 256>>>(a2h, conv_a_w, conv_a_b, mean16, rstd16, a8);

    // conv_m path
    stats_kernel<<<9, 256>>>(a8, 8, plddt, mean9, rstd9);
    convm_kernel<<<dim3(24, 24), 256>>>(a8, plddt, conv_m_w, conv_m_b, mean9, rstd9, afin);

    // stats for afin channels (128..135 of zp)
    stats_kernel<<<8, 256>>>(afin, 8, nullptr, mean136 + 128, rstd136 + 128);

    // aggregations
    nfn_kernel<<<dim3(8, 12), dim3(32, 32)>>>(afin, v, cat);
    nfp_kernel<<<384, 256>>>(afin, z, cat);

    // MLP + final node LN
    ln_kernel<<<384, 256, 1280*sizeof(float)>>>(cat, nullptr, catn, ln1_w, ln1_b, 1280, 0);
    gemm_kernel<<<dim3(16, 12), dim3(16, 16)>>>(catn, lin1_w, lin1_b, h1, 384, 512, 1280);
    ln_kernel<<<384, 256, 512*sizeof(float)>>>(h1, nullptr, h2, ln2_w, ln2_b, 512, 1);
    gemm_kernel<<<dim3(8, 12), dim3(16, 16)>>>(h2, lin2_w, lin2_b, h3, 384, 256, 512);
    ln_kernel<<<384, 256, 256*sizeof(float)>>>(h3, x, out, lnf_w, lnf_b, 256, 0);

    // pair update
    convp_kernel<<<dim3(12, 12, 8), 256>>>(z, afin, wt, conv_p_b, mean136, rstd136,
                                           out + 384*256);
}

// round 13
// speedup vs baseline: 1.8307x; 1.5769x over previous
#include <cuda_runtime.h>
#include <cuda_bf16.h>
#include <cstdint>
#include <cstddef>

// Shapes: N=1, L=384, NODE=256, H=8, HD=32, PD=128, D1=1280
#define L 384
#define SPAT 147456       // 384*384
#define NODE 256
#define NH 8
#define HD 32
#define PD 128

// ---- scratch layout (floats) ----
#define OFF_Q       0          // 98304
#define OFF_K       98304
#define OFF_V       196608
#define OFF_A2H     294912     // 16*147456 = 2359296
#define OFF_A8      2654208    // 8*147456 = 1179648
#define OFF_AFIN    3833856    // 1179648
#define OFF_CAT     5013504    // 384*1280 = 491520
#define OFF_CATN    5505024    // 491520
#define OFF_H1      5996544    // 384*512
#define OFF_H2      6193152    // 384*512
#define OFF_H3      6389760    // 384*256
#define OFF_MEAN16  6644736
#define OFF_RSTD16  6644752
#define OFF_MEAN9   6644768
#define OFF_RSTD9   6644784
#define OFF_MEAN136 6644800    // 160 slots
#define OFF_RSTD136 6644960    // 160 slots
#define OFF_PSUM    6645120    // 128*384
#define OFF_PSQ     6694272    // 128*384
#define OFF_WMMA_HI 6743424    // 9*9*8*128 = 82944 uint32
#define OFF_WMMA_LO 6826368    // 82944 uint32
#define SCRATCH_FLOATS 6909312

__device__ float g_scratch[SCRATCH_FLOATS];

__device__ __forceinline__ float lrelu(float v){ return v >= 0.f ? v : 0.01f*v; }

// ---- bf16 split/pack helpers ----
// split pair (a,b) into hi word + lo word (bf16 residuals)
__device__ __forceinline__ void nsplit2(float a, float b, unsigned &hw, unsigned &lw){
    __nv_bfloat16 ha = __float2bfloat16_rn(a);
    __nv_bfloat16 hb = __float2bfloat16_rn(b);
    float la = a - __bfloat162float(ha);
    float lb = b - __bfloat162float(hb);
    __nv_bfloat162 hp; hp.x = ha; hp.y = hb;
    __nv_bfloat162 lp; lp.x = __float2bfloat16_rn(la); lp.y = __float2bfloat16_rn(lb);
    hw = *reinterpret_cast<unsigned*>(&hp);
    lw = *reinterpret_cast<unsigned*>(&lp);
}

__device__ __forceinline__ void mma_bf16(float* c, unsigned a0, unsigned a1,
                                         unsigned a2, unsigned a3,
                                         unsigned b0, unsigned b1){
    asm volatile(
      "mma.sync.aligned.m16n8k16.row.col.f32.bf16.bf16.f32 "
      "{%0,%1,%2,%3}, {%4,%5,%6,%7}, {%8,%9}, {%0,%1,%2,%3};"
      : "+f"(c[0]), "+f"(c[1]), "+f"(c[2]), "+f"(c[3])
      : "r"(a0), "r"(a1), "r"(a2), "r"(a3), "r"(b0), "r"(b1));
}
__device__ __forceinline__ void ldmx4(unsigned addr, unsigned &r0, unsigned &r1,
                                      unsigned &r2, unsigned &r3){
    asm volatile("ldmatrix.sync.aligned.m8n8.x4.shared.b16 {%0,%1,%2,%3}, [%4];"
      : "=r"(r0), "=r"(r1), "=r"(r2), "=r"(r3) : "r"(addr));
}

// ------------------------------------------------------------------
// q/k/v = x @ W.  grid (96 row-tiles, 3 matrices), block 256, 4 rows/block.
// ------------------------------------------------------------------
__global__ void qkv_kernel(const float* __restrict__ x, const float* __restrict__ Wq,
                           const float* __restrict__ Wk, const float* __restrict__ Wv,
                           float* __restrict__ q, float* __restrict__ k, float* __restrict__ v){
    __shared__ float xs[4*256];
    int l0 = blockIdx.x*4, t = threadIdx.x;
    const float* W; float* o;
    if (blockIdx.y == 0){ W = Wq; o = q; }
    else if (blockIdx.y == 1){ W = Wk; o = k; }
    else { W = Wv; o = v; }
    for (int i = t; i < 4*256; i += 256) xs[i] = x[l0*256 + i];
    __syncthreads();
    float acc[4] = {0.f, 0.f, 0.f, 0.f};
    #pragma unroll 4
    for (int i = 0; i < 256; i++){
        float w = W[i*256 + t];
        #pragma unroll
        for (int r = 0; r < 4; r++) acc[r] += xs[r*256 + i]*w;
    }
    #pragma unroll
    for (int r = 0; r < 4; r++) o[(l0+r)*256 + t] = acc[r];
}

// ------------------------------------------------------------------
// a_pair[h][l][m] = z[l,m,:] . Wp2a[:,h]   (channels 0..7 of a2h)
// ------------------------------------------------------------------
__global__ void apair_kernel(const float* __restrict__ z, const float* __restrict__ Wp2a,
                             float* __restrict__ a2h){
    __shared__ float ws[128*9];
    int t = threadIdx.x;
    for (int i = t; i < 1024; i += 256){
        int p = i >> 3, h = i & 7;
        ws[p*9 + h] = Wp2a[i];
    }
    __syncthreads();
    int lane = t & 31, wp = t >> 5;
    int m = blockIdx.x*8 + wp;
    int l = blockIdx.y;
    const float4 zv = *(const float4*)(z + ((size_t)l*L + m)*128 + lane*4);
    int p = lane*4;
    float acc[8];
    #pragma unroll
    for (int h = 0; h < 8; h++){
        acc[h] = zv.x*ws[p*9 + h] + zv.y*ws[(p+1)*9 + h]
               + zv.z*ws[(p+2)*9 + h] + zv.w*ws[(p+3)*9 + h];
    }
    #pragma unroll
    for (int h = 0; h < 8; h++){
        float s = acc[h];
        for (int o = 16; o > 0; o >>= 1) s += __shfl_down_sync(0xffffffffu, s, o);
        if (lane == 0) a2h[h*SPAT + l*L + m] = s;
    }
}

// ------------------------------------------------------------------
// a_node[h][l][m] = q[l,h,:].k[m,h,:]/sqrt(32)  (channels 8..15)
// ------------------------------------------------------------------
__global__ void anode_kernel(const float* __restrict__ q, const float* __restrict__ k,
                             float* __restrict__ a2h){
    int h = blockIdx.z;
    int l0 = blockIdx.y*32, m0 = blockIdx.x*32;
    __shared__ float Qs[32][33], Ks[32][33];
    int tx = threadIdx.x, ty = threadIdx.y;
    Qs[ty][tx] = q[(l0+ty)*256 + h*32 + tx];
    Ks[ty][tx] = k[(m0+ty)*256 + h*32 + tx];
    __syncthreads();
    float acc = 0.f;
    #pragma unroll
    for (int d = 0; d < 32; d++) acc += Qs[ty][d]*Ks[tx][d];
    a2h[(8+h)*SPAT + (l0+ty)*L + m0 + tx] = acc * 0.17677669529663687f;
}

// ------------------------------------------------------------------
// Per-channel instance-norm stats for channel-first contiguous buffers
// ------------------------------------------------------------------
__global__ void stats_kernel(const float* __restrict__ srcA, int nA,
                             const float* __restrict__ srcB,
                             float* __restrict__ mean, float* __restrict__ rstd){
    int c = blockIdx.x, t = threadIdx.x;
    const float* p = (c < nA) ? srcA + (size_t)c*SPAT : srcB + (size_t)(c-nA)*SPAT;
    const float4* p4 = (const float4*)p;
    float s = 0.f, s2 = 0.f;
    for (int i = t; i < SPAT/4; i += 256){
        float4 v = p4[i];
        s  += v.x + v.y + v.z + v.w;
        s2 += v.x*v.x + v.y*v.y + v.z*v.z + v.w*v.w;
    }
    __shared__ float ss[256], ss2[256];
    ss[t] = s; ss2[t] = s2; __syncthreads();
    for (int o = 128; o > 0; o >>= 1){
        if (t < o){ ss[t] += ss[t+o]; ss2[t] += ss2[t+o]; }
        __syncthreads();
    }
    if (t == 0){
        float m = ss[0] * (1.f/SPAT);
        float var = ss2[0] * (1.f/SPAT) - m*m;
        mean[c] = m; rstd[c] = rsqrtf(var + 1e-5f);
    }
}

// z channel stats, stage 1: per-(l) partials, deterministic. grid 384, block 256.
__global__ void zstats1_kernel(const float* __restrict__ z,
                               float* __restrict__ psum, float* __restrict__ psq){
    int l = blockIdx.x, t = threadIdx.x;
    int c = t & 127, half = t >> 7;
    const float* base = z + (size_t)l*L*128;
    float s = 0.f, s2 = 0.f;
    for (int m = half; m < L; m += 2){
        float v = base[m*128 + c];
        s += v; s2 += v*v;
    }
    __shared__ float sh[256], sh2[256];
    sh[t] = s; sh2[t] = s2; __syncthreads();
    if (half == 0){
        psum[c*L + l] = sh[t] + sh[t+128];
        psq [c*L + l] = sh2[t] + sh2[t+128];
    }
}

// stage 2: reduce over l. grid 128, block 128.
__global__ void zstats2_kernel(const float* __restrict__ psum, const float* __restrict__ psq,
                               float* __restrict__ mean, float* __restrict__ rstd){
    int c = blockIdx.x, t = threadIdx.x;
    float s = 0.f, s2 = 0.f;
    for (int l = t; l < L; l += 128){ s += psum[c*L + l]; s2 += psq[c*L + l]; }
    __shared__ float ss[128], ss2[128];
    ss[t] = s; ss2[t] = s2; __syncthreads();
    for (int o = 64; o > 0; o >>= 1){
        if (t < o){ ss[t] += ss[t+o]; ss2[t] += ss2[t+o]; }
        __syncthreads();
    }
    if (t == 0){
        float m = ss[0] * (1.f/SPAT);
        float var = ss2[0] * (1.f/SPAT) - m*m;
        mean[c] = m; rstd[c] = rsqrtf(var + 1e-5f);
    }
}

// ------------------------------------------------------------------
// conv_a: 16ch (instance-normed a2h) -> 8ch, 3x3 SAME, leaky. grid (24,24), 256 thr
// ------------------------------------------------------------------
__global__ void conva_kernel(const float* __restrict__ a2h, const float* __restrict__ w,
                             const float* __restrict__ bias, const float* __restrict__ mean,
                             const float* __restrict__ rstd, float* __restrict__ a8){
    __shared__ float tin[16*324];
    __shared__ float wk[1152];
    int t = threadIdx.x;
    for (int i = t; i < 1152; i += 256) wk[i] = w[i];
    int x0 = blockIdx.x*16 - 1, y0 = blockIdx.y*16 - 1;
    for (int i = t; i < 16*324; i += 256){
        int c = i / 324, r = i % 324;
        int gy = y0 + r/18, gx = x0 + r%18;
        float v = 0.f;
        if ((unsigned)gy < 384u && (unsigned)gx < 384u)
            v = (a2h[c*SPAT + gy*L + gx] - mean[c]) * rstd[c];
        tin[i] = v;
    }
    __syncthreads();
    int lx = t & 15, ly = t >> 4;
    float acc[8];
    #pragma unroll
    for (int o = 0; o < 8; o++) acc[o] = bias[o];
    for (int c = 0; c < 16; c++){
        float iv[9];
        #pragma unroll
        for (int ky = 0; ky < 3; ky++)
            #pragma unroll
            for (int kx = 0; kx < 3; kx++)
                iv[ky*3+kx] = tin[c*324 + (ly+ky)*18 + lx + kx];
        #pragma unroll
        for (int o = 0; o < 8; o++){
            const float* wp = &wk[(o*16 + c)*9];
            acc[o] += wp[0]*iv[0]+wp[1]*iv[1]+wp[2]*iv[2]
                    + wp[3]*iv[3]+wp[4]*iv[4]+wp[5]*iv[5]
                    + wp[6]*iv[6]+wp[7]*iv[7]+wp[8]*iv[8];
        }
    }
    int gx = blockIdx.x*16 + lx, gy = blockIdx.y*16 + ly;
    #pragma unroll
    for (int o = 0; o < 8; o++)
        a8[o*SPAT + gy*L + gx] = lrelu(acc[o]);
}

// conv_m: 9ch (a8 normed + plddt normed) -> 8ch, leaky. grid (24,24), 256 thr
__global__ void convm_kernel(const float* __restrict__ a8, const float* __restrict__ plddt,
                             const float* __restrict__ w, const float* __restrict__ bias,
                             const float* __restrict__ mean, const float* __restrict__ rstd,
                             float* __restrict__ afin){
    __shared__ float tin[9*324];
    __shared__ float wk[648];
    int t = threadIdx.x;
    for (int i = t; i < 648; i += 256) wk[i] = w[i];
    int x0 = blockIdx.x*16 - 1, y0 = blockIdx.y*16 - 1;
    for (int i = t; i < 9*324; i += 256){
        int c = i / 324, r = i % 324;
        int gy = y0 + r/18, gx = x0 + r%18;
        float v = 0.f;
        if ((unsigned)gy < 384u && (unsigned)gx < 384u){
            float raw = (c < 8) ? a8[c*SPAT + gy*L + gx] : plddt[gy*L + gx];
            v = (raw - mean[c]) * rstd[c];
        }
        tin[i] = v;
    }
    __syncthreads();
    int lx = t & 15, ly = t >> 4;
    float acc[8];
    #pragma unroll
    for (int o = 0; o < 8; o++) acc[o] = bias[o];
    for (int c = 0; c < 9; c++){
        float iv[9];
        #pragma unroll
        for (int ky = 0; ky < 3; ky++)
            #pragma unroll
            for (int kx = 0; kx < 3; kx++)
                iv[ky*3+kx] = tin[c*324 + (ly+ky)*18 + lx + kx];
        #pragma unroll
        for (int o = 0; o < 8; o++){
            const float* wp = &wk[(o*9 + c)*9];
            acc[o] += wp[0]*iv[0]+wp[1]*iv[1]+wp[2]*iv[2]
                    + wp[3]*iv[3]+wp[4]*iv[4]+wp[5]*iv[5]
                    + wp[6]*iv[6]+wp[7]*iv[7]+wp[8]*iv[8];
        }
    }
    int gx = blockIdx.x*16 + lx, gy = blockIdx.y*16 + ly;
    #pragma unroll
    for (int o = 0; o < 8; o++)
        afin[o*SPAT + gy*L + gx] = lrelu(acc[o]);
}

// ------------------------------------------------------------------
// nfn: cat[l, 1024 + h*32+d] = sum_m afin[h][l][m] * v[m, h*32+d]
// ------------------------------------------------------------------
__global__ void nfn_kernel(const float* __restrict__ afin, const float* __restrict__ v,
                           float* __restrict__ cat){
    int h = blockIdx.x, l0 = blockIdx.y*32;
    int tx = threadIdx.x, ty = threadIdx.y;
    __shared__ float As[32][33], Vs[32][33];
    float acc = 0.f;
    for (int m0 = 0; m0 < L; m0 += 32){
        As[ty][tx] = afin[h*SPAT + (l0+ty)*L + m0 + tx];
        Vs[ty][tx] = v[(m0+ty)*256 + h*32 + tx];
        __syncthreads();
        #pragma unroll
        for (int kk = 0; kk < 32; kk++) acc += As[ty][kk]*Vs[kk][tx];
        __syncthreads();
    }
    cat[(size_t)(l0+ty)*1280 + 1024 + h*32 + tx] = acc;
}

// nfp: cat[l, h*128+p] = sum_m afin[h][l][m] * z[l,m,p].  grid 384, block 256
__global__ void nfp_kernel(const float* __restrict__ afin, const float* __restrict__ z,
                           float* __restrict__ cat){
    int l = blockIdx.x, t = threadIdx.x;
    __shared__ float As[8][32];
    __shared__ float Zs[32*128];
    int p = t & 127, hb = (t >> 7)*4;
    float acc0 = 0.f, acc1 = 0.f, acc2 = 0.f, acc3 = 0.f;
    for (int m0 = 0; m0 < L; m0 += 32){
        __syncthreads();
        { int hh = t >> 5, mm = t & 31; As[hh][mm] = afin[hh*SPAT + l*L + m0 + mm]; }
        const float4* zsrc = (const float4*)(z + ((size_t)l*L + m0)*128);
        float4* zd = (float4*)Zs;
        for (int i = t; i < 1024; i += 256) zd[i] = zsrc[i];
        __syncthreads();
        #pragma unroll 8
        for (int mm = 0; mm < 32; mm++){
            float zv = Zs[mm*128 + p];
            acc0 += As[hb  ][mm]*zv;
            acc1 += As[hb+1][mm]*zv;
            acc2 += As[hb+2][mm]*zv;
            acc3 += As[hb+3][mm]*zv;
        }
    }
    cat[(size_t)l*1280 + (hb  )*128 + p] = acc0;
    cat[(size_t)l*1280 + (hb+1)*128 + p] = acc1;
    cat[(size_t)l*1280 + (hb+2)*128 + p] = acc2;
    cat[(size_t)l*1280 + (hb+3)*128 + p] = acc3;
}

// ------------------------------------------------------------------
// row LayerNorm: out = [(in+add?) - m]/sqrt(v+eps)*w + b  (opt leaky)
// ------------------------------------------------------------------
__global__ void ln_kernel(const float* __restrict__ in, const float* __restrict__ add,
                          float* __restrict__ out, const float* __restrict__ w,
                          const float* __restrict__ b, int D, int do_leaky){
    extern __shared__ float sh[];
    __shared__ float red[256];
    int r = blockIdx.x, t = threadIdx.x;
    float s = 0.f;
    for (int i = t; i < D; i += 256){
        float v = in[(size_t)r*D + i];
        if (add) v += add[(size_t)r*D + i];
        sh[i] = v; s += v;
    }
    red[t] = s; __syncthreads();
    for (int o = 128; o > 0; o >>= 1){ if (t < o) red[t] += red[t+o]; __syncthreads(); }
    float mean = red[0] / D;
    __syncthreads();
    float s2 = 0.f;
    for (int i = t; i < D; i += 256){ float d = sh[i] - mean; s2 += d*d; }
    red[t] = s2; __syncthreads();
    for (int o = 128; o > 0; o >>= 1){ if (t < o) red[t] += red[t+o]; __syncthreads(); }
    float rstd = rsqrtf(red[0]/D + 1e-5f);
    for (int i = t; i < D; i += 256){
        float v = (sh[i] - mean)*rstd*w[i] + b[i];
        if (do_leaky) v = lrelu(v);
        out[(size_t)r*D + i] = v;
    }
}

// generic GEMM C = A(MxK) @ B(KxN) + bias.  block (16,16), tiles 32x32x32
__global__ void gemm_kernel(const float* __restrict__ A, const float* __restrict__ B,
                            const float* __restrict__ bias, float* __restrict__ C,
                            int M, int N, int K){
    __shared__ float As[32][33], Bs[32][33];
    int tx = threadIdx.x, ty = threadIdx.y;
    int t = ty*16 + tx;
    int r0 = blockIdx.y*32, c0 = blockIdx.x*32;
    float a00 = 0.f, a01 = 0.f, a10 = 0.f, a11 = 0.f;
    for (int k0 = 0; k0 < K; k0 += 32){
        for (int i = t; i < 1024; i += 256){
            int rr = i >> 5, cc = i & 31;
            As[rr][cc] = A[(size_t)(r0+rr)*K + k0 + cc];
            Bs[rr][cc] = B[(size_t)(k0+rr)*N + c0 + cc];
        }
        __syncthreads();
        #pragma unroll
        for (int kk = 0; kk < 32; kk++){
            float av0 = As[ty*2][kk], av1 = As[ty*2+1][kk];
            float bv0 = Bs[kk][tx*2], bv1 = Bs[kk][tx*2+1];
            a00 += av0*bv0; a01 += av0*bv1; a10 += av1*bv0; a11 += av1*bv1;
        }
        __syncthreads();
    }
    int r = r0 + ty*2, c = c0 + tx*2;
    C[(size_t)r*N + c]       = a00 + bias[c];
    C[(size_t)r*N + c+1]     = a01 + bias[c+1];
    C[(size_t)(r+1)*N + c]   = a10 + bias[c];
    C[(size_t)(r+1)*N + c+1] = a11 + bias[c+1];
}

// ------------------------------------------------------------------
// conv_p weight prep for mma: split fp32 -> bf16 hi/lo, pack k-pairs.
// Layout: [chunk 9][tap 9][k2 8][oc 128], word = pack(bf16(ci=2k2), bf16(ci=2k2+1))
// where ci = chunk*16 + 2*k2 (zero beyond 136).
// ------------------------------------------------------------------
__global__ void wprep_mma_kernel(const float* __restrict__ w,
                                 unsigned* __restrict__ whi, unsigned* __restrict__ wlo){
    int i = blockIdx.x*256 + threadIdx.x;   // 82944 total
    if (i >= 9*9*8*128) return;
    int oc = i & 127; int r = i >> 7;
    int k2 = r & 7; r >>= 3;
    int tap = r % 9; int chunk = r / 9;
    int ci = chunk*16 + 2*k2;
    float w0 = (ci     < 136) ? w[(oc*136 + ci    )*9 + tap] : 0.f;
    float w1 = (ci + 1 < 136) ? w[(oc*136 + ci + 1)*9 + tap] : 0.f;
    unsigned hw, lw;
    nsplit2(w0, w1, hw, lw);
    whi[i] = hw; wlo[i] = lw;
}

// ------------------------------------------------------------------
// conv_p via bf16 tensor cores with split-bf16 compensation (3 mma terms).
// grid (12 x-tiles, 24 y-tiles, 2 ocg), block 256 (8 warps).
// Block tile: 16 rows x 32 cols px, 64 oc. Warp: 2 px rows (64 px) x 64 oc.
// K: 9 chunks of 16 ci; per (chunk, tap) one K=16 mma slice; A straight from
// normalized halo slab (18x34 px, 48B px stride, conflict-free ldmatrix).
// ------------------------------------------------------------------
#define AHI_OFF 0
#define ALO_OFF 29376
#define WHI_OFF 58752
#define WLO_OFF 79488
#define CONVP_SMEM 100224

__global__ void __launch_bounds__(256)
convp_mma_kernel(const float* __restrict__ z, const float* __restrict__ afin,
                 const unsigned* __restrict__ whi, const unsigned* __restrict__ wlo,
                 const float* __restrict__ bias,
                 const float* __restrict__ mean136, const float* __restrict__ rstd136,
                 float* __restrict__ out){
    extern __shared__ char sm[];
    char* A_HI = sm + AHI_OFF;            // 612 px * 48B (16 ci bf16 + 16B pad)
    unsigned* W_HI = (unsigned*)(sm + WHI_OFF);  // [tap9][k2 8][stride 72]
    unsigned* W_LO = (unsigned*)(sm + WLO_OFF);

    int t = threadIdx.x;
    int x0 = blockIdx.x*32, y0 = blockIdx.y*16, ocg = blockIdx.z;
    int lane = t & 31, wrp = t >> 5;
    int t4 = lane & 3, g = lane >> 2;
    int q = lane >> 3, r8 = lane & 7;
    int p = (q & 1)*8 + r8;        // mma row (pixel within m-tile)
    int khalf = q >> 1;            // k halves for ldmatrix
    unsigned aHiU = (unsigned)__cvta_generic_to_shared(A_HI);
    unsigned baseoffA = (unsigned)(((2*wrp)*34 + p)*48 + khalf*16);

    float acc[4][8][4];
    #pragma unroll
    for (int nt = 0; nt < 8; nt++){
        float2 bv = *(const float2*)(bias + ocg*64 + nt*8 + 2*t4);
        #pragma unroll
        for (int m = 0; m < 4; m++){
            acc[m][nt][0] = bv.x; acc[m][nt][1] = bv.y;
            acc[m][nt][2] = bv.x; acc[m][nt][3] = bv.y;
        }
    }

    for (int chunk = 0; chunk < 9; chunk++){
        __syncthreads();
        // ---- weights: [tap][k2][oc64] for this (chunk, ocg), stride-72 layout
        for (int i = t; i < 4608; i += 256){
            int oc = i & 63; int r = i >> 6;
            int k2 = r & 7; int tap = r >> 3;
            int gi = ((chunk*9 + tap)*8 + k2)*128 + ocg*64 + oc;
            int di = (tap*8 + k2)*72 + oc;
            W_HI[di] = whi[gi];
            W_LO[di] = wlo[gi];
        }
        // ---- input halo slab: 18x34 px x 16 ci, normalized, bf16 hi/lo split
        int ci0 = chunk*16;
        for (int i = t; i < 612; i += 256){
            int hy = i / 34, hx = i - hy*34;
            int gy = y0 - 1 + hy, gx = x0 - 1 + hx;
            bool inb = ((unsigned)gy < 384u) && ((unsigned)gx < 384u);
            uint4 H0 = {0,0,0,0}, H1 = {0,0,0,0}, L0 = {0,0,0,0}, L1 = {0,0,0,0};
            if (inb){
                if (chunk < 8){
                    const float4* src = (const float4*)(z + ((size_t)gy*L + gx)*128 + ci0);
                    const float4* mp  = (const float4*)(mean136 + ci0);
                    const float4* rp  = (const float4*)(rstd136 + ci0);
                    float4 v0 = src[0], v1 = src[1], v2 = src[2], v3 = src[3];
                    float4 m0 = mp[0], m1 = mp[1], m2 = mp[2], m3 = mp[3];
                    float4 r0 = rp[0], r1 = rp[1], r2 = rp[2], r3 = rp[3];
                    nsplit2((v0.x-m0.x)*r0.x, (v0.y-m0.y)*r0.y, H0.x, L0.x);
                    nsplit2((v0.z-m0.z)*r0.z, (v0.w-m0.w)*r0.w, H0.y, L0.y);
                    nsplit2((v1.x-m1.x)*r1.x, (v1.y-m1.y)*r1.y, H0.z, L0.z);
                    nsplit2((v1.z-m1.z)*r1.z, (v1.w-m1.w)*r1.w, H0.w, L0.w);
                    nsplit2((v2.x-m2.x)*r2.x, (v2.y-m2.y)*r2.y, H1.x, L1.x);
                    nsplit2((v2.z-m2.z)*r2.z, (v2.w-m2.w)*r2.w, H1.y, L1.y);
                    nsplit2((v3.x-m3.x)*r3.x, (v3.y-m3.y)*r3.y, H1.z, L1.z);
                    nsplit2((v3.z-m3.z)*r3.z, (v3.w-m3.w)*r3.w, H1.w, L1.w);
                } else {
                    int sp = gy*L + gx;
                    float v[8];
                    #pragma unroll
                    for (int c = 0; c < 8; c++)
                        v[c] = (afin[c*SPAT + sp] - mean136[128+c]) * rstd136[128+c];
                    nsplit2(v[0], v[1], H0.x, L0.x);
                    nsplit2(v[2], v[3], H0.y, L0.y);
                    nsplit2(v[4], v[5], H0.z, L0.z);
                    nsplit2(v[6], v[7], H0.w, L0.w);
                    // ci 8..15 stay zero (H1/L1 zero; weights also zero)
                }
            }
            char* dH = A_HI + i*48;
            *(uint4*)dH = H0; *(uint4*)(dH + 16) = H1;
            char* dL = A_HI + ALO_OFF + i*48;
            *(uint4*)dL = L0; *(uint4*)(dL + 16) = L1;
        }
        __syncthreads();

        for (int ky = 0; ky < 3; ky++){
            for (int kx = 0; kx < 3; kx++){
                int tap = ky*3 + kx;
                unsigned bh0[8], bh1[8], bl0[8], bl1[8];
                #pragma unroll
                for (int nt = 0; nt < 8; nt++){
                    int i0 = (tap*8 + t4    )*72 + nt*8 + g;
                    int i1 = (tap*8 + t4 + 4)*72 + nt*8 + g;
                    bh0[nt] = W_HI[i0]; bh1[nt] = W_HI[i1];
                    bl0[nt] = W_LO[i0]; bl1[nt] = W_LO[i1];
                }
                unsigned tapoff = (unsigned)((ky*34 + kx)*48);
                #pragma unroll
                for (int m = 0; m < 4; m++){
                    unsigned addr = aHiU + baseoffA + tapoff
                                  + (unsigned)((((m>>1))*34 + (m&1)*16)*48);
                    unsigned ah0, ah1, ah2, ah3, al0, al1, al2, al3;
                    ldmx4(addr, ah0, ah1, ah2, ah3);
                    ldmx4(addr + ALO_OFF, al0, al1, al2, al3);
                    #pragma unroll
                    for (int nt = 0; nt < 8; nt++)
                        mma_bf16(acc[m][nt], ah0, ah1, ah2, ah3, bh0[nt], bh1[nt]);
                    #pragma unroll
                    for (int nt = 0; nt < 8; nt++)
                        mma_bf16(acc[m][nt], al0, al1, al2, al3, bh0[nt], bh1[nt]);
                    #pragma unroll
                    for (int nt = 0; nt < 8; nt++)
                        mma_bf16(acc[m][nt], ah0, ah1, ah2, ah3, bl0[nt], bl1[nt]);
                }
            }
        }
    }

    // ---- epilogue: leaky relu, write channel-last float2 pairs
    #pragma unroll
    for (int m = 0; m < 4; m++){
        int gy = y0 + 2*wrp + (m >> 1);
        int gxb = x0 + (m & 1)*16;
        #pragma unroll
        for (int nt = 0; nt < 8; nt++){
            int oc = ocg*64 + nt*8 + 2*t4;
            float* o1 = out + ((size_t)gy*L + gxb + g    )*128 + oc;
            float* o2 = out + ((size_t)gy*L + gxb + g + 8)*128 + oc;
            *(float2*)o1 = make_float2(lrelu(acc[m][nt][0]), lrelu(acc[m][nt][1]));
            *(float2*)o2 = make_float2(lrelu(acc[m][nt][2]), lrelu(acc[m][nt][3]));
        }
    }
}

// ------------------------------------------------------------------
extern "C" void kernel_launch(void* const* d_in, const int* in_sizes, int n_in,
                              void* d_out, int out_size){
    (void)in_sizes; (void)n_in; (void)out_size;
    const float* x        = (const float*)d_in[0];
    const float* z        = (const float*)d_in[1];
    const float* plddt    = (const float*)d_in[2];
    const float* Wq       = (const float*)d_in[3];
    const float* Wk       = (const float*)d_in[4];
    const float* Wv       = (const float*)d_in[5];
    const float* Wp2a     = (const float*)d_in[6];
    const float* conv_a_w = (const float*)d_in[7];
    const float* conv_a_b = (const float*)d_in[8];
    const float* conv_m_w = (const float*)d_in[9];
    const float* conv_m_b = (const float*)d_in[10];
    const float* ln1_w    = (const float*)d_in[11];
    const float* ln1_b    = (const float*)d_in[12];
    const float* lin1_w   = (const float*)d_in[13];
    const float* lin1_b   = (const float*)d_in[14];
    const float* ln2_w    = (const float*)d_in[15];
    const float* ln2_b    = (const float*)d_in[16];
    const float* lin2_w   = (const float*)d_in[17];
    const float* lin2_b   = (const float*)d_in[18];
    const float* lnf_w    = (const float*)d_in[19];
    const float* lnf_b    = (const float*)d_in[20];
    const float* conv_p_w = (const float*)d_in[21];
    const float* conv_p_b = (const float*)d_in[22];
    float* out = (float*)d_out;

    float* S = nullptr;
    cudaGetSymbolAddress((void**)&S, g_scratch);
    float* q       = S + OFF_Q;
    float* k       = S + OFF_K;
    float* v       = S + OFF_V;
    float* a2h     = S + OFF_A2H;
    float* a8      = S + OFF_A8;
    float* afin    = S + OFF_AFIN;
    float* cat     = S + OFF_CAT;
    float* catn    = S + OFF_CATN;
    float* h1      = S + OFF_H1;
    float* h2      = S + OFF_H2;
    float* h3      = S + OFF_H3;
    float* mean16  = S + OFF_MEAN16;
    float* rstd16  = S + OFF_RSTD16;
    float* mean9   = S + OFF_MEAN9;
    float* rstd9   = S + OFF_RSTD9;
    float* mean136 = S + OFF_MEAN136;
    float* rstd136 = S + OFF_RSTD136;
    float* psum    = S + OFF_PSUM;
    float* psq     = S + OFF_PSQ;
    unsigned* wmma_hi = (unsigned*)(S + OFF_WMMA_HI);
    unsigned* wmma_lo = (unsigned*)(S + OFF_WMMA_LO);

    cudaFuncSetAttribute(convp_mma_kernel,
                         cudaFuncAttributeMaxDynamicSharedMemorySize, CONVP_SMEM);

    // z per-channel stats (channels 0..127 of zp) — independent, start early
    zstats1_kernel<<<384, 256>>>(z, psum, psq);
    zstats2_kernel<<<128, 128>>>(psum, psq, mean136, rstd136);
    // conv_p weight split/pack — independent
    wprep_mma_kernel<<<324, 256>>>(conv_p_w, wmma_hi, wmma_lo);

    // qkv + attention logits
    qkv_kernel<<<dim3(96, 3), 256>>>(x, Wq, Wk, Wv, q, k, v);
    apair_kernel<<<dim3(48, 384), 256>>>(z, Wp2a, a2h);
    anode_kernel<<<dim3(12, 12, 8), dim3(32, 32)>>>(q, k, a2h);

    // conv_a path
    stats_kernel<<<16, 256>>>(a2h, 16, nullptr, mean16, rstd16);
    conva_kernel<<<dim3(24, 24), 256>>>(a2h, conv_a_w, conv_a_b, mean16, rstd16, a8);

    // conv_m path
    stats_kernel<<<9, 256>>>(a8, 8, plddt, mean9, rstd9);
    convm_kernel<<<dim3(24, 24), 256>>>(a8, plddt, conv_m_w, conv_m_b, mean9, rstd9, afin);

    // stats for afin channels (128..135 of zp)
    stats_kernel<<<8, 256>>>(afin, 8, nullptr, mean136 + 128, rstd136 + 128);

    // pair update first (big tensor-core kernel; node tail queued after)
    convp_mma_kernel<<<dim3(12, 24, 2), 256, CONVP_SMEM>>>(
        z, afin, wmma_hi, wmma_lo, conv_p_b, mean136, rstd136, out + 384*256);

    // aggregations
    nfn_kernel<<<dim3(8, 12), dim3(32, 32)>>>(afin, v, cat);
    nfp_kernel<<<384, 256>>>(afin, z, cat);

    // MLP + final node LN
    ln_kernel<<<384, 256, 1280*sizeof(float)>>>(cat, nullptr, catn, ln1_w, ln1_b, 1280, 0);
    gemm_kernel<<<dim3(16, 12), dim3(16, 16)>>>(catn, lin1_w, lin1_b, h1, 384, 512, 1280);
    ln_kernel<<<384, 256, 512*sizeof(float)>>>(h1, nullptr, h2, ln2_w, ln2_b, 512, 1);
    gemm_kernel<<<dim3(8, 12), dim3(16, 16)>>>(h2, lin2_w, lin2_b, h3, 384, 256, 512);
    ln_kernel<<<384, 256, 256*sizeof(float)>>>(h3, x, out, lnf_w, lnf_b, 256, 0);
}

// round 14
// speedup vs baseline: 1.9853x; 1.0845x over previous
#include <cuda_runtime.h>
#include <cuda_bf16.h>
#include <cstdint>
#include <cstddef>

// Shapes: N=1, L=384, NODE=256, H=8, HD=32, PD=128, D1=1280
#define L 384
#define SPAT 147456       // 384*384
#define NODE 256
#define NH 8
#define HD 32
#define PD 128

// ---- scratch layout (floats) ----
#define OFF_Q       0
#define OFF_K       98304
#define OFF_V       196608
#define OFF_A2H     294912     // 16*147456
#define OFF_A8      2654208    // 8*147456
#define OFF_AFIN    3833856
#define OFF_CAT     5013504    // 384*1280
#define OFF_CATN    5505024
#define OFF_H1      5996544
#define OFF_H2      6193152
#define OFF_H3      6389760
#define OFF_MEAN16  6644736
#define OFF_RSTD16  6644752
#define OFF_MEAN9   6644768
#define OFF_RSTD9   6644784
#define OFF_MEAN136 6644800    // 160 slots
#define OFF_RSTD136 6644960    // 160 slots
#define OFF_PSUM    6645120    // 128*384
#define OFF_PSQ     6694272    // 128*384
#define OFF_WMMA_HI 6743424    // 663552 u32 words (= 82944 floats *8? stored as u32; 663552 words)
#define OFF_WMMA_LO 7406976    // +663552
// bf16 slabs: [chunk 9][px 147456][16 ci] bf16 = 32B/px -> 10616832 floats each
#define OFF_ZSH     8070528
#define OFF_ZSL     18687360
#define SCRATCH_FLOATS 29304192

__device__ float g_scratch[SCRATCH_FLOATS];

__device__ __forceinline__ float lrelu(float v){ return v >= 0.f ? v : 0.01f*v; }

// ---- bf16 split/pack: (a,b) -> hi word + lo (residual) word ----
__device__ __forceinline__ void nsplit2(float a, float b, unsigned &hw, unsigned &lw){
    __nv_bfloat16 ha = __float2bfloat16_rn(a);
    __nv_bfloat16 hb = __float2bfloat16_rn(b);
    float la = a - __bfloat162float(ha);
    float lb = b - __bfloat162float(hb);
    __nv_bfloat162 hp; hp.x = ha; hp.y = hb;
    __nv_bfloat162 lp; lp.x = __float2bfloat16_rn(la); lp.y = __float2bfloat16_rn(lb);
    hw = *reinterpret_cast<unsigned*>(&hp);
    lw = *reinterpret_cast<unsigned*>(&lp);
}

__device__ __forceinline__ void mma_bf16(float* c, unsigned a0, unsigned a1,
                                         unsigned a2, unsigned a3,
                                         unsigned b0, unsigned b1){
    asm volatile(
      "mma.sync.aligned.m16n8k16.row.col.f32.bf16.bf16.f32 "
      "{%0,%1,%2,%3}, {%4,%5,%6,%7}, {%8,%9}, {%0,%1,%2,%3};"
      : "+f"(c[0]), "+f"(c[1]), "+f"(c[2]), "+f"(c[3])
      : "r"(a0), "r"(a1), "r"(a2), "r"(a3), "r"(b0), "r"(b1));
}
__device__ __forceinline__ void ldmx4(unsigned addr, unsigned &r0, unsigned &r1,
                                      unsigned &r2, unsigned &r3){
    asm volatile("ldmatrix.sync.aligned.m8n8.x4.shared.b16 {%0,%1,%2,%3}, [%4];"
      : "=r"(r0), "=r"(r1), "=r"(r2), "=r"(r3) : "r"(addr));
}
__device__ __forceinline__ void cp16(unsigned sm, const void* gm, unsigned bytes){
    asm volatile("cp.async.cg.shared.global [%0], [%1], 16, %2;"
      :: "r"(sm), "l"(gm), "r"(bytes));
}
#define CP_COMMIT() asm volatile("cp.async.commit_group;")
#define CP_WAIT0()  asm volatile("cp.async.wait_group 0;")

// ------------------------------------------------------------------
// q/k/v = x @ W.  grid (96 row-tiles, 3 matrices), block 256, 4 rows/block.
// ------------------------------------------------------------------
__global__ void qkv_kernel(const float* __restrict__ x, const float* __restrict__ Wq,
                           const float* __restrict__ Wk, const float* __restrict__ Wv,
                           float* __restrict__ q, float* __restrict__ k, float* __restrict__ v){
    __shared__ float xs[4*256];
    int l0 = blockIdx.x*4, t = threadIdx.x;
    const float* W; float* o;
    if (blockIdx.y == 0){ W = Wq; o = q; }
    else if (blockIdx.y == 1){ W = Wk; o = k; }
    else { W = Wv; o = v; }
    for (int i = t; i < 4*256; i += 256) xs[i] = x[l0*256 + i];
    __syncthreads();
    float acc[4] = {0.f, 0.f, 0.f, 0.f};
    #pragma unroll 4
    for (int i = 0; i < 256; i++){
        float w = W[i*256 + t];
        #pragma unroll
        for (int r = 0; r < 4; r++) acc[r] += xs[r*256 + i]*w;
    }
    #pragma unroll
    for (int r = 0; r < 4; r++) o[(l0+r)*256 + t] = acc[r];
}

// ------------------------------------------------------------------
// a_pair[h][l][m] = z[l,m,:].Wp2a[:,h]  AND emit normalized bf16 hi/lo slabs
// (chunks 0..7 of zp). grid (48, 384), block 256 (warp per px).
// ------------------------------------------------------------------
__global__ void apair_kernel(const float* __restrict__ z, const float* __restrict__ Wp2a,
                             const float* __restrict__ mean136, const float* __restrict__ rstd136,
                             float* __restrict__ a2h,
                             uint8_t* __restrict__ zsh, uint8_t* __restrict__ zsl){
    __shared__ float ws[128*9];
    int t = threadIdx.x;
    for (int i = t; i < 1024; i += 256){
        int p = i >> 3, h = i & 7;
        ws[p*9 + h] = Wp2a[i];
    }
    __syncthreads();
    int lane = t & 31, wp = t >> 5;
    int m = blockIdx.x*8 + wp;
    int l = blockIdx.y;
    const float4 zv = *(const float4*)(z + ((size_t)l*L + m)*128 + lane*4);
    int p = lane*4;
    float acc[8];
    #pragma unroll
    for (int h = 0; h < 8; h++){
        acc[h] = zv.x*ws[p*9 + h] + zv.y*ws[(p+1)*9 + h]
               + zv.z*ws[(p+2)*9 + h] + zv.w*ws[(p+3)*9 + h];
    }
    #pragma unroll
    for (int h = 0; h < 8; h++){
        float s = acc[h];
        for (int o = 16; o > 0; o >>= 1) s += __shfl_down_sync(0xffffffffu, s, o);
        if (lane == 0) a2h[h*SPAT + l*L + m] = s;
    }
    // slab emit: lane owns ci 4*lane..4*lane+3 -> chunk lane>>2, word pair (lane&3)
    float4 mm = *(const float4*)(mean136 + p);
    float4 rr = *(const float4*)(rstd136 + p);
    unsigned h0, l0w, h1, l1w;
    nsplit2((zv.x - mm.x)*rr.x, (zv.y - mm.y)*rr.y, h0, l0w);
    nsplit2((zv.z - mm.z)*rr.z, (zv.w - mm.w)*rr.w, h1, l1w);
    size_t off = ((size_t)(lane >> 2)*SPAT + (size_t)l*L + m)*32 + (lane & 3)*8;
    uint2 hv; hv.x = h0; hv.y = h1;
    uint2 lv; lv.x = l0w; lv.y = l1w;
    *(uint2*)(zsh + off) = hv;
    *(uint2*)(zsl + off) = lv;
}

// afin slab (chunk 8): 8 real ci + 8 zeros. grid 576, block 256.
__global__ void afin_slab_kernel(const float* __restrict__ afin,
                                 const float* __restrict__ mean136,
                                 const float* __restrict__ rstd136,
                                 uint8_t* __restrict__ zsh, uint8_t* __restrict__ zsl){
    __shared__ float ms[8], rs[8];
    int t = threadIdx.x;
    if (t < 8){ ms[t] = mean136[128 + t]; rs[t] = rstd136[128 + t]; }
    __syncthreads();
    int px = blockIdx.x*256 + t;
    float v[8];
    #pragma unroll
    for (int c = 0; c < 8; c++)
        v[c] = (afin[c*SPAT + px] - ms[c]) * rs[c];
    uint4 H, Lo;
    nsplit2(v[0], v[1], H.x, Lo.x);
    nsplit2(v[2], v[3], H.y, Lo.y);
    nsplit2(v[4], v[5], H.z, Lo.z);
    nsplit2(v[6], v[7], H.w, Lo.w);
    uint4 Z = {0,0,0,0};
    size_t off = ((size_t)8*SPAT + px)*32;
    *(uint4*)(zsh + off) = H;  *(uint4*)(zsh + off + 16) = Z;
    *(uint4*)(zsl + off) = Lo; *(uint4*)(zsl + off + 16) = Z;
}

// ------------------------------------------------------------------
// a_node[h][l][m] = q[l,h,:].k[m,h,:]/sqrt(32)  (channels 8..15)
// ------------------------------------------------------------------
__global__ void anode_kernel(const float* __restrict__ q, const float* __restrict__ k,
                             float* __restrict__ a2h){
    int h = blockIdx.z;
    int l0 = blockIdx.y*32, m0 = blockIdx.x*32;
    __shared__ float Qs[32][33], Ks[32][33];
    int tx = threadIdx.x, ty = threadIdx.y;
    Qs[ty][tx] = q[(l0+ty)*256 + h*32 + tx];
    Ks[ty][tx] = k[(m0+ty)*256 + h*32 + tx];
    __syncthreads();
    float acc = 0.f;
    #pragma unroll
    for (int d = 0; d < 32; d++) acc += Qs[ty][d]*Ks[tx][d];
    a2h[(8+h)*SPAT + (l0+ty)*L + m0 + tx] = acc * 0.17677669529663687f;
}

// ------------------------------------------------------------------
// Per-channel instance-norm stats for channel-first contiguous buffers
// ------------------------------------------------------------------
__global__ void stats_kernel(const float* __restrict__ srcA, int nA,
                             const float* __restrict__ srcB,
                             float* __restrict__ mean, float* __restrict__ rstd){
    int c = blockIdx.x, t = threadIdx.x;
    const float* p = (c < nA) ? srcA + (size_t)c*SPAT : srcB + (size_t)(c-nA)*SPAT;
    const float4* p4 = (const float4*)p;
    float s = 0.f, s2 = 0.f;
    for (int i = t; i < SPAT/4; i += 256){
        float4 v = p4[i];
        s  += v.x + v.y + v.z + v.w;
        s2 += v.x*v.x + v.y*v.y + v.z*v.z + v.w*v.w;
    }
    __shared__ float ss[256], ss2[256];
    ss[t] = s; ss2[t] = s2; __syncthreads();
    for (int o = 128; o > 0; o >>= 1){
        if (t < o){ ss[t] += ss[t+o]; ss2[t] += ss2[t+o]; }
        __syncthreads();
    }
    if (t == 0){
        float m = ss[0] * (1.f/SPAT);
        float var = ss2[0] * (1.f/SPAT) - m*m;
        mean[c] = m; rstd[c] = rsqrtf(var + 1e-5f);
    }
}

// z channel stats, stage 1. grid 384, block 256.
__global__ void zstats1_kernel(const float* __restrict__ z,
                               float* __restrict__ psum, float* __restrict__ psq){
    int l = blockIdx.x, t = threadIdx.x;
    int c = t & 127, half = t >> 7;
    const float* base = z + (size_t)l*L*128;
    float s = 0.f, s2 = 0.f;
    for (int m = half; m < L; m += 2){
        float v = base[m*128 + c];
        s += v; s2 += v*v;
    }
    __shared__ float sh[256], sh2[256];
    sh[t] = s; sh2[t] = s2; __syncthreads();
    if (half == 0){
        psum[c*L + l] = sh[t] + sh[t+128];
        psq [c*L + l] = sh2[t] + sh2[t+128];
    }
}

// stage 2. grid 128, block 128.
__global__ void zstats2_kernel(const float* __restrict__ psum, const float* __restrict__ psq,
                               float* __restrict__ mean, float* __restrict__ rstd){
    int c = blockIdx.x, t = threadIdx.x;
    float s = 0.f, s2 = 0.f;
    for (int l = t; l < L; l += 128){ s += psum[c*L + l]; s2 += psq[c*L + l]; }
    __shared__ float ss[128], ss2[128];
    ss[t] = s; ss2[t] = s2; __syncthreads();
    for (int o = 64; o > 0; o >>= 1){
        if (t < o){ ss[t] += ss[t+o]; ss2[t] += ss2[t+o]; }
        __syncthreads();
    }
    if (t == 0){
        float m = ss[0] * (1.f/SPAT);
        float var = ss2[0] * (1.f/SPAT) - m*m;
        mean[c] = m; rstd[c] = rsqrtf(var + 1e-5f);
    }
}

// ------------------------------------------------------------------
// conv_a: 16ch -> 8ch, 3x3, leaky. grid (24,24), 256 thr
// ------------------------------------------------------------------
__global__ void conva_kernel(const float* __restrict__ a2h, const float* __restrict__ w,
                             const float* __restrict__ bias, const float* __restrict__ mean,
                             const float* __restrict__ rstd, float* __restrict__ a8){
    __shared__ float tin[16*324];
    __shared__ float wk[1152];
    int t = threadIdx.x;
    for (int i = t; i < 1152; i += 256) wk[i] = w[i];
    int x0 = blockIdx.x*16 - 1, y0 = blockIdx.y*16 - 1;
    for (int i = t; i < 16*324; i += 256){
        int c = i / 324, r = i % 324;
        int gy = y0 + r/18, gx = x0 + r%18;
        float v = 0.f;
        if ((unsigned)gy < 384u && (unsigned)gx < 384u)
            v = (a2h[c*SPAT + gy*L + gx] - mean[c]) * rstd[c];
        tin[i] = v;
    }
    __syncthreads();
    int lx = t & 15, ly = t >> 4;
    float acc[8];
    #pragma unroll
    for (int o = 0; o < 8; o++) acc[o] = bias[o];
    for (int c = 0; c < 16; c++){
        float iv[9];
        #pragma unroll
        for (int ky = 0; ky < 3; ky++)
            #pragma unroll
            for (int kx = 0; kx < 3; kx++)
                iv[ky*3+kx] = tin[c*324 + (ly+ky)*18 + lx + kx];
        #pragma unroll
        for (int o = 0; o < 8; o++){
            const float* wp = &wk[(o*16 + c)*9];
            acc[o] += wp[0]*iv[0]+wp[1]*iv[1]+wp[2]*iv[2]
                    + wp[3]*iv[3]+wp[4]*iv[4]+wp[5]*iv[5]
                    + wp[6]*iv[6]+wp[7]*iv[7]+wp[8]*iv[8];
        }
    }
    int gx = blockIdx.x*16 + lx, gy = blockIdx.y*16 + ly;
    #pragma unroll
    for (int o = 0; o < 8; o++)
        a8[o*SPAT + gy*L + gx] = lrelu(acc[o]);
}

// conv_m: 9ch -> 8ch, leaky. grid (24,24), 256 thr
__global__ void convm_kernel(const float* __restrict__ a8, const float* __restrict__ plddt,
                             const float* __restrict__ w, const float* __restrict__ bias,
                             const float* __restrict__ mean, const float* __restrict__ rstd,
                             float* __restrict__ afin){
    __shared__ float tin[9*324];
    __shared__ float wk[648];
    int t = threadIdx.x;
    for (int i = t; i < 648; i += 256) wk[i] = w[i];
    int x0 = blockIdx.x*16 - 1, y0 = blockIdx.y*16 - 1;
    for (int i = t; i < 9*324; i += 256){
        int c = i / 324, r = i % 324;
        int gy = y0 + r/18, gx = x0 + r%18;
        float v = 0.f;
        if ((unsigned)gy < 384u && (unsigned)gx < 384u){
            float raw = (c < 8) ? a8[c*SPAT + gy*L + gx] : plddt[gy*L + gx];
            v = (raw - mean[c]) * rstd[c];
        }
        tin[i] = v;
    }
    __syncthreads();
    int lx = t & 15, ly = t >> 4;
    float acc[8];
    #pragma unroll
    for (int o = 0; o < 8; o++) acc[o] = bias[o];
    for (int c = 0; c < 9; c++){
        float iv[9];
        #pragma unroll
        for (int ky = 0; ky < 3; ky++)
            #pragma unroll
            for (int kx = 0; kx < 3; kx++)
                iv[ky*3+kx] = tin[c*324 + (ly+ky)*18 + lx + kx];
        #pragma unroll
        for (int o = 0; o < 8; o++){
            const float* wp = &wk[(o*9 + c)*9];
            acc[o] += wp[0]*iv[0]+wp[1]*iv[1]+wp[2]*iv[2]
                    + wp[3]*iv[3]+wp[4]*iv[4]+wp[5]*iv[5]
                    + wp[6]*iv[6]+wp[7]*iv[7]+wp[8]*iv[8];
        }
    }
    int gx = blockIdx.x*16 + lx, gy = blockIdx.y*16 + ly;
    #pragma unroll
    for (int o = 0; o < 8; o++)
        afin[o*SPAT + gy*L + gx] = lrelu(acc[o]);
}

// ------------------------------------------------------------------
// nfn: cat[l, 1024 + h*32+d] = sum_m afin[h][l][m] * v[m, h*32+d]
// ------------------------------------------------------------------
__global__ void nfn_kernel(const float* __restrict__ afin, const float* __restrict__ v,
                           float* __restrict__ cat){
    int h = blockIdx.x, l0 = blockIdx.y*32;
    int tx = threadIdx.x, ty = threadIdx.y;
    __shared__ float As[32][33], Vs[32][33];
    float acc = 0.f;
    for (int m0 = 0; m0 < L; m0 += 32){
        As[ty][tx] = afin[h*SPAT + (l0+ty)*L + m0 + tx];
        Vs[ty][tx] = v[(m0+ty)*256 + h*32 + tx];
        __syncthreads();
        #pragma unroll
        for (int kk = 0; kk < 32; kk++) acc += As[ty][kk]*Vs[kk][tx];
        __syncthreads();
    }
    cat[(size_t)(l0+ty)*1280 + 1024 + h*32 + tx] = acc;
}

// nfp: cat[l, h*128+p] = sum_m afin[h][l][m] * z[l,m,p].  grid 384, block 256
__global__ void nfp_kernel(const float* __restrict__ afin, const float* __restrict__ z,
                           float* __restrict__ cat){
    int l = blockIdx.x, t = threadIdx.x;
    __shared__ float As[8][32];
    __shared__ float Zs[32*128];
    int p = t & 127, hb = (t >> 7)*4;
    float acc0 = 0.f, acc1 = 0.f, acc2 = 0.f, acc3 = 0.f;
    for (int m0 = 0; m0 < L; m0 += 32){
        __syncthreads();
        { int hh = t >> 5, mm = t & 31; As[hh][mm] = afin[hh*SPAT + l*L + m0 + mm]; }
        const float4* zsrc = (const float4*)(z + ((size_t)l*L + m0)*128);
        float4* zd = (float4*)Zs;
        for (int i = t; i < 1024; i += 256) zd[i] = zsrc[i];
        __syncthreads();
        #pragma unroll 8
        for (int mm = 0; mm < 32; mm++){
            float zv = Zs[mm*128 + p];
            acc0 += As[hb  ][mm]*zv;
            acc1 += As[hb+1][mm]*zv;
            acc2 += As[hb+2][mm]*zv;
            acc3 += As[hb+3][mm]*zv;
        }
    }
    cat[(size_t)l*1280 + (hb  )*128 + p] = acc0;
    cat[(size_t)l*1280 + (hb+1)*128 + p] = acc1;
    cat[(size_t)l*1280 + (hb+2)*128 + p] = acc2;
    cat[(size_t)l*1280 + (hb+3)*128 + p] = acc3;
}

// ------------------------------------------------------------------
// row LayerNorm
// ------------------------------------------------------------------
__global__ void ln_kernel(const float* __restrict__ in, const float* __restrict__ add,
                          float* __restrict__ out, const float* __restrict__ w,
                          const float* __restrict__ b, int D, int do_leaky){
    extern __shared__ float sh[];
    __shared__ float red[256];
    int r = blockIdx.x, t = threadIdx.x;
    float s = 0.f;
    for (int i = t; i < D; i += 256){
        float v = in[(size_t)r*D + i];
        if (add) v += add[(size_t)r*D + i];
        sh[i] = v; s += v;
    }
    red[t] = s; __syncthreads();
    for (int o = 128; o > 0; o >>= 1){ if (t < o) red[t] += red[t+o]; __syncthreads(); }
    float mean = red[0] / D;
    __syncthreads();
    float s2 = 0.f;
    for (int i = t; i < D; i += 256){ float d = sh[i] - mean; s2 += d*d; }
    red[t] = s2; __syncthreads();
    for (int o = 128; o > 0; o >>= 1){ if (t < o) red[t] += red[t+o]; __syncthreads(); }
    float rstd = rsqrtf(red[0]/D + 1e-5f);
    for (int i = t; i < D; i += 256){
        float v = (sh[i] - mean)*rstd*w[i] + b[i];
        if (do_leaky) v = lrelu(v);
        out[(size_t)r*D + i] = v;
    }
}

// generic GEMM C = A(MxK) @ B(KxN) + bias.
__global__ void gemm_kernel(const float* __restrict__ A, const float* __restrict__ B,
                            const float* __restrict__ bias, float* __restrict__ C,
                            int M, int N, int K){
    __shared__ float As[32][33], Bs[32][33];
    int tx = threadIdx.x, ty = threadIdx.y;
    int t = ty*16 + tx;
    int r0 = blockIdx.y*32, c0 = blockIdx.x*32;
    float a00 = 0.f, a01 = 0.f, a10 = 0.f, a11 = 0.f;
    for (int k0 = 0; k0 < K; k0 += 32){
        for (int i = t; i < 1024; i += 256){
            int rr = i >> 5, cc = i & 31;
            As[rr][cc] = A[(size_t)(r0+rr)*K + k0 + cc];
            Bs[rr][cc] = B[(size_t)(k0+rr)*N + c0 + cc];
        }
        __syncthreads();
        #pragma unroll
        for (int kk = 0; kk < 32; kk++){
            float av0 = As[ty*2][kk], av1 = As[ty*2+1][kk];
            float bv0 = Bs[kk][tx*2], bv1 = Bs[kk][tx*2+1];
            a00 += av0*bv0; a01 += av0*bv1; a10 += av1*bv0; a11 += av1*bv1;
        }
        __syncthreads();
    }
    int r = r0 + ty*2, c = c0 + tx*2;
    C[(size_t)r*N + c]       = a00 + bias[c];
    C[(size_t)r*N + c+1]     = a01 + bias[c+1];
    C[(size_t)(r+1)*N + c]   = a10 + bias[c];
    C[(size_t)(r+1)*N + c+1] = a11 + bias[c+1];
}

// ------------------------------------------------------------------
// conv_p weight prep: split fp32 -> bf16 hi/lo packed into 8x8 ldmatrix-B tiles.
// Word layout: [chunk 9][tap 9][nt 16][b 2][ocrow 8][kw 4]  (u32 = bf16 pair
// along k). tile(nt,b) = 8 rows (oc) x 16B (8 k-values).
// ------------------------------------------------------------------
__global__ void wprep_mma_kernel(const float* __restrict__ w,
                                 unsigned* __restrict__ whi, unsigned* __restrict__ wlo){
    int j = blockIdx.x*256 + threadIdx.x;   // 663552 words
    if (j >= 9*9*16*2*8*4) return;
    int kw  = j & 3;
    int ocr = (j >> 2) & 7;
    int b   = (j >> 5) & 1;
    int nt  = (j >> 6) & 15;
    int tt  = j >> 10;
    int tap = tt % 9, chunk = tt / 9;
    int ci = chunk*16 + b*8 + 2*kw;
    int oc = nt*8 + ocr;
    float w0 = (ci     < 136) ? w[(oc*136 + ci    )*9 + tap] : 0.f;
    float w1 = (ci + 1 < 136) ? w[(oc*136 + ci + 1)*9 + tap] : 0.f;
    unsigned hw, lw;
    nsplit2(w0, w1, hw, lw);
    whi[j] = hw; wlo[j] = lw;
}

// ------------------------------------------------------------------
// conv_p via bf16 mma, cp.async double-buffered pipeline.
// grid (12 x-tiles, 24 y-tiles, 2 ocg), block 256 (8 warps).
// smem: A(hi+lo) x2 bufs @58752 each; W(hi+lo) x2 bufs @36864 each = 191232 B.
// ------------------------------------------------------------------
#define A_BUF_SZ   58752     // 612 px * 48B * 2 (hi+lo)
#define A_LO_DELTA 29376
#define W_BASE     117504
#define W_BUF_SZ   36864     // 9 taps * 2048B * 2 (hi+lo)
#define W_LO_DELTA 18432
#define CONVP_SMEM 191232

__global__ void __launch_bounds__(256)
convp_mma_kernel(const uint8_t* __restrict__ zsh, const uint8_t* __restrict__ zsl,
                 const unsigned* __restrict__ whi, const unsigned* __restrict__ wlo,
                 const float* __restrict__ bias, float* __restrict__ out){
    extern __shared__ char sm[];
    unsigned smU = (unsigned)__cvta_generic_to_shared(sm);

    int t = threadIdx.x;
    int x0 = blockIdx.x*32, y0 = blockIdx.y*16, ocg = blockIdx.z;
    int lane = t & 31, wrp = t >> 5;
    int t4 = lane & 3, g = lane >> 2;
    int qd = lane >> 3, r8 = lane & 7;
    int prow = (qd & 1)*8 + r8;
    int khalf = qd >> 1;
    unsigned baseoffA = (unsigned)(((2*wrp)*34 + prow)*48 + khalf*16);

    float acc[4][8][4];
    #pragma unroll
    for (int nt = 0; nt < 8; nt++){
        float2 bv = *(const float2*)(bias + ocg*64 + nt*8 + 2*t4);
        #pragma unroll
        for (int m = 0; m < 4; m++){
            acc[m][nt][0] = bv.x; acc[m][nt][1] = bv.y;
            acc[m][nt][2] = bv.x; acc[m][nt][3] = bv.y;
        }
    }

    auto issueA = [&](int chunk, int buf){
        unsigned abase = smU + buf*A_BUF_SZ;
        for (int i = t; i < 612; i += 256){
            int hy = i / 34, hx = i - hy*34;
            int gy = y0 - 1 + hy, gx = x0 - 1 + hx;
            bool inb = ((unsigned)gy < 384u) && ((unsigned)gx < 384u);
            unsigned nb = inb ? 16u : 0u;
            size_t go = ((size_t)chunk*SPAT + (inb ? (gy*L + gx) : 0))*32;
            unsigned sa = abase + i*48;
            cp16(sa,                  zsh + go,      nb);
            cp16(sa + 16,             zsh + go + 16, nb);
            cp16(sa + A_LO_DELTA,     zsl + go,      nb);
            cp16(sa + A_LO_DELTA+16,  zsl + go + 16, nb);
        }
    };
    auto issueW = [&](int chunk, int buf){
        unsigned wb = smU + W_BASE + buf*W_BUF_SZ;
        const char* gh = (const char*)whi;
        const char* gl = (const char*)wlo;
        for (int i = t; i < 1152; i += 256){
            int tap = i >> 7, wi = i & 127;
            unsigned sa = wb + tap*2048 + wi*16;
            size_t go = (((size_t)(chunk*9 + tap))*1024 + (size_t)ocg*512)*4 + wi*16;
            cp16(sa,              gh + go, 16);
            cp16(sa + W_LO_DELTA, gl + go, 16);
        }
    };

    issueA(0, 0); issueW(0, 0); CP_COMMIT();
    CP_WAIT0(); __syncthreads();

    for (int c = 0; c < 9; c++){
        int cur = c & 1;
        if (c < 8){ issueA(c+1, cur^1); issueW(c+1, cur^1); CP_COMMIT(); }

        unsigned aBase = smU + cur*A_BUF_SZ;
        unsigned wBase = smU + W_BASE + cur*W_BUF_SZ;

        #pragma unroll
        for (int ky = 0; ky < 3; ky++){
            #pragma unroll
            for (int kx = 0; kx < 3; kx++){
                int tap = ky*3 + kx;
                unsigned bh0[8], bh1[8], bl0[8], bl1[8];
                #pragma unroll
                for (int p = 0; p < 4; p++){
                    unsigned baddr = wBase + tap*2048 + p*512
                                   + (lane >> 3)*128 + (lane & 7)*16;
                    ldmx4(baddr, bh0[2*p], bh1[2*p], bh0[2*p+1], bh1[2*p+1]);
                    ldmx4(baddr + W_LO_DELTA, bl0[2*p], bl1[2*p], bl0[2*p+1], bl1[2*p+1]);
                }
                unsigned tapoff = (unsigned)((ky*34 + kx)*48);
                #pragma unroll
                for (int m = 0; m < 4; m++){
                    unsigned addr = aBase + baseoffA + tapoff
                                  + (unsigned)((((m>>1))*34 + (m&1)*16)*48);
                    unsigned ah0, ah1, ah2, ah3, al0, al1, al2, al3;
                    ldmx4(addr, ah0, ah1, ah2, ah3);
                    ldmx4(addr + A_LO_DELTA, al0, al1, al2, al3);
                    #pragma unroll
                    for (int nt = 0; nt < 8; nt++)
                        mma_bf16(acc[m][nt], ah0, ah1, ah2, ah3, bh0[nt], bh1[nt]);
                    #pragma unroll
                    for (int nt = 0; nt < 8; nt++)
                        mma_bf16(acc[m][nt], al0, al1, al2, al3, bh0[nt], bh1[nt]);
                    #pragma unroll
                    for (int nt = 0; nt < 8; nt++)
                        mma_bf16(acc[m][nt], ah0, ah1, ah2, ah3, bl0[nt], bl1[nt]);
                }
            }
        }
        if (c < 8){ CP_WAIT0(); __syncthreads(); }
    }

    // ---- epilogue: leaky relu, write channel-last float2 pairs
    #pragma unroll
    for (int m = 0; m < 4; m++){
        int gy = y0 + 2*wrp + (m >> 1);
        int gxb = x0 + (m & 1)*16;
        #pragma unroll
        for (int nt = 0; nt < 8; nt++){
            int oc = ocg*64 + nt*8 + 2*t4;
            float* o1 = out + ((size_t)gy*L + gxb + g    )*128 + oc;
            float* o2 = out + ((size_t)gy*L + gxb + g + 8)*128 + oc;
            *(float2*)o1 = make_float2(lrelu(acc[m][nt][0]), lrelu(acc[m][nt][1]));
            *(float2*)o2 = make_float2(lrelu(acc[m][nt][2]), lrelu(acc[m][nt][3]));
        }
    }
}

// ------------------------------------------------------------------
extern "C" void kernel_launch(void* const* d_in, const int* in_sizes, int n_in,
                              void* d_out, int out_size){
    (void)in_sizes; (void)n_in; (void)out_size;
    const float* x        = (const float*)d_in[0];
    const float* z        = (const float*)d_in[1];
    const float* plddt    = (const float*)d_in[2];
    const float* Wq       = (const float*)d_in[3];
    const float* Wk       = (const float*)d_in[4];
    const float* Wv       = (const float*)d_in[5];
    const float* Wp2a     = (const float*)d_in[6];
    const float* conv_a_w = (const float*)d_in[7];
    const float* conv_a_b = (const float*)d_in[8];
    const float* conv_m_w = (const float*)d_in[9];
    const float* conv_m_b = (const float*)d_in[10];
    const float* ln1_w    = (const float*)d_in[11];
    const float* ln1_b    = (const float*)d_in[12];
    const float* lin1_w   = (const float*)d_in[13];
    const float* lin1_b   = (const float*)d_in[14];
    const float* ln2_w    = (const float*)d_in[15];
    const float* ln2_b    = (const float*)d_in[16];
    const float* lin2_w   = (const float*)d_in[17];
    const float* lin2_b   = (const float*)d_in[18];
    const float* lnf_w    = (const float*)d_in[19];
    const float* lnf_b    = (const float*)d_in[20];
    const float* conv_p_w = (const float*)d_in[21];
    const float* conv_p_b = (const float*)d_in[22];
    float* out = (float*)d_out;

    float* S = nullptr;
    cudaGetSymbolAddress((void**)&S, g_scratch);
    float* q       = S + OFF_Q;
    float* k       = S + OFF_K;
    float* v       = S + OFF_V;
    float* a2h     = S + OFF_A2H;
    float* a8      = S + OFF_A8;
    float* afin    = S + OFF_AFIN;
    float* cat     = S + OFF_CAT;
    float* catn    = S + OFF_CATN;
    float* h1      = S + OFF_H1;
    float* h2      = S + OFF_H2;
    float* h3      = S + OFF_H3;
    float* mean16  = S + OFF_MEAN16;
    float* rstd16  = S + OFF_RSTD16;
    float* mean9   = S + OFF_MEAN9;
    float* rstd9   = S + OFF_RSTD9;
    float* mean136 = S + OFF_MEAN136;
    float* rstd136 = S + OFF_RSTD136;
    float* psum    = S + OFF_PSUM;
    float* psq     = S + OFF_PSQ;
    unsigned* wmma_hi = (unsigned*)(S + OFF_WMMA_HI);
    unsigned* wmma_lo = (unsigned*)(S + OFF_WMMA_LO);
    uint8_t* zsh = (uint8_t*)(S + OFF_ZSH);
    uint8_t* zsl = (uint8_t*)(S + OFF_ZSL);

    cudaFuncSetAttribute(convp_mma_kernel,
                         cudaFuncAttributeMaxDynamicSharedMemorySize, CONVP_SMEM);

    // z per-channel stats — must precede apair (slab emit needs mean/rstd)
    zstats1_kernel<<<384, 256>>>(z, psum, psq);
    zstats2_kernel<<<128, 128>>>(psum, psq, mean136, rstd136);
    // conv_p weight split/pack — independent
    wprep_mma_kernel<<<2592, 256>>>(conv_p_w, wmma_hi, wmma_lo);

    // qkv + attention logits (apair also emits z bf16 slabs, chunks 0..7)
    qkv_kernel<<<dim3(96, 3), 256>>>(x, Wq, Wk, Wv, q, k, v);
    apair_kernel<<<dim3(48, 384), 256>>>(z, Wp2a, mean136, rstd136, a2h, zsh, zsl);
    anode_kernel<<<dim3(12, 12, 8), dim3(32, 32)>>>(q, k, a2h);

    // conv_a path
    stats_kernel<<<16, 256>>>(a2h, 16, nullptr, mean16, rstd16);
    conva_kernel<<<dim3(24, 24), 256>>>(a2h, conv_a_w, conv_a_b, mean16, rstd16, a8);

    // conv_m path
    stats_kernel<<<9, 256>>>(a8, 8, plddt, mean9, rstd9);
    convm_kernel<<<dim3(24, 24), 256>>>(a8, plddt, conv_m_w, conv_m_b, mean9, rstd9, afin);

    // stats + slab for afin channels (chunk 8 of zp)
    stats_kernel<<<8, 256>>>(afin, 8, nullptr, mean136 + 128, rstd136 + 128);
    afin_slab_kernel<<<576, 256>>>(afin, mean136, rstd136, zsh, zsl);

    // pair update (pipelined tensor-core conv)
    convp_mma_kernel<<<dim3(12, 24, 2), 256, CONVP_SMEM>>>(
        zsh, zsl, wmma_hi, wmma_lo, conv_p_b, out + 384*256);

    // aggregations
    nfn_kernel<<<dim3(8, 12), dim3(32, 32)>>>(afin, v, cat);
    nfp_kernel<<<384, 256>>>(afin, z, cat);

    // MLP + final node LN
    ln_kernel<<<384, 256, 1280*sizeof(float)>>>(cat, nullptr, catn, ln1_w, ln1_b, 1280, 0);
    gemm_kernel<<<dim3(16, 12), dim3(16, 16)>>>(catn, lin1_w, lin1_b, h1, 384, 512, 1280);
    ln_kernel<<<384, 256, 512*sizeof(float)>>>(h1, nullptr, h2, ln2_w, ln2_b, 512, 1);
    gemm_kernel<<<dim3(8, 12), dim3(16, 16)>>>(h2, lin2_w, lin2_b, h3, 384, 256, 512);
    ln_kernel<<<384, 256, 256*sizeof(float)>>>(h3, x, out, lnf_w, lnf_b, 256, 0);
}

// round 15
// speedup vs baseline: 2.0065x; 1.0107x over previous
#include <cuda_runtime.h>
#include <cuda_bf16.h>
#include <cstdint>
#include <cstddef>

// Shapes: N=1, L=384, NODE=256, H=8, HD=32, PD=128, D1=1280
#define L 384
#define SPAT 147456       // 384*384
#define NODE 256
#define NH 8
#define HD 32
#define PD 128

// ---- scratch layout (floats) ----
#define OFF_Q       0
#define OFF_K       98304
#define OFF_V       196608
#define OFF_A2H     294912     // 16*147456
#define OFF_A8      2654208    // 8*147456
#define OFF_AFIN    3833856
#define OFF_CAT     5013504    // 384*1280
#define OFF_CATN    5505024
#define OFF_H1      5996544
#define OFF_H2      6193152
#define OFF_H3      6389760
#define OFF_MEAN16  6644736
#define OFF_RSTD16  6644752
#define OFF_MEAN9   6644768
#define OFF_RSTD9   6644784
#define OFF_MEAN136 6644800    // 160 slots
#define OFF_RSTD136 6644960    // 160 slots
#define OFF_PSUM    6645120    // 128*384
#define OFF_PSQ     6694272    // 128*384
#define OFF_WMMA_HI 6743424    // 663552 u32 words (= 82944 floats *8? stored as u32; 663552 words)
#define OFF_WMMA_LO 7406976    // +663552
// bf16 slabs: [chunk 9][px 147456][16 ci] bf16 = 32B/px -> 10616832 floats each
#define OFF_ZSH     8070528
#define OFF_ZSL     18687360
#define SCRATCH_FLOATS 29304192

__device__ float g_scratch[SCRATCH_FLOATS];

__device__ __forceinline__ float lrelu(float v){ return v >= 0.f ? v : 0.01f*v; }

// ---- bf16 split/pack: (a,b) -> hi word + lo (residual) word ----
__device__ __forceinline__ void nsplit2(float a, float b, unsigned &hw, unsigned &lw){
    __nv_bfloat16 ha = __float2bfloat16_rn(a);
    __nv_bfloat16 hb = __float2bfloat16_rn(b);
    float la = a - __bfloat162float(ha);
    float lb = b - __bfloat162float(hb);
    __nv_bfloat162 hp; hp.x = ha; hp.y = hb;
    __nv_bfloat162 lp; lp.x = __float2bfloat16_rn(la); lp.y = __float2bfloat16_rn(lb);
    hw = *reinterpret_cast<unsigned*>(&hp);
    lw = *reinterpret_cast<unsigned*>(&lp);
}

__device__ __forceinline__ void mma_bf16(float* c, unsigned a0, unsigned a1,
                                         unsigned a2, unsigned a3,
                                         unsigned b0, unsigned b1){
    asm volatile(
      "mma.sync.aligned.m16n8k16.row.col.f32.bf16.bf16.f32 "
      "{%0,%1,%2,%3}, {%4,%5,%6,%7}, {%8,%9}, {%0,%1,%2,%3};"
      : "+f"(c[0]), "+f"(c[1]), "+f"(c[2]), "+f"(c[3])
      : "r"(a0), "r"(a1), "r"(a2), "r"(a3), "r"(b0), "r"(b1));
}
__device__ __forceinline__ void ldmx4(unsigned addr, unsigned &r0, unsigned &r1,
                                      unsigned &r2, unsigned &r3){
    asm volatile("ldmatrix.sync.aligned.m8n8.x4.shared.b16 {%0,%1,%2,%3}, [%4];"
      : "=r"(r0), "=r"(r1), "=r"(r2), "=r"(r3) : "r"(addr));
}
__device__ __forceinline__ void cp16(unsigned sm, const void* gm, unsigned bytes){
    asm volatile("cp.async.cg.shared.global [%0], [%1], 16, %2;"
      :: "r"(sm), "l"(gm), "r"(bytes));
}
#define CP_COMMIT() asm volatile("cp.async.commit_group;")
#define CP_WAIT0()  asm volatile("cp.async.wait_group 0;")

// ------------------------------------------------------------------
// q/k/v = x @ W.  grid (96 row-tiles, 3 matrices), block 256, 4 rows/block.
// ------------------------------------------------------------------
__global__ void qkv_kernel(const float* __restrict__ x, const float* __restrict__ Wq,
                           const float* __restrict__ Wk, const float* __restrict__ Wv,
                           float* __restrict__ q, float* __restrict__ k, float* __restrict__ v){
    __shared__ float xs[4*256];
    int l0 = blockIdx.x*4, t = threadIdx.x;
    const float* W; float* o;
    if (blockIdx.y == 0){ W = Wq; o = q; }
    else if (blockIdx.y == 1){ W = Wk; o = k; }
    else { W = Wv; o = v; }
    for (int i = t; i < 4*256; i += 256) xs[i] = x[l0*256 + i];
    __syncthreads();
    float acc[4] = {0.f, 0.f, 0.f, 0.f};
    #pragma unroll 4
    for (int i = 0; i < 256; i++){
        float w = W[i*256 + t];
        #pragma unroll
        for (int r = 0; r < 4; r++) acc[r] += xs[r*256 + i]*w;
    }
    #pragma unroll
    for (int r = 0; r < 4; r++) o[(l0+r)*256 + t] = acc[r];
}

// ------------------------------------------------------------------
// a_pair[h][l][m] = z[l,m,:].Wp2a[:,h]  AND emit normalized bf16 hi/lo slabs
// (chunks 0..7 of zp). grid (48, 384), block 256 (warp per px).
// ------------------------------------------------------------------
__global__ void apair_kernel(const float* __restrict__ z, const float* __restrict__ Wp2a,
                             const float* __restrict__ mean136, const float* __restrict__ rstd136,
                             float* __restrict__ a2h,
                             uint8_t* __restrict__ zsh, uint8_t* __restrict__ zsl){
    __shared__ float ws[128*9];
    int t = threadIdx.x;
    for (int i = t; i < 1024; i += 256){
        int p = i >> 3, h = i & 7;
        ws[p*9 + h] = Wp2a[i];
    }
    __syncthreads();
    int lane = t & 31, wp = t >> 5;
    int m = blockIdx.x*8 + wp;
    int l = blockIdx.y;
    const float4 zv = *(const float4*)(z + ((size_t)l*L + m)*128 + lane*4);
    int p = lane*4;
    float acc[8];
    #pragma unroll
    for (int h = 0; h < 8; h++){
        acc[h] = zv.x*ws[p*9 + h] + zv.y*ws[(p+1)*9 + h]
               + zv.z*ws[(p+2)*9 + h] + zv.w*ws[(p+3)*9 + h];
    }
    #pragma unroll
    for (int h = 0; h < 8; h++){
        float s = acc[h];
        for (int o = 16; o > 0; o >>= 1) s += __shfl_down_sync(0xffffffffu, s, o);
        if (lane == 0) a2h[h*SPAT + l*L + m] = s;
    }
    // slab emit: lane owns ci 4*lane..4*lane+3 -> chunk lane>>2, word pair (lane&3)
    float4 mm = *(const float4*)(mean136 + p);
    float4 rr = *(const float4*)(rstd136 + p);
    unsigned h0, l0w, h1, l1w;
    nsplit2((zv.x - mm.x)*rr.x, (zv.y - mm.y)*rr.y, h0, l0w);
    nsplit2((zv.z - mm.z)*rr.z, (zv.w - mm.w)*rr.w, h1, l1w);
    size_t off = ((size_t)(lane >> 2)*SPAT + (size_t)l*L + m)*32 + (lane & 3)*8;
    uint2 hv; hv.x = h0; hv.y = h1;
    uint2 lv; lv.x = l0w; lv.y = l1w;
    *(uint2*)(zsh + off) = hv;
    *(uint2*)(zsl + off) = lv;
}

// afin slab (chunk 8): 8 real ci + 8 zeros. grid 576, block 256.
__global__ void afin_slab_kernel(const float* __restrict__ afin,
                                 const float* __restrict__ mean136,
                                 const float* __restrict__ rstd136,
                                 uint8_t* __restrict__ zsh, uint8_t* __restrict__ zsl){
    __shared__ float ms[8], rs[8];
    int t = threadIdx.x;
    if (t < 8){ ms[t] = mean136[128 + t]; rs[t] = rstd136[128 + t]; }
    __syncthreads();
    int px = blockIdx.x*256 + t;
    float v[8];
    #pragma unroll
    for (int c = 0; c < 8; c++)
        v[c] = (afin[c*SPAT + px] - ms[c]) * rs[c];
    uint4 H, Lo;
    nsplit2(v[0], v[1], H.x, Lo.x);
    nsplit2(v[2], v[3], H.y, Lo.y);
    nsplit2(v[4], v[5], H.z, Lo.z);
    nsplit2(v[6], v[7], H.w, Lo.w);
    uint4 Z = {0,0,0,0};
    size_t off = ((size_t)8*SPAT + px)*32;
    *(uint4*)(zsh + off) = H;  *(uint4*)(zsh + off + 16) = Z;
    *(uint4*)(zsl + off) = Lo; *(uint4*)(zsl + off + 16) = Z;
}

// ------------------------------------------------------------------
// a_node[h][l][m] = q[l,h,:].k[m,h,:]/sqrt(32)  (channels 8..15)
// ------------------------------------------------------------------
__global__ void anode_kernel(const float* __restrict__ q, const float* __restrict__ k,
                             float* __restrict__ a2h){
    int h = blockIdx.z;
    int l0 = blockIdx.y*32, m0 = blockIdx.x*32;
    __shared__ float Qs[32][33], Ks[32][33];
    int tx = threadIdx.x, ty = threadIdx.y;
    Qs[ty][tx] = q[(l0+ty)*256 + h*32 + tx];
    Ks[ty][tx] = k[(m0+ty)*256 + h*32 + tx];
    __syncthreads();
    float acc = 0.f;
    #pragma unroll
    for (int d = 0; d < 32; d++) acc += Qs[ty][d]*Ks[tx][d];
    a2h[(8+h)*SPAT + (l0+ty)*L + m0 + tx] = acc * 0.17677669529663687f;
}

// ------------------------------------------------------------------
// Per-channel instance-norm stats for channel-first contiguous buffers
// ------------------------------------------------------------------
__global__ void stats_kernel(const float* __restrict__ srcA, int nA,
                             const float* __restrict__ srcB,
                             float* __restrict__ mean, float* __restrict__ rstd){
    int c = blockIdx.x, t = threadIdx.x;
    const float* p = (c < nA) ? srcA + (size_t)c*SPAT : srcB + (size_t)(c-nA)*SPAT;
    const float4* p4 = (const float4*)p;
    float s = 0.f, s2 = 0.f;
    for (int i = t; i < SPAT/4; i += 256){
        float4 v = p4[i];
        s  += v.x + v.y + v.z + v.w;
        s2 += v.x*v.x + v.y*v.y + v.z*v.z + v.w*v.w;
    }
    __shared__ float ss[256], ss2[256];
    ss[t] = s; ss2[t] = s2; __syncthreads();
    for (int o = 128; o > 0; o >>= 1){
        if (t < o){ ss[t] += ss[t+o]; ss2[t] += ss2[t+o]; }
        __syncthreads();
    }
    if (t == 0){
        float m = ss[0] * (1.f/SPAT);
        float var = ss2[0] * (1.f/SPAT) - m*m;
        mean[c] = m; rstd[c] = rsqrtf(var + 1e-5f);
    }
}

// z channel stats, stage 1. grid 384, block 256.
__global__ void zstats1_kernel(const float* __restrict__ z,
                               float* __restrict__ psum, float* __restrict__ psq){
    int l = blockIdx.x, t = threadIdx.x;
    int c = t & 127, half = t >> 7;
    const float* base = z + (size_t)l*L*128;
    float s = 0.f, s2 = 0.f;
    for (int m = half; m < L; m += 2){
        float v = base[m*128 + c];
        s += v; s2 += v*v;
    }
    __shared__ float sh[256], sh2[256];
    sh[t] = s; sh2[t] = s2; __syncthreads();
    if (half == 0){
        psum[c*L + l] = sh[t] + sh[t+128];
        psq [c*L + l] = sh2[t] + sh2[t+128];
    }
}

// stage 2. grid 128, block 128.
__global__ void zstats2_kernel(const float* __restrict__ psum, const float* __restrict__ psq,
                               float* __restrict__ mean, float* __restrict__ rstd){
    int c = blockIdx.x, t = threadIdx.x;
    float s = 0.f, s2 = 0.f;
    for (int l = t; l < L; l += 128){ s += psum[c*L + l]; s2 += psq[c*L + l]; }
    __shared__ float ss[128], ss2[128];
    ss[t] = s; ss2[t] = s2; __syncthreads();
    for (int o = 64; o > 0; o >>= 1){
        if (t < o){ ss[t] += ss[t+o]; ss2[t] += ss2[t+o]; }
        __syncthreads();
    }
    if (t == 0){
        float m = ss[0] * (1.f/SPAT);
        float var = ss2[0] * (1.f/SPAT) - m*m;
        mean[c] = m; rstd[c] = rsqrtf(var + 1e-5f);
    }
}

// ------------------------------------------------------------------
// conv_a: 16ch -> 8ch, 3x3, leaky. grid (24,24), 256 thr
// ------------------------------------------------------------------
__global__ void conva_kernel(const float* __restrict__ a2h, const float* __restrict__ w,
                             const float* __restrict__ bias, const float* __restrict__ mean,
                             const float* __restrict__ rstd, float* __restrict__ a8){
    __shared__ float tin[16*324];
    __shared__ float wk[1152];
    int t = threadIdx.x;
    for (int i = t; i < 1152; i += 256) wk[i] = w[i];
    int x0 = blockIdx.x*16 - 1, y0 = blockIdx.y*16 - 1;
    for (int i = t; i < 16*324; i += 256){
        int c = i / 324, r = i % 324;
        int gy = y0 + r/18, gx = x0 + r%18;
        float v = 0.f;
        if ((unsigned)gy < 384u && (unsigned)gx < 384u)
            v = (a2h[c*SPAT + gy*L + gx] - mean[c]) * rstd[c];
        tin[i] = v;
    }
    __syncthreads();
    int lx = t & 15, ly = t >> 4;
    float acc[8];
    #pragma unroll
    for (int o = 0; o < 8; o++) acc[o] = bias[o];
    for (int c = 0; c < 16; c++){
        float iv[9];
        #pragma unroll
        for (int ky = 0; ky < 3; ky++)
            #pragma unroll
            for (int kx = 0; kx < 3; kx++)
                iv[ky*3+kx] = tin[c*324 + (ly+ky)*18 + lx + kx];
        #pragma unroll
        for (int o = 0; o < 8; o++){
            const float* wp = &wk[(o*16 + c)*9];
            acc[o] += wp[0]*iv[0]+wp[1]*iv[1]+wp[2]*iv[2]
                    + wp[3]*iv[3]+wp[4]*iv[4]+wp[5]*iv[5]
                    + wp[6]*iv[6]+wp[7]*iv[7]+wp[8]*iv[8];
        }
    }
    int gx = blockIdx.x*16 + lx, gy = blockIdx.y*16 + ly;
    #pragma unroll
    for (int o = 0; o < 8; o++)
        a8[o*SPAT + gy*L + gx] = lrelu(acc[o]);
}

// conv_m: 9ch -> 8ch, leaky. grid (24,24), 256 thr
__global__ void convm_kernel(const float* __restrict__ a8, const float* __restrict__ plddt,
                             const float* __restrict__ w, const float* __restrict__ bias,
                             const float* __restrict__ mean, const float* __restrict__ rstd,
                             float* __restrict__ afin){
    __shared__ float tin[9*324];
    __shared__ float wk[648];
    int t = threadIdx.x;
    for (int i = t; i < 648; i += 256) wk[i] = w[i];
    int x0 = blockIdx.x*16 - 1, y0 = blockIdx.y*16 - 1;
    for (int i = t; i < 9*324; i += 256){
        int c = i / 324, r = i % 324;
        int gy = y0 + r/18, gx = x0 + r%18;
        float v = 0.f;
        if ((unsigned)gy < 384u && (unsigned)gx < 384u){
            float raw = (c < 8) ? a8[c*SPAT + gy*L + gx] : plddt[gy*L + gx];
            v = (raw - mean[c]) * rstd[c];
        }
        tin[i] = v;
    }
    __syncthreads();
    int lx = t & 15, ly = t >> 4;
    float acc[8];
    #pragma unroll
    for (int o = 0; o < 8; o++) acc[o] = bias[o];
    for (int c = 0; c < 9; c++){
        float iv[9];
        #pragma unroll
        for (int ky = 0; ky < 3; ky++)
            #pragma unroll
            for (int kx = 0; kx < 3; kx++)
                iv[ky*3+kx] = tin[c*324 + (ly+ky)*18 + lx + kx];
        #pragma unroll
        for (int o = 0; o < 8; o++){
            const float* wp = &wk[(o*9 + c)*9];
            acc[o] += wp[0]*iv[0]+wp[1]*iv[1]+wp[2]*iv[2]
                    + wp[3]*iv[3]+wp[4]*iv[4]+wp[5]*iv[5]
                    + wp[6]*iv[6]+wp[7]*iv[7]+wp[8]*iv[8];
        }
    }
    int gx = blockIdx.x*16 + lx, gy = blockIdx.y*16 + ly;
    #pragma unroll
    for (int o = 0; o < 8; o++)
        afin[o*SPAT + gy*L + gx] = lrelu(acc[o]);
}

// ------------------------------------------------------------------
// nfn: cat[l, 1024 + h*32+d] = sum_m afin[h][l][m] * v[m, h*32+d]
// ------------------------------------------------------------------
__global__ void nfn_kernel(const float* __restrict__ afin, const float* __restrict__ v,
                           float* __restrict__ cat){
    int h = blockIdx.x, l0 = blockIdx.y*32;
    int tx = threadIdx.x, ty = threadIdx.y;
    __shared__ float As[32][33], Vs[32][33];
    float acc = 0.f;
    for (int m0 = 0; m0 < L; m0 += 32){
        As[ty][tx] = afin[h*SPAT + (l0+ty)*L + m0 + tx];
        Vs[ty][tx] = v[(m0+ty)*256 + h*32 + tx];
        __syncthreads();
        #pragma unroll
        for (int kk = 0; kk < 32; kk++) acc += As[ty][kk]*Vs[kk][tx];
        __syncthreads();
    }
    cat[(size_t)(l0+ty)*1280 + 1024 + h*32 + tx] = acc;
}

// nfp: cat[l, h*128+p] = sum_m afin[h][l][m] * z[l,m,p].  grid 384, block 256
__global__ void nfp_kernel(const float* __restrict__ afin, const float* __restrict__ z,
                           float* __restrict__ cat){
    int l = blockIdx.x, t = threadIdx.x;
    __shared__ float As[8][32];
    __shared__ float Zs[32*128];
    int p = t & 127, hb = (t >> 7)*4;
    float acc0 = 0.f, acc1 = 0.f, acc2 = 0.f, acc3 = 0.f;
    for (int m0 = 0; m0 < L; m0 += 32){
        __syncthreads();
        { int hh = t >> 5, mm = t & 31; As[hh][mm] = afin[hh*SPAT + l*L + m0 + mm]; }
        const float4* zsrc = (const float4*)(z + ((size_t)l*L + m0)*128);
        float4* zd = (float4*)Zs;
        for (int i = t; i < 1024; i += 256) zd[i] = zsrc[i];
        __syncthreads();
        #pragma unroll 8
        for (int mm = 0; mm < 32; mm++){
            float zv = Zs[mm*128 + p];
            acc0 += As[hb  ][mm]*zv;
            acc1 += As[hb+1][mm]*zv;
            acc2 += As[hb+2][mm]*zv;
            acc3 += As[hb+3][mm]*zv;
        }
    }
    cat[(size_t)l*1280 + (hb  )*128 + p] = acc0;
    cat[(size_t)l*1280 + (hb+1)*128 + p] = acc1;
    cat[(size_t)l*1280 + (hb+2)*128 + p] = acc2;
    cat[(size_t)l*1280 + (hb+3)*128 + p] = acc3;
}

// ------------------------------------------------------------------
// row LayerNorm
// ------------------------------------------------------------------
__global__ void ln_kernel(const float* __restrict__ in, const float* __restrict__ add,
                          float* __restrict__ out, const float* __restrict__ w,
                          const float* __restrict__ b, int D, int do_leaky){
    extern __shared__ float sh[];
    __shared__ float red[256];
    int r = blockIdx.x, t = threadIdx.x;
    float s = 0.f;
    for (int i = t; i < D; i += 256){
        float v = in[(size_t)r*D + i];
        if (add) v += add[(size_t)r*D + i];
        sh[i] = v; s += v;
    }
    red[t] = s; __syncthreads();
    for (int o = 128; o > 0; o >>= 1){ if (t < o) red[t] += red[t+o]; __syncthreads(); }
    float mean = red[0] / D;
    __syncthreads();
    float s2 = 0.f;
    for (int i = t; i < D; i += 256){ float d = sh[i] - mean; s2 += d*d; }
    red[t] = s2; __syncthreads();
    for (int o = 128; o > 0; o >>= 1){ if (t < o) red[t] += red[t+o]; __syncthreads(); }
    float rstd = rsqrtf(red[0]/D + 1e-5f);
    for (int i = t; i < D; i += 256){
        float v = (sh[i] - mean)*rstd*w[i] + b[i];
        if (do_leaky) v = lrelu(v);
        out[(size_t)r*D + i] = v;
    }
}

// generic GEMM C = A(MxK) @ B(KxN) + bias.
__global__ void gemm_kernel(const float* __restrict__ A, const float* __restrict__ B,
                            const float* __restrict__ bias, float* __restrict__ C,
                            int M, int N, int K){
    __shared__ float As[32][33], Bs[32][33];
    int tx = threadIdx.x, ty = threadIdx.y;
    int t = ty*16 + tx;
    int r0 = blockIdx.y*32, c0 = blockIdx.x*32;
    float a00 = 0.f, a01 = 0.f, a10 = 0.f, a11 = 0.f;
    for (int k0 = 0; k0 < K; k0 += 32){
        for (int i = t; i < 1024; i += 256){
            int rr = i >> 5, cc = i & 31;
            As[rr][cc] = A[(size_t)(r0+rr)*K + k0 + cc];
            Bs[rr][cc] = B[(size_t)(k0+rr)*N + c0 + cc];
        }
        __syncthreads();
        #pragma unroll
        for (int kk = 0; kk < 32; kk++){
            float av0 = As[ty*2][kk], av1 = As[ty*2+1][kk];
            float bv0 = Bs[kk][tx*2], bv1 = Bs[kk][tx*2+1];
            a00 += av0*bv0; a01 += av0*bv1; a10 += av1*bv0; a11 += av1*bv1;
        }
        __syncthreads();
    }
    int r = r0 + ty*2, c = c0 + tx*2;
    C[(size_t)r*N + c]       = a00 + bias[c];
    C[(size_t)r*N + c+1]     = a01 + bias[c+1];
    C[(size_t)(r+1)*N + c]   = a10 + bias[c];
    C[(size_t)(r+1)*N + c+1] = a11 + bias[c+1];
}

// ------------------------------------------------------------------
// conv_p weight prep: split fp32 -> bf16 hi/lo packed into 8x8 ldmatrix-B tiles.
// Word layout: [chunk 9][tap 9][nt 16][b 2][ocrow 8][kw 4]  (u32 = bf16 pair
// along k). tile(nt,b) = 8 rows (oc) x 16B (8 k-values).
// ------------------------------------------------------------------
__global__ void wprep_mma_kernel(const float* __restrict__ w,
                                 unsigned* __restrict__ whi, unsigned* __restrict__ wlo){
    int j = blockIdx.x*256 + threadIdx.x;   // 663552 words
    if (j >= 9*9*16*2*8*4) return;
    int kw  = j & 3;
    int ocr = (j >> 2) & 7;
    int b   = (j >> 5) & 1;
    int nt  = (j >> 6) & 15;
    int tt  = j >> 10;
    int tap = tt % 9, chunk = tt / 9;
    int ci = chunk*16 + b*8 + 2*kw;
    int oc = nt*8 + ocr;
    float w0 = (ci     < 136) ? w[(oc*136 + ci    )*9 + tap] : 0.f;
    float w1 = (ci + 1 < 136) ? w[(oc*136 + ci + 1)*9 + tap] : 0.f;
    unsigned hw, lw;
    nsplit2(w0, w1, hw, lw);
    whi[j] = hw; wlo[j] = lw;
}

// ------------------------------------------------------------------
// conv_p via bf16 mma, cp.async double-buffered pipeline.
// grid (12 x-tiles, 24 y-tiles, 2 ocg), block 256 (8 warps).
// smem: A(hi+lo) x2 bufs @58752 each; W(hi+lo) x2 bufs @36864 each = 191232 B.
// ------------------------------------------------------------------
#define A_BUF_SZ   58752     // 612 px * 48B * 2 (hi+lo)
#define A_LO_DELTA 29376
#define W_BASE     117504
#define W_BUF_SZ   36864     // 9 taps * 2048B * 2 (hi+lo)
#define W_LO_DELTA 18432
#define CONVP_SMEM 191232

__global__ void __launch_bounds__(256)
convp_mma_kernel(const uint8_t* __restrict__ zsh, const uint8_t* __restrict__ zsl,
                 const unsigned* __restrict__ whi, const unsigned* __restrict__ wlo,
                 const float* __restrict__ bias, float* __restrict__ out){
    extern __shared__ char sm[];
    unsigned smU = (unsigned)__cvta_generic_to_shared(sm);

    int t = threadIdx.x;
    int x0 = blockIdx.x*32, y0 = blockIdx.y*16, ocg = blockIdx.z;
    int lane = t & 31, wrp = t >> 5;
    int t4 = lane & 3, g = lane >> 2;
    int qd = lane >> 3, r8 = lane & 7;
    int prow = (qd & 1)*8 + r8;
    int khalf = qd >> 1;
    unsigned baseoffA = (unsigned)(((2*wrp)*34 + prow)*48 + khalf*16);

    float acc[4][8][4];
    #pragma unroll
    for (int nt = 0; nt < 8; nt++){
        float2 bv = *(const float2*)(bias + ocg*64 + nt*8 + 2*t4);
        #pragma unroll
        for (int m = 0; m < 4; m++){
            acc[m][nt][0] = bv.x; acc[m][nt][1] = bv.y;
            acc[m][nt][2] = bv.x; acc[m][nt][3] = bv.y;
        }
    }

    auto issueA = [&](int chunk, int buf){
        unsigned abase = smU + buf*A_BUF_SZ;
        for (int i = t; i < 612; i += 256){
            int hy = i / 34, hx = i - hy*34;
            int gy = y0 - 1 + hy, gx = x0 - 1 + hx;
            bool inb = ((unsigned)gy < 384u) && ((unsigned)gx < 384u);
            unsigned nb = inb ? 16u : 0u;
            size_t go = ((size_t)chunk*SPAT + (inb ? (gy*L + gx) : 0))*32;
            unsigned sa = abase + i*48;
            cp16(sa,                  zsh + go,      nb);
            cp16(sa + 16,             zsh + go + 16, nb);
            cp16(sa + A_LO_DELTA,     zsl + go,      nb);
            cp16(sa + A_LO_DELTA+16,  zsl + go + 16, nb);
        }
    };
    auto issueW = [&](int chunk, int buf){
        unsigned wb = smU + W_BASE + buf*W_BUF_SZ;
        const char* gh = (const char*)whi;
        const char* gl = (const char*)wlo;
        for (int i = t; i < 1152; i += 256){
            int tap = i >> 7, wi = i & 127;
            unsigned sa = wb + tap*2048 + wi*16;
            size_t go = (((size_t)(chunk*9 + tap))*1024 + (size_t)ocg*512)*4 + wi*16;
            cp16(sa,              gh + go, 16);
            cp16(sa + W_LO_DELTA, gl + go, 16);
        }
    };

    issueA(0, 0); issueW(0, 0); CP_COMMIT();
    CP_WAIT0(); __syncthreads();

    for (int c = 0; c < 9; c++){
        int cur = c & 1;
        if (c < 8){ issueA(c+1, cur^1); issueW(c+1, cur^1); CP_COMMIT(); }

        unsigned aBase = smU + cur*A_BUF_SZ;
        unsigned wBase = smU + W_BASE + cur*W_BUF_SZ;

        #pragma unroll
        for (int ky = 0; ky < 3; ky++){
            #pragma unroll
            for (int kx = 0; kx < 3; kx++){
                int tap = ky*3 + kx;
                unsigned bh0[8], bh1[8], bl0[8], bl1[8];
                #pragma unroll
                for (int p = 0; p < 4; p++){
                    unsigned baddr = wBase + tap*2048 + p*512
                                   + (lane >> 3)*128 + (lane & 7)*16;
                    ldmx4(baddr, bh0[2*p], bh1[2*p], bh0[2*p+1], bh1[2*p+1]);
                    ldmx4(baddr + W_LO_DELTA, bl0[2*p], bl1[2*p], bl0[2*p+1], bl1[2*p+1]);
                }
                unsigned tapoff = (unsigned)((ky*34 + kx)*48);
                #pragma unroll
                for (int m = 0; m < 4; m++){
                    unsigned addr = aBase + baseoffA + tapoff
                                  + (unsigned)((((m>>1))*34 + (m&1)*16)*48);
                    unsigned ah0, ah1, ah2, ah3, al0, al1, al2, al3;
                    ldmx4(addr, ah0, ah1, ah2, ah3);
                    ldmx4(addr + A_LO_DELTA, al0, al1, al2, al3);
                    #pragma unroll
                    for (int nt = 0; nt < 8; nt++)
                        mma_bf16(acc[m][nt], ah0, ah1, ah2, ah3, bh0[nt], bh1[nt]);
                    #pragma unroll
                    for (int nt = 0; nt < 8; nt++)
                        mma_bf16(acc[m][nt], al0, al1, al2, al3, bh0[nt], bh1[nt]);
                    #pragma unroll
                    for (int nt = 0; nt < 8; nt++)
                        mma_bf16(acc[m][nt], ah0, ah1, ah2, ah3, bl0[nt], bl1[nt]);
                }
            }
        }
        if (c < 8){ CP_WAIT0(); __syncthreads(); }
    }

    // ---- epilogue: leaky relu, write channel-last float2 pairs
    #pragma unroll
    for (int m = 0; m < 4; m++){
        int gy = y0 + 2*wrp + (m >> 1);
        int gxb = x0 + (m & 1)*16;
        #pragma unroll
        for (int nt = 0; nt < 8; nt++){
            int oc = ocg*64 + nt*8 + 2*t4;
            float* o1 = out + ((size_t)gy*L + gxb + g    )*128 + oc;
            float* o2 = out + ((size_t)gy*L + gxb + g + 8)*128 + oc;
            *(float2*)o1 = make_float2(lrelu(acc[m][nt][0]), lrelu(acc[m][nt][1]));
            *(float2*)o2 = make_float2(lrelu(acc[m][nt][2]), lrelu(acc[m][nt][3]));
        }
    }
}

// ------------------------------------------------------------------
extern "C" void kernel_launch(void* const* d_in, const int* in_sizes, int n_in,
                              void* d_out, int out_size){
    (void)in_sizes; (void)n_in; (void)out_size;
    const float* x        = (const float*)d_in[0];
    const float* z        = (const float*)d_in[1];
    const float* plddt    = (const float*)d_in[2];
    const float* Wq       = (const float*)d_in[3];
    const float* Wk       = (const float*)d_in[4];
    const float* Wv       = (const float*)d_in[5];
    const float* Wp2a     = (const float*)d_in[6];
    const float* conv_a_w = (const float*)d_in[7];
    const float* conv_a_b = (const float*)d_in[8];
    const float* conv_m_w = (const float*)d_in[9];
    const float* conv_m_b = (const float*)d_in[10];
    const float* ln1_w    = (const float*)d_in[11];
    const float* ln1_b    = (const float*)d_in[12];
    const float* lin1_w   = (const float*)d_in[13];
    const float* lin1_b   = (const float*)d_in[14];
    const float* ln2_w    = (const float*)d_in[15];
    const float* ln2_b    = (const float*)d_in[16];
    const float* lin2_w   = (const float*)d_in[17];
    const float* lin2_b   = (const float*)d_in[18];
    const float* lnf_w    = (const float*)d_in[19];
    const float* lnf_b    = (const float*)d_in[20];
    const float* conv_p_w = (const float*)d_in[21];
    const float* conv_p_b = (const float*)d_in[22];
    float* out = (float*)d_out;

    float* S = nullptr;
    cudaGetSymbolAddress((void**)&S, g_scratch);
    float* q       = S + OFF_Q;
    float* k       = S + OFF_K;
    float* v       = S + OFF_V;
    float* a2h     = S + OFF_A2H;
    float* a8      = S + OFF_A8;
    float* afin    = S + OFF_AFIN;
    float* cat     = S + OFF_CAT;
    float* catn    = S + OFF_CATN;
    float* h1      = S + OFF_H1;
    float* h2      = S + OFF_H2;
    float* h3      = S + OFF_H3;
    float* mean16  = S + OFF_MEAN16;
    float* rstd16  = S + OFF_RSTD16;
    float* mean9   = S + OFF_MEAN9;
    float* rstd9   = S + OFF_RSTD9;
    float* mean136 = S + OFF_MEAN136;
    float* rstd136 = S + OFF_RSTD136;
    float* psum    = S + OFF_PSUM;
    float* psq     = S + OFF_PSQ;
    unsigned* wmma_hi = (unsigned*)(S + OFF_WMMA_HI);
    unsigned* wmma_lo = (unsigned*)(S + OFF_WMMA_LO);
    uint8_t* zsh = (uint8_t*)(S + OFF_ZSH);
    uint8_t* zsl = (uint8_t*)(S + OFF_ZSL);

    cudaFuncSetAttribute(convp_mma_kernel,
                         cudaFuncAttributeMaxDynamicSharedMemorySize, CONVP_SMEM);

    // z per-channel stats — must precede apair (slab emit needs mean/rstd)
    zstats1_kernel<<<384, 256>>>(z, psum, psq);
    zstats2_kernel<<<128, 128>>>(psum, psq, mean136, rstd136);
    // conv_p weight split/pack — independent
    wprep_mma_kernel<<<2592, 256>>>(conv_p_w, wmma_hi, wmma_lo);

    // qkv + attention logits (apair also emits z bf16 slabs, chunks 0..7)
    qkv_kernel<<<dim3(96, 3), 256>>>(x, Wq, Wk, Wv, q, k, v);
    apair_kernel<<<dim3(48, 384), 256>>>(z, Wp2a, mean136, rstd136, a2h, zsh, zsl);
    anode_kernel<<<dim3(12, 12, 8), dim3(32, 32)>>>(q, k, a2h);

    // conv_a path
    stats_kernel<<<16, 256>>>(a2h, 16, nullptr, mean16, rstd16);
    conva_kernel<<<dim3(24, 24), 256>>>(a2h, conv_a_w, conv_a_b, mean16, rstd16, a8);

    // conv_m path
    stats_kernel<<<9, 256>>>(a8, 8, plddt, mean9, rstd9);
    convm_kernel<<<dim3(24, 24), 256>>>(a8, plddt, conv_m_w, conv_m_b, mean9, rstd9, afin);

    // stats + slab for afin channels (chunk 8 of zp)
    stats_kernel<<<8, 256>>>(afin, 8, nullptr, mean136 + 128, rstd136 + 128);
    afin_slab_kernel<<<576, 256>>>(afin, mean136, rstd136, zsh, zsl);

    // pair update (pipelined tensor-core conv)
    convp_mma_kernel<<<dim3(12, 24, 2), 256, CONVP_SMEM>>>(
        zsh, zsl, wmma_hi, wmma_lo, conv_p_b, out + 384*256);

    // aggregations
    nfn_kernel<<<dim3(8, 12), dim3(32, 32)>>>(afin, v, cat);
    nfp_kernel<<<384, 256>>>(afin, z, cat);

    // MLP + final node LN
    ln_kernel<<<384, 256, 1280*sizeof(float)>>>(cat, nullptr, catn, ln1_w, ln1_b, 1280, 0);
    gemm_kernel<<<dim3(16, 12), dim3(16, 16)>>>(catn, lin1_w, lin1_b, h1, 384, 512, 1280);
    ln_kernel<<<384, 256, 512*sizeof(float)>>>(h1, nullptr, h2, ln2_w, ln2_b, 512, 1);
    gemm_kernel<<<dim3(8, 12), dim3(16, 16)>>>(h2, lin2_w, lin2_b, h3, 384, 256, 512);
    ln_kernel<<<384, 256, 256*sizeof(float)>>>(h3, x, out, lnf_w, lnf_b, 256, 0);
}

// round 17
// speedup vs baseline: 2.1159x; 1.0545x over previous
#include <cuda_runtime.h>
#include <cuda_bf16.h>
#include <cstdint>
#include <cstddef>

// Shapes: N=1, L=384, NODE=256, H=8, HD=32, PD=128, D1=1280
#define L 384
#define SPAT 147456       // 384*384
#define NODE 256
#define NH 8
#define HD 32
#define PD 128

// ---- scratch layout (floats) ----
#define OFF_Q       0
#define OFF_K       98304
#define OFF_V       196608
#define OFF_A2H     294912     // 16*147456
#define OFF_A8      2654208    // 8*147456
#define OFF_AFIN    3833856
#define OFF_CAT     5013504    // 384*1280
#define OFF_CATN    5505024
#define OFF_H1      5996544
#define OFF_H2      6193152
#define OFF_H3      6389760
#define OFF_MEAN16  6644736
#define OFF_RSTD16  6644752
#define OFF_MEAN9   6644768
#define OFF_RSTD9   6644784
#define OFF_MEAN136 6644800    // 160 slots
#define OFF_RSTD136 6644960    // 160 slots
#define OFF_PSUM    6645120    // 128*384
#define OFF_PSQ     6694272    // 128*384
#define OFF_WMMA_HI 6743424    // 663552 u32 words
#define OFF_WMMA_LO 7406976    // +663552
// bf16 slabs: [chunk 9][px 147456][16 ci] bf16 = 32B/px
#define OFF_ZSH     8070528
#define OFF_ZSL     18687360
#define SCRATCH_FLOATS 29304192

__device__ float g_scratch[SCRATCH_FLOATS];

__device__ __forceinline__ float lrelu(float v){ return v >= 0.f ? v : 0.01f*v; }

// ---- bf16 split/pack: (a,b) -> hi word + lo (residual) word ----
__device__ __forceinline__ void nsplit2(float a, float b, unsigned &hw, unsigned &lw){
    __nv_bfloat16 ha = __float2bfloat16_rn(a);
    __nv_bfloat16 hb = __float2bfloat16_rn(b);
    float la = a - __bfloat162float(ha);
    float lb = b - __bfloat162float(hb);
    __nv_bfloat162 hp; hp.x = ha; hp.y = hb;
    __nv_bfloat162 lp; lp.x = __float2bfloat16_rn(la); lp.y = __float2bfloat16_rn(lb);
    hw = *reinterpret_cast<unsigned*>(&hp);
    lw = *reinterpret_cast<unsigned*>(&lp);
}

__device__ __forceinline__ void mma_bf16(float* c, unsigned a0, unsigned a1,
                                         unsigned a2, unsigned a3,
                                         unsigned b0, unsigned b1){
    asm volatile(
      "mma.sync.aligned.m16n8k16.row.col.f32.bf16.bf16.f32 "
      "{%0,%1,%2,%3}, {%4,%5,%6,%7}, {%8,%9}, {%0,%1,%2,%3};"
      : "+f"(c[0]), "+f"(c[1]), "+f"(c[2]), "+f"(c[3])
      : "r"(a0), "r"(a1), "r"(a2), "r"(a3), "r"(b0), "r"(b1));
}
__device__ __forceinline__ void ldmx4(unsigned addr, unsigned &r0, unsigned &r1,
                                      unsigned &r2, unsigned &r3){
    asm volatile("ldmatrix.sync.aligned.m8n8.x4.shared.b16 {%0,%1,%2,%3}, [%4];"
      : "=r"(r0), "=r"(r1), "=r"(r2), "=r"(r3) : "r"(addr));
}
__device__ __forceinline__ void cp16(unsigned sm, const void* gm, unsigned bytes){
    asm volatile("cp.async.cg.shared.global [%0], [%1], 16, %2;"
      :: "r"(sm), "l"(gm), "r"(bytes));
}
#define CP_COMMIT() asm volatile("cp.async.commit_group;")
#define CP_WAIT0()  asm volatile("cp.async.wait_group 0;")

// ------------------------------------------------------------------
// q/k/v = x @ W.  grid (96 row-tiles, 3 matrices), block 256, 4 rows/block.
// ------------------------------------------------------------------
__global__ void qkv_kernel(const float* __restrict__ x, const float* __restrict__ Wq,
                           const float* __restrict__ Wk, const float* __restrict__ Wv,
                           float* __restrict__ q, float* __restrict__ k, float* __restrict__ v){
    __shared__ float xs[4*256];
    int l0 = blockIdx.x*4, t = threadIdx.x;
    const float* W; float* o;
    if (blockIdx.y == 0){ W = Wq; o = q; }
    else if (blockIdx.y == 1){ W = Wk; o = k; }
    else { W = Wv; o = v; }
    for (int i = t; i < 4*256; i += 256) xs[i] = x[l0*256 + i];
    __syncthreads();
    float acc[4] = {0.f, 0.f, 0.f, 0.f};
    #pragma unroll 4
    for (int i = 0; i < 256; i++){
        float w = W[i*256 + t];
        #pragma unroll
        for (int r = 0; r < 4; r++) acc[r] += xs[r*256 + i]*w;
    }
    #pragma unroll
    for (int r = 0; r < 4; r++) o[(l0+r)*256 + t] = acc[r];
}

// ------------------------------------------------------------------
// a_pair + emit normalized bf16 hi/lo slabs (chunks 0..7).
// grid (48, 384), block 256 (warp per px).
// ------------------------------------------------------------------
__global__ void apair_kernel(const float* __restrict__ z, const float* __restrict__ Wp2a,
                             const float* __restrict__ mean136, const float* __restrict__ rstd136,
                             float* __restrict__ a2h,
                             uint8_t* __restrict__ zsh, uint8_t* __restrict__ zsl){
    __shared__ float ws[128*9];
    int t = threadIdx.x;
    for (int i = t; i < 1024; i += 256){
        int p = i >> 3, h = i & 7;
        ws[p*9 + h] = Wp2a[i];
    }
    __syncthreads();
    int lane = t & 31, wp = t >> 5;
    int m = blockIdx.x*8 + wp;
    int l = blockIdx.y;
    const float4 zv = *(const float4*)(z + ((size_t)l*L + m)*128 + lane*4);
    int p = lane*4;
    float acc[8];
    #pragma unroll
    for (int h = 0; h < 8; h++){
        acc[h] = zv.x*ws[p*9 + h] + zv.y*ws[(p+1)*9 + h]
               + zv.z*ws[(p+2)*9 + h] + zv.w*ws[(p+3)*9 + h];
    }
    #pragma unroll
    for (int h = 0; h < 8; h++){
        float s = acc[h];
        for (int o = 16; o > 0; o >>= 1) s += __shfl_down_sync(0xffffffffu, s, o);
        if (lane == 0) a2h[h*SPAT + l*L + m] = s;
    }
    float4 mm = *(const float4*)(mean136 + p);
    float4 rr = *(const float4*)(rstd136 + p);
    unsigned h0, l0w, h1, l1w;
    nsplit2((zv.x - mm.x)*rr.x, (zv.y - mm.y)*rr.y, h0, l0w);
    nsplit2((zv.z - mm.z)*rr.z, (zv.w - mm.w)*rr.w, h1, l1w);
    size_t off = ((size_t)(lane >> 2)*SPAT + (size_t)l*L + m)*32 + (lane & 3)*8;
    uint2 hv; hv.x = h0; hv.y = h1;
    uint2 lv; lv.x = l0w; lv.y = l1w;
    *(uint2*)(zsh + off) = hv;
    *(uint2*)(zsl + off) = lv;
}

// afin slab (chunk 8): 8 real ci + 8 zeros. grid 576, block 256.
__global__ void afin_slab_kernel(const float* __restrict__ afin,
                                 const float* __restrict__ mean136,
                                 const float* __restrict__ rstd136,
                                 uint8_t* __restrict__ zsh, uint8_t* __restrict__ zsl){
    __shared__ float ms[8], rs[8];
    int t = threadIdx.x;
    if (t < 8){ ms[t] = mean136[128 + t]; rs[t] = rstd136[128 + t]; }
    __syncthreads();
    int px = blockIdx.x*256 + t;
    float v[8];
    #pragma unroll
    for (int c = 0; c < 8; c++)
        v[c] = (afin[c*SPAT + px] - ms[c]) * rs[c];
    uint4 H, Lo;
    nsplit2(v[0], v[1], H.x, Lo.x);
    nsplit2(v[2], v[3], H.y, Lo.y);
    nsplit2(v[4], v[5], H.z, Lo.z);
    nsplit2(v[6], v[7], H.w, Lo.w);
    uint4 Z = {0,0,0,0};
    size_t off = ((size_t)8*SPAT + px)*32;
    *(uint4*)(zsh + off) = H;  *(uint4*)(zsh + off + 16) = Z;
    *(uint4*)(zsl + off) = Lo; *(uint4*)(zsl + off + 16) = Z;
}

// ------------------------------------------------------------------
// a_node[h][l][m] = q[l,h,:].k[m,h,:]/sqrt(32)  (channels 8..15)
// ------------------------------------------------------------------
__global__ void anode_kernel(const float* __restrict__ q, const float* __restrict__ k,
                             float* __restrict__ a2h){
    int h = blockIdx.z;
    int l0 = blockIdx.y*32, m0 = blockIdx.x*32;
    __shared__ float Qs[32][33], Ks[32][33];
    int tx = threadIdx.x, ty = threadIdx.y;
    Qs[ty][tx] = q[(l0+ty)*256 + h*32 + tx];
    Ks[ty][tx] = k[(m0+ty)*256 + h*32 + tx];
    __syncthreads();
    float acc = 0.f;
    #pragma unroll
    for (int d = 0; d < 32; d++) acc += Qs[ty][d]*Ks[tx][d];
    a2h[(8+h)*SPAT + (l0+ty)*L + m0 + tx] = acc * 0.17677669529663687f;
}

// ------------------------------------------------------------------
// Per-channel instance-norm stats
// ------------------------------------------------------------------
__global__ void stats_kernel(const float* __restrict__ srcA, int nA,
                             const float* __restrict__ srcB,
                             float* __restrict__ mean, float* __restrict__ rstd){
    int c = blockIdx.x, t = threadIdx.x;
    const float* p = (c < nA) ? srcA + (size_t)c*SPAT : srcB + (size_t)(c-nA)*SPAT;
    const float4* p4 = (const float4*)p;
    float s = 0.f, s2 = 0.f;
    for (int i = t; i < SPAT/4; i += 256){
        float4 v = p4[i];
        s  += v.x + v.y + v.z + v.w;
        s2 += v.x*v.x + v.y*v.y + v.z*v.z + v.w*v.w;
    }
    __shared__ float ss[256], ss2[256];
    ss[t] = s; ss2[t] = s2; __syncthreads();
    for (int o = 128; o > 0; o >>= 1){
        if (t < o){ ss[t] += ss[t+o]; ss2[t] += ss2[t+o]; }
        __syncthreads();
    }
    if (t == 0){
        float m = ss[0] * (1.f/SPAT);
        float var = ss2[0] * (1.f/SPAT) - m*m;
        mean[c] = m; rstd[c] = rsqrtf(var + 1e-5f);
    }
}

// z channel stats, stage 1. grid 384, block 256.
__global__ void zstats1_kernel(const float* __restrict__ z,
                               float* __restrict__ psum, float* __restrict__ psq){
    int l = blockIdx.x, t = threadIdx.x;
    int c = t & 127, half = t >> 7;
    const float* base = z + (size_t)l*L*128;
    float s = 0.f, s2 = 0.f;
    for (int m = half; m < L; m += 2){
        float v = base[m*128 + c];
        s += v; s2 += v*v;
    }
    __shared__ float sh[256], sh2[256];
    sh[t] = s; sh2[t] = s2; __syncthreads();
    if (half == 0){
        psum[c*L + l] = sh[t] + sh[t+128];
        psq [c*L + l] = sh2[t] + sh2[t+128];
    }
}

// stage 2. grid 128, block 128.
__global__ void zstats2_kernel(const float* __restrict__ psum, const float* __restrict__ psq,
                               float* __restrict__ mean, float* __restrict__ rstd){
    int c = blockIdx.x, t = threadIdx.x;
    float s = 0.f, s2 = 0.f;
    for (int l = t; l < L; l += 128){ s += psum[c*L + l]; s2 += psq[c*L + l]; }
    __shared__ float ss[128], ss2[128];
    ss[t] = s; ss2[t] = s2; __syncthreads();
    for (int o = 64; o > 0; o >>= 1){
        if (t < o){ ss[t] += ss[t+o]; ss2[t] += ss2[t+o]; }
        __syncthreads();
    }
    if (t == 0){
        float m = ss[0] * (1.f/SPAT);
        float var = ss2[0] * (1.f/SPAT) - m*m;
        mean[c] = m; rstd[c] = rsqrtf(var + 1e-5f);
    }
}

// ------------------------------------------------------------------
// conv_a: 16ch -> 8ch, 3x3, leaky. grid (24,24), 256 thr
// ------------------------------------------------------------------
__global__ void conva_kernel(const float* __restrict__ a2h, const float* __restrict__ w,
                             const float* __restrict__ bias, const float* __restrict__ mean,
                             const float* __restrict__ rstd, float* __restrict__ a8){
    __shared__ float tin[16*324];
    __shared__ float wk[1152];
    int t = threadIdx.x;
    for (int i = t; i < 1152; i += 256) wk[i] = w[i];
    int x0 = blockIdx.x*16 - 1, y0 = blockIdx.y*16 - 1;
    for (int i = t; i < 16*324; i += 256){
        int c = i / 324, r = i % 324;
        int gy = y0 + r/18, gx = x0 + r%18;
        float v = 0.f;
        if ((unsigned)gy < 384u && (unsigned)gx < 384u)
            v = (a2h[c*SPAT + gy*L + gx] - mean[c]) * rstd[c];
        tin[i] = v;
    }
    __syncthreads();
    int lx = t & 15, ly = t >> 4;
    float acc[8];
    #pragma unroll
    for (int o = 0; o < 8; o++) acc[o] = bias[o];
    for (int c = 0; c < 16; c++){
        float iv[9];
        #pragma unroll
        for (int ky = 0; ky < 3; ky++)
            #pragma unroll
            for (int kx = 0; kx < 3; kx++)
                iv[ky*3+kx] = tin[c*324 + (ly+ky)*18 + lx + kx];
        #pragma unroll
        for (int o = 0; o < 8; o++){
            const float* wp = &wk[(o*16 + c)*9];
            acc[o] += wp[0]*iv[0]+wp[1]*iv[1]+wp[2]*iv[2]
                    + wp[3]*iv[3]+wp[4]*iv[4]+wp[5]*iv[5]
                    + wp[6]*iv[6]+wp[7]*iv[7]+wp[8]*iv[8];
        }
    }
    int gx = blockIdx.x*16 + lx, gy = blockIdx.y*16 + ly;
    #pragma unroll
    for (int o = 0; o < 8; o++)
        a8[o*SPAT + gy*L + gx] = lrelu(acc[o]);
}

// conv_m: 9ch -> 8ch, leaky. grid (24,24), 256 thr
__global__ void convm_kernel(const float* __restrict__ a8, const float* __restrict__ plddt,
                             const float* __restrict__ w, const float* __restrict__ bias,
                             const float* __restrict__ mean, const float* __restrict__ rstd,
                             float* __restrict__ afin){
    __shared__ float tin[9*324];
    __shared__ float wk[648];
    int t = threadIdx.x;
    for (int i = t; i < 648; i += 256) wk[i] = w[i];
    int x0 = blockIdx.x*16 - 1, y0 = blockIdx.y*16 - 1;
    for (int i = t; i < 9*324; i += 256){
        int c = i / 324, r = i % 324;
        int gy = y0 + r/18, gx = x0 + r%18;
        float v = 0.f;
        if ((unsigned)gy < 384u && (unsigned)gx < 384u){
            float raw = (c < 8) ? a8[c*SPAT + gy*L + gx] : plddt[gy*L + gx];
            v = (raw - mean[c]) * rstd[c];
        }
        tin[i] = v;
    }
    __syncthreads();
    int lx = t & 15, ly = t >> 4;
    float acc[8];
    #pragma unroll
    for (int o = 0; o < 8; o++) acc[o] = bias[o];
    for (int c = 0; c < 9; c++){
        float iv[9];
        #pragma unroll
        for (int ky = 0; ky < 3; ky++)
            #pragma unroll
            for (int kx = 0; kx < 3; kx++)
                iv[ky*3+kx] = tin[c*324 + (ly+ky)*18 + lx + kx];
        #pragma unroll
        for (int o = 0; o < 8; o++){
            const float* wp = &wk[(o*9 + c)*9];
            acc[o] += wp[0]*iv[0]+wp[1]*iv[1]+wp[2]*iv[2]
                    + wp[3]*iv[3]+wp[4]*iv[4]+wp[5]*iv[5]
                    + wp[6]*iv[6]+wp[7]*iv[7]+wp[8]*iv[8];
        }
    }
    int gx = blockIdx.x*16 + lx, gy = blockIdx.y*16 + ly;
    #pragma unroll
    for (int o = 0; o < 8; o++)
        afin[o*SPAT + gy*L + gx] = lrelu(acc[o]);
}

// ------------------------------------------------------------------
// nfn: cat[l, 1024 + h*32+d] = sum_m afin[h][l][m] * v[m, h*32+d]
// ------------------------------------------------------------------
__global__ void nfn_kernel(const float* __restrict__ afin, const float* __restrict__ v,
                           float* __restrict__ cat){
    int h = blockIdx.x, l0 = blockIdx.y*32;
    int tx = threadIdx.x, ty = threadIdx.y;
    __shared__ float As[32][33], Vs[32][33];
    float acc = 0.f;
    for (int m0 = 0; m0 < L; m0 += 32){
        As[ty][tx] = afin[h*SPAT + (l0+ty)*L + m0 + tx];
        Vs[ty][tx] = v[(m0+ty)*256 + h*32 + tx];
        __syncthreads();
        #pragma unroll
        for (int kk = 0; kk < 32; kk++) acc += As[ty][kk]*Vs[kk][tx];
        __syncthreads();
    }
    cat[(size_t)(l0+ty)*1280 + 1024 + h*32 + tx] = acc;
}

// nfp: cat[l, h*128+p] = sum_m afin[h][l][m] * z[l,m,p].  grid 384, block 256
__global__ void nfp_kernel(const float* __restrict__ afin, const float* __restrict__ z,
                           float* __restrict__ cat){
    int l = blockIdx.x, t = threadIdx.x;
    __shared__ float As[8][32];
    __shared__ float Zs[32*128];
    int p = t & 127, hb = (t >> 7)*4;
    float acc0 = 0.f, acc1 = 0.f, acc2 = 0.f, acc3 = 0.f;
    for (int m0 = 0; m0 < L; m0 += 32){
        __syncthreads();
        { int hh = t >> 5, mm = t & 31; As[hh][mm] = afin[hh*SPAT + l*L + m0 + mm]; }
        const float4* zsrc = (const float4*)(z + ((size_t)l*L + m0)*128);
        float4* zd = (float4*)Zs;
        for (int i = t; i < 1024; i += 256) zd[i] = zsrc[i];
        __syncthreads();
        #pragma unroll 8
        for (int mm = 0; mm < 32; mm++){
            float zv = Zs[mm*128 + p];
            acc0 += As[hb  ][mm]*zv;
            acc1 += As[hb+1][mm]*zv;
            acc2 += As[hb+2][mm]*zv;
            acc3 += As[hb+3][mm]*zv;
        }
    }
    cat[(size_t)l*1280 + (hb  )*128 + p] = acc0;
    cat[(size_t)l*1280 + (hb+1)*128 + p] = acc1;
    cat[(size_t)l*1280 + (hb+2)*128 + p] = acc2;
    cat[(size_t)l*1280 + (hb+3)*128 + p] = acc3;
}

// ------------------------------------------------------------------
// row LayerNorm
// ------------------------------------------------------------------
__global__ void ln_kernel(const float* __restrict__ in, const float* __restrict__ add,
                          float* __restrict__ out, const float* __restrict__ w,
                          const float* __restrict__ b, int D, int do_leaky){
    extern __shared__ float sh[];
    __shared__ float red[256];
    int r = blockIdx.x, t = threadIdx.x;
    float s = 0.f;
    for (int i = t; i < D; i += 256){
        float v = in[(size_t)r*D + i];
        if (add) v += add[(size_t)r*D + i];
        sh[i] = v; s += v;
    }
    red[t] = s; __syncthreads();
    for (int o = 128; o > 0; o >>= 1){ if (t < o) red[t] += red[t+o]; __syncthreads(); }
    float mean = red[0] / D;
    __syncthreads();
    float s2 = 0.f;
    for (int i = t; i < D; i += 256){ float d = sh[i] - mean; s2 += d*d; }
    red[t] = s2; __syncthreads();
    for (int o = 128; o > 0; o >>= 1){ if (t < o) red[t] += red[t+o]; __syncthreads(); }
    float rstd = rsqrtf(red[0]/D + 1e-5f);
    for (int i = t; i < D; i += 256){
        float v = (sh[i] - mean)*rstd*w[i] + b[i];
        if (do_leaky) v = lrelu(v);
        out[(size_t)r*D + i] = v;
    }
}

// generic GEMM C = A(MxK) @ B(KxN) + bias.
__global__ void gemm_kernel(const float* __restrict__ A, const float* __restrict__ B,
                            const float* __restrict__ bias, float* __restrict__ C,
                            int M, int N, int K){
    __shared__ float As[32][33], Bs[32][33];
    int tx = threadIdx.x, ty = threadIdx.y;
    int t = ty*16 + tx;
    int r0 = blockIdx.y*32, c0 = blockIdx.x*32;
    float a00 = 0.f, a01 = 0.f, a10 = 0.f, a11 = 0.f;
    for (int k0 = 0; k0 < K; k0 += 32){
        for (int i = t; i < 1024; i += 256){
            int rr = i >> 5, cc = i & 31;
            As[rr][cc] = A[(size_t)(r0+rr)*K + k0 + cc];
            Bs[rr][cc] = B[(size_t)(k0+rr)*N + c0 + cc];
        }
        __syncthreads();
        #pragma unroll
        for (int kk = 0; kk < 32; kk++){
            float av0 = As[ty*2][kk], av1 = As[ty*2+1][kk];
            float bv0 = Bs[kk][tx*2], bv1 = Bs[kk][tx*2+1];
            a00 += av0*bv0; a01 += av0*bv1; a10 += av1*bv0; a11 += av1*bv1;
        }
        __syncthreads();
    }
    int r = r0 + ty*2, c = c0 + tx*2;
    C[(size_t)r*N + c]       = a00 + bias[c];
    C[(size_t)r*N + c+1]     = a01 + bias[c+1];
    C[(size_t)(r+1)*N + c]   = a10 + bias[c];
    C[(size_t)(r+1)*N + c+1] = a11 + bias[c+1];
}

// ------------------------------------------------------------------
// conv_p weight prep: split fp32 -> bf16 hi/lo packed into 8x8 ldmatrix-B tiles.
// ------------------------------------------------------------------
__global__ void wprep_mma_kernel(const float* __restrict__ w,
                                 unsigned* __restrict__ whi, unsigned* __restrict__ wlo){
    int j = blockIdx.x*256 + threadIdx.x;   // 663552 words
    if (j >= 9*9*16*2*8*4) return;
    int kw  = j & 3;
    int ocr = (j >> 2) & 7;
    int b   = (j >> 5) & 1;
    int nt  = (j >> 6) & 15;
    int tt  = j >> 10;
    int tap = tt % 9, chunk = tt / 9;
    int ci = chunk*16 + b*8 + 2*kw;
    int oc = nt*8 + ocr;
    float w0 = (ci     < 136) ? w[(oc*136 + ci    )*9 + tap] : 0.f;
    float w1 = (ci + 1 < 136) ? w[(oc*136 + ci + 1)*9 + tap] : 0.f;
    unsigned hw, lw;
    nsplit2(w0, w1, hw, lw);
    whi[j] = hw; wlo[j] = lw;
}

// ------------------------------------------------------------------
// conv_p via bf16 mma, cp.async double-buffered pipeline.
// grid (12, 24, 2 ocg), block 256 (8 warps).
// ------------------------------------------------------------------
#define A_BUF_SZ   58752
#define A_LO_DELTA 29376
#define W_BASE     117504
#define W_BUF_SZ   36864
#define W_LO_DELTA 18432
#define CONVP_SMEM 191232

__global__ void __launch_bounds__(256)
convp_mma_kernel(const uint8_t* __restrict__ zsh, const uint8_t* __restrict__ zsl,
                 const unsigned* __restrict__ whi, const unsigned* __restrict__ wlo,
                 const float* __restrict__ bias, float* __restrict__ out){
    extern __shared__ char sm[];
    unsigned smU = (unsigned)__cvta_generic_to_shared(sm);

    int t = threadIdx.x;
    int x0 = blockIdx.x*32, y0 = blockIdx.y*16, ocg = blockIdx.z;
    int lane = t & 31, wrp = t >> 5;
    int t4 = lane & 3, g = lane >> 2;
    int qd = lane >> 3, r8 = lane & 7;
    int prow = (qd & 1)*8 + r8;
    int khalf = qd >> 1;
    unsigned baseoffA = (unsigned)(((2*wrp)*34 + prow)*48 + khalf*16);

    float acc[4][8][4];
    #pragma unroll
    for (int nt = 0; nt < 8; nt++){
        float2 bv = *(const float2*)(bias + ocg*64 + nt*8 + 2*t4);
        #pragma unroll
        for (int m = 0; m < 4; m++){
            acc[m][nt][0] = bv.x; acc[m][nt][1] = bv.y;
            acc[m][nt][2] = bv.x; acc[m][nt][3] = bv.y;
        }
    }

    auto issueA = [&](int chunk, int buf){
        unsigned abase = smU + buf*A_BUF_SZ;
        for (int i = t; i < 612; i += 256){
            int hy = i / 34, hx = i - hy*34;
            int gy = y0 - 1 + hy, gx = x0 - 1 + hx;
            bool inb = ((unsigned)gy < 384u) && ((unsigned)gx < 384u);
            unsigned nb = inb ? 16u : 0u;
            size_t go = ((size_t)chunk*SPAT + (inb ? (gy*L + gx) : 0))*32;
            unsigned sa = abase + i*48;
            cp16(sa,                  zsh + go,      nb);
            cp16(sa + 16,             zsh + go + 16, nb);
            cp16(sa + A_LO_DELTA,     zsl + go,      nb);
            cp16(sa + A_LO_DELTA+16,  zsl + go + 16, nb);
        }
    };
    auto issueW = [&](int chunk, int buf){
        unsigned wb = smU + W_BASE + buf*W_BUF_SZ;
        const char* gh = (const char*)whi;
        const char* gl = (const char*)wlo;
        for (int i = t; i < 1152; i += 256){
            int tap = i >> 7, wi = i & 127;
            unsigned sa = wb + tap*2048 + wi*16;
            size_t go = (((size_t)(chunk*9 + tap))*1024 + (size_t)ocg*512)*4 + wi*16;
            cp16(sa,              gh + go, 16);
            cp16(sa + W_LO_DELTA, gl + go, 16);
        }
    };

    issueA(0, 0); issueW(0, 0); CP_COMMIT();
    CP_WAIT0(); __syncthreads();

    for (int c = 0; c < 9; c++){
        int cur = c & 1;
        if (c < 8){ issueA(c+1, cur^1); issueW(c+1, cur^1); CP_COMMIT(); }

        unsigned aBase = smU + cur*A_BUF_SZ;
        unsigned wBase = smU + W_BASE + cur*W_BUF_SZ;

        #pragma unroll
        for (int ky = 0; ky < 3; ky++){
            #pragma unroll
            for (int kx = 0; kx < 3; kx++){
                int tap = ky*3 + kx;
                unsigned bh0[8], bh1[8], bl0[8], bl1[8];
                #pragma unroll
                for (int p = 0; p < 4; p++){
                    unsigned baddr = wBase + tap*2048 + p*512
                                   + (lane >> 3)*128 + (lane & 7)*16;
                    ldmx4(baddr, bh0[2*p], bh1[2*p], bh0[2*p+1], bh1[2*p+1]);
                    ldmx4(baddr + W_LO_DELTA, bl0[2*p], bl1[2*p], bl0[2*p+1], bl1[2*p+1]);
                }
                unsigned tapoff = (unsigned)((ky*34 + kx)*48);
                #pragma unroll
                for (int m = 0; m < 4; m++){
                    unsigned addr = aBase + baseoffA + tapoff
                                  + (unsigned)((((m>>1))*34 + (m&1)*16)*48);
                    unsigned ah0, ah1, ah2, ah3, al0, al1, al2, al3;
                    ldmx4(addr, ah0, ah1, ah2, ah3);
                    ldmx4(addr + A_LO_DELTA, al0, al1, al2, al3);
                    #pragma unroll
                    for (int nt = 0; nt < 8; nt++)
                        mma_bf16(acc[m][nt], ah0, ah1, ah2, ah3, bh0[nt], bh1[nt]);
                    #pragma unroll
                    for (int nt = 0; nt < 8; nt++)
                        mma_bf16(acc[m][nt], al0, al1, al2, al3, bh0[nt], bh1[nt]);
                    #pragma unroll
                    for (int nt = 0; nt < 8; nt++)
                        mma_bf16(acc[m][nt], ah0, ah1, ah2, ah3, bl0[nt], bl1[nt]);
                }
            }
        }
        if (c < 8){ CP_WAIT0(); __syncthreads(); }
    }

    #pragma unroll
    for (int m = 0; m < 4; m++){
        int gy = y0 + 2*wrp + (m >> 1);
        int gxb = x0 + (m & 1)*16;
        #pragma unroll
        for (int nt = 0; nt < 8; nt++){
            int oc = ocg*64 + nt*8 + 2*t4;
            float* o1 = out + ((size_t)gy*L + gxb + g    )*128 + oc;
            float* o2 = out + ((size_t)gy*L + gxb + g + 8)*128 + oc;
            *(float2*)o1 = make_float2(lrelu(acc[m][nt][0]), lrelu(acc[m][nt][1]));
            *(float2*)o2 = make_float2(lrelu(acc[m][nt][2]), lrelu(acc[m][nt][3]));
        }
    }
}

// ------------------------------------------------------------------
// Launcher: fork-join multi-stream graph. Streams/events are created ONCE
// (first = correctness call, before the harness takes its pre-capture memory
// baseline) and reused on every later call, so capture/replay allocates
// nothing. Every call records the identical kernel DAG.
// ------------------------------------------------------------------
extern "C" void kernel_launch(void* const* d_in, const int* in_sizes, int n_in,
                              void* d_out, int out_size){
    (void)in_sizes; (void)n_in; (void)out_size;
    const float* x        = (const float*)d_in[0];
    const float* z        = (const float*)d_in[1];
    const float* plddt    = (const float*)d_in[2];
    const float* Wq       = (const float*)d_in[3];
    const float* Wk       = (const float*)d_in[4];
    const float* Wv       = (const float*)d_in[5];
    const float* Wp2a     = (const float*)d_in[6];
    const float* conv_a_w = (const float*)d_in[7];
    const float* conv_a_b = (const float*)d_in[8];
    const float* conv_m_w = (const float*)d_in[9];
    const float* conv_m_b = (const float*)d_in[10];
    const float* ln1_w    = (const float*)d_in[11];
    const float* ln1_b    = (const float*)d_in[12];
    const float* lin1_w   = (const float*)d_in[13];
    const float* lin1_b   = (const float*)d_in[14];
    const float* ln2_w    = (const float*)d_in[15];
    const float* ln2_b    = (const float*)d_in[16];
    const float* lin2_w   = (const float*)d_in[17];
    const float* lin2_b   = (const float*)d_in[18];
    const float* lnf_w    = (const float*)d_in[19];
    const float* lnf_b    = (const float*)d_in[20];
    const float* conv_p_w = (const float*)d_in[21];
    const float* conv_p_b = (const float*)d_in[22];
    float* out = (float*)d_out;

    float* S = nullptr;
    cudaGetSymbolAddress((void**)&S, g_scratch);
    float* q       = S + OFF_Q;
    float* k       = S + OFF_K;
    float* v       = S + OFF_V;
    float* a2h     = S + OFF_A2H;
    float* a8      = S + OFF_A8;
    float* afin    = S + OFF_AFIN;
    float* cat     = S + OFF_CAT;
    float* catn    = S + OFF_CATN;
    float* h1      = S + OFF_H1;
    float* h2      = S + OFF_H2;
    float* h3      = S + OFF_H3;
    float* mean16  = S + OFF_MEAN16;
    float* rstd16  = S + OFF_RSTD16;
    float* mean9   = S + OFF_MEAN9;
    float* rstd9   = S + OFF_RSTD9;
    float* mean136 = S + OFF_MEAN136;
    float* rstd136 = S + OFF_RSTD136;
    float* psum    = S + OFF_PSUM;
    float* psq     = S + OFF_PSQ;
    unsigned* wmma_hi = (unsigned*)(S + OFF_WMMA_HI);
    unsigned* wmma_lo = (unsigned*)(S + OFF_WMMA_LO);
    uint8_t* zsh = (uint8_t*)(S + OFF_ZSH);
    uint8_t* zsl = (uint8_t*)(S + OFF_ZSL);

    // One-time resource setup (first call = correctness run, pre-capture).
    static bool inited = false;
    static cudaStream_t s1, s2;
    static cudaEvent_t eRoot, eS1, eMid, eS2;
    if (!inited){
        cudaFuncSetAttribute(convp_mma_kernel,
                             cudaFuncAttributeMaxDynamicSharedMemorySize, CONVP_SMEM);
        cudaStreamCreateWithFlags(&s1, cudaStreamNonBlocking);
        cudaStreamCreateWithFlags(&s2, cudaStreamNonBlocking);
        cudaEventCreateWithFlags(&eRoot, cudaEventDisableTiming);
        cudaEventCreateWithFlags(&eS1,   cudaEventDisableTiming);
        cudaEventCreateWithFlags(&eMid,  cudaEventDisableTiming);
        cudaEventCreateWithFlags(&eS2,   cudaEventDisableTiming);
        inited = true;
    }
    cudaStream_t s0 = 0;

    // fork
    cudaEventRecord(eRoot, s0);
    cudaStreamWaitEvent(s1, eRoot, 0);

    // s1 branch: conv_p weight prep + qkv + anode
    wprep_mma_kernel<<<2592, 256, 0, s1>>>(conv_p_w, wmma_hi, wmma_lo);
    qkv_kernel<<<dim3(96, 3), 256, 0, s1>>>(x, Wq, Wk, Wv, q, k, v);
    anode_kernel<<<dim3(12, 12, 8), dim3(32, 32), 0, s1>>>(q, k, a2h);
    cudaEventRecord(eS1, s1);

    // main: z stats -> apair (emits bf16 slabs + a2h ch 0..7)
    zstats1_kernel<<<384, 256, 0, s0>>>(z, psum, psq);
    zstats2_kernel<<<128, 128, 0, s0>>>(psum, psq, mean136, rstd136);
    apair_kernel<<<dim3(48, 384), 256, 0, s0>>>(z, Wp2a, mean136, rstd136, a2h, zsh, zsl);

    // join s1 (a2h complete, q/k/v + weights ready)
    cudaStreamWaitEvent(s0, eS1, 0);

    // conv_a / conv_m chain
    stats_kernel<<<16, 256, 0, s0>>>(a2h, 16, nullptr, mean16, rstd16);
    conva_kernel<<<dim3(24, 24), 256, 0, s0>>>(a2h, conv_a_w, conv_a_b, mean16, rstd16, a8);
    stats_kernel<<<9, 256, 0, s0>>>(a8, 8, plddt, mean9, rstd9);
    convm_kernel<<<dim3(24, 24), 256, 0, s0>>>(a8, plddt, conv_m_w, conv_m_b, mean9, rstd9, afin);
    stats_kernel<<<8, 256, 0, s0>>>(afin, 8, nullptr, mean136 + 128, rstd136 + 128);
    afin_slab_kernel<<<576, 256, 0, s0>>>(afin, mean136, rstd136, zsh, zsl);
    cudaEventRecord(eMid, s0);

    // main: big tensor-core pair conv
    convp_mma_kernel<<<dim3(12, 24, 2), 256, CONVP_SMEM, s0>>>(
        zsh, zsl, wmma_hi, wmma_lo, conv_p_b, out + 384*256);

    // s2 branch (overlaps convp): node aggregations + MLP + final LN
    cudaStreamWaitEvent(s2, eMid, 0);
    nfn_kernel<<<dim3(8, 12), dim3(32, 32), 0, s2>>>(afin, v, cat);
    nfp_kernel<<<384, 256, 0, s2>>>(afin, z, cat);
    ln_kernel<<<384, 256, 1280*sizeof(float), s2>>>(cat, nullptr, catn, ln1_w, ln1_b, 1280, 0);
    gemm_kernel<<<dim3(16, 12), dim3(16, 16), 0, s2>>>(catn, lin1_w, lin1_b, h1, 384, 512, 1280);
    ln_kernel<<<384, 256, 512*sizeof(float), s2>>>(h1, nullptr, h2, ln2_w, ln2_b, 512, 1);
    gemm_kernel<<<dim3(8, 12), dim3(16, 16), 0, s2>>>(h2, lin2_w, lin2_b, h3, 384, 256, 512);
    ln_kernel<<<384, 256, 256*sizeof(float), s2>>>(h3, x, out, lnf_w, lnf_b, 256, 0);
    cudaEventRecord(eS2, s2);

    // join
    cudaStreamWaitEvent(s0, eS2, 0);
}